// round 1
// baseline (speedup 1.0000x reference)
#include <cuda_runtime.h>
#include <cuda_bf16.h>
#include <math.h>

// ---------------------------------------------------------------------------
// Problem constants
// ---------------------------------------------------------------------------
#define TI_   128
#define NB_   8
#define TO_   32
#define TS_   33          // T = TO+1
#define D_    512
#define H_    8
#define HD_   64
#define FF_   2048
#define V_    2000
#define L_    6
#define TOK_  (TS_ * NB_)          // 264 token rows (t-major: row = t*8+n)
#define MJ_   (NB_ * TI_ * TS_)    // 33792 joiner rows (n,i,t)

// ---------------------------------------------------------------------------
// Scratch (single __device__ array; no allocations allowed)
// ---------------------------------------------------------------------------
#define OFF_X     0
#define SZ_X      (TOK_ * D_)                 // 135168
#define OFF_QKV   (OFF_X + SZ_X)
#define SZ_QKV    (TOK_ * 3 * D_)             // 405504
#define OFF_ATTN  (OFF_QKV + SZ_QKV)
#define SZ_ATTN   (TOK_ * D_)
#define OFF_TMP   (OFF_ATTN + SZ_ATTN)
#define SZ_TMP    (TOK_ * D_)
#define OFF_FFH   (OFF_TMP + SZ_TMP)
#define SZ_FFH    (TOK_ * FF_)                // 540672
#define OFF_ENC   (OFF_FFH + SZ_FFH)
#define SZ_ENC    (TI_ * NB_ * D_)            // 524288
#define OFF_A     (OFF_ENC + SZ_ENC)
#define SZ_A      (MJ_ * D_)                  // 17301504
#define SCRATCH_TOTAL (OFF_A + SZ_A)

__device__ float g_scratch[SCRATCH_TOTAL];

// ---------------------------------------------------------------------------
// f32x2 packed-FMA helpers (FFMA2 path, PTX-only per sm_103a SASS quickref)
// ---------------------------------------------------------------------------
__device__ __forceinline__ unsigned long long pk2(float lo, float hi) {
    unsigned long long r;
    asm("mov.b64 %0, {%1, %2};" : "=l"(r) : "f"(lo), "f"(hi));
    return r;
}
__device__ __forceinline__ void unpk2(unsigned long long v, float& lo, float& hi) {
    asm("mov.b64 {%0, %1}, %2;" : "=f"(lo), "=f"(hi) : "l"(v));
}
__device__ __forceinline__ unsigned long long ffma2(unsigned long long a,
                                                    unsigned long long b,
                                                    unsigned long long c) {
    unsigned long long d;
    asm("fma.rn.f32x2 %0, %1, %2, %3;" : "=l"(d) : "l"(a), "l"(b), "l"(c));
    return d;
}

// ---------------------------------------------------------------------------
// Embedding + sinusoidal positional encoding
// x[t*8+n][d] = embed[tok]*sqrt(512) + pe(t,d)
// ---------------------------------------------------------------------------
__global__ void embed_kernel(const float* __restrict__ embed,
                             const int* __restrict__ tgt_pad,
                             const int* __restrict__ sos,
                             float* __restrict__ x) {
    int r = blockIdx.x;              // 0..263
    int t = r >> 3, n = r & 7;
    int tok = (t == 0) ? sos[0] : tgt_pad[n * TO_ + (t - 1)];
    const float* e = embed + (size_t)tok * D_;
    const float sc = sqrtf(512.0f);
    int tid = threadIdx.x;           // 128
#pragma unroll
    for (int i = 0; i < 4; i++) {
        int d = tid * 4 + i;
        int half = d >> 1;
        double ddiv = exp((double)(2 * half) * (-9.210340371976184 / 512.0));
        double ang = (double)t * ddiv;
        double pv = (d & 1) ? cos(ang) : sin(ang);
        x[(size_t)r * D_ + d] = e[d] * sc + (float)pv;
    }
}

// ---------------------------------------------------------------------------
// Generic small GEMM: C[M][N] = A[M][K] @ W[N][K]^T + bias, optional relu
// 64x64 tile, BK=16, 128 threads, 8x4 per-thread in f32x2 pairs.
// Requires K % 16 == 0 (true for 512/2048).
// ---------------------------------------------------------------------------
__global__ void __launch_bounds__(128) gemm64(const float* __restrict__ A,
                                              const float* __restrict__ W,
                                              const float* __restrict__ bias,
                                              float* __restrict__ C,
                                              int M, int N, int K, int relu) {
    __shared__ float As[16][64];
    __shared__ float Bs[16][64];
    const int tid = threadIdx.x;
    const int tx = tid & 15, ty = tid >> 4;    // ty 0..7
    const int m0 = blockIdx.y * 64, n0 = blockIdx.x * 64;

    unsigned long long acc[8][2];
#pragma unroll
    for (int i = 0; i < 8; i++) { acc[i][0] = 0ull; acc[i][1] = 0ull; }

    const int lrow = tid >> 1;
    const int lk = (tid & 1) * 8;
    const int gm = m0 + lrow, gn = n0 + lrow;
    const bool avalid = gm < M, bvalid = gn < N;
    const float* pa = A + (size_t)gm * K + lk;
    const float* pb = W + (size_t)gn * K + lk;

    for (int k0 = 0; k0 < K; k0 += 16) {
        float4 a0 = make_float4(0, 0, 0, 0), a1 = a0, b0 = a0, b1 = a0;
        if (avalid) {
            a0 = *(const float4*)(pa + k0);
            a1 = *(const float4*)(pa + k0 + 4);
        }
        if (bvalid) {
            b0 = *(const float4*)(pb + k0);
            b1 = *(const float4*)(pb + k0 + 4);
        }
        __syncthreads();
        As[lk + 0][lrow] = a0.x; As[lk + 1][lrow] = a0.y;
        As[lk + 2][lrow] = a0.z; As[lk + 3][lrow] = a0.w;
        As[lk + 4][lrow] = a1.x; As[lk + 5][lrow] = a1.y;
        As[lk + 6][lrow] = a1.z; As[lk + 7][lrow] = a1.w;
        Bs[lk + 0][lrow] = b0.x; Bs[lk + 1][lrow] = b0.y;
        Bs[lk + 2][lrow] = b0.z; Bs[lk + 3][lrow] = b0.w;
        Bs[lk + 4][lrow] = b1.x; Bs[lk + 5][lrow] = b1.y;
        Bs[lk + 6][lrow] = b1.z; Bs[lk + 7][lrow] = b1.w;
        __syncthreads();
#pragma unroll
        for (int k = 0; k < 16; k++) {
            float4 al = *(const float4*)&As[k][ty * 4];
            float4 ah = *(const float4*)&As[k][32 + ty * 4];
            float4 b  = *(const float4*)&Bs[k][tx * 4];
            unsigned long long bp0 = pk2(b.x, b.y), bp1 = pk2(b.z, b.w);
            float av8[8] = {al.x, al.y, al.z, al.w, ah.x, ah.y, ah.z, ah.w};
#pragma unroll
            for (int i = 0; i < 8; i++) {
                unsigned long long ap = pk2(av8[i], av8[i]);
                acc[i][0] = ffma2(ap, bp0, acc[i][0]);
                acc[i][1] = ffma2(ap, bp1, acc[i][1]);
            }
        }
    }
#pragma unroll
    for (int i = 0; i < 8; i++) {
        int r = m0 + ((i < 4) ? (ty * 4 + i) : (32 + ty * 4 + (i - 4)));
        if (r < M) {
            float v[4];
            unpk2(acc[i][0], v[0], v[1]);
            unpk2(acc[i][1], v[2], v[3]);
#pragma unroll
            for (int j = 0; j < 4; j++) {
                int c = n0 + tx * 4 + j;
                if (c < N) {
                    float o = v[j] + bias[c];
                    if (relu && o < 0.f) o = 0.f;
                    C[(size_t)r * N + c] = o;
                }
            }
        }
    }
}

// ---------------------------------------------------------------------------
// Attention: one block per (n,h). T=33, hd=64.
// ---------------------------------------------------------------------------
__global__ void attention_kernel(const float* __restrict__ qkv,
                                 const int* __restrict__ tgt_len,
                                 float* __restrict__ o) {
    int n = blockIdx.x >> 3, h = blockIdx.x & 7;
    __shared__ float qs[TS_][HD_];
    __shared__ float ks[TS_][HD_];
    __shared__ float vs[TS_][HD_];
    __shared__ float sc[TS_][TS_ + 1];
    int tid = threadIdx.x;   // 128
    int len = tgt_len[n]; if (len < 1) len = 1;

    for (int e = tid; e < TS_ * HD_; e += 128) {
        int t = e >> 6, d = e & 63;
        const float* base = qkv + (size_t)(t * 8 + n) * (3 * D_) + h * 64 + d;
        qs[t][d] = base[0];
        ks[t][d] = base[512];
        vs[t][d] = base[1024];
    }
    __syncthreads();

    for (int p = tid; p < TS_ * TS_; p += 128) {
        int tq = p / TS_, tk = p - tq * TS_;
        float s;
        if (tk > tq || tk >= len) {
            s = -1e9f;
        } else {
            s = 0.f;
#pragma unroll 8
            for (int d = 0; d < HD_; d++) s += qs[tq][d] * ks[tk][d];
            s *= 0.125f;   // 1/sqrt(64)
        }
        sc[tq][tk] = s;
    }
    __syncthreads();

    if (tid < TS_) {
        int tq = tid;
        float mx = -1e30f;
        for (int tk = 0; tk < TS_; tk++) mx = fmaxf(mx, sc[tq][tk]);
        float sum = 0.f;
        for (int tk = 0; tk < TS_; tk++) {
            float e = expf(sc[tq][tk] - mx);
            sc[tq][tk] = e;
            sum += e;
        }
        float inv = 1.0f / sum;
        for (int tk = 0; tk < TS_; tk++) sc[tq][tk] *= inv;
    }
    __syncthreads();

    for (int e = tid; e < TS_ * HD_; e += 128) {
        int tq = e >> 6, d = e & 63;
        float s = 0.f;
#pragma unroll 8
        for (int tk = 0; tk < TS_; tk++) s += sc[tq][tk] * vs[tk][d];
        o[(size_t)(tq * 8 + n) * D_ + h * 64 + d] = s;
    }
}

// ---------------------------------------------------------------------------
// Fused residual add + layernorm, in place into x. One block per token row.
// ---------------------------------------------------------------------------
__global__ void add_ln_kernel(float* __restrict__ x,
                              const float* __restrict__ y,
                              const float* __restrict__ s,
                              const float* __restrict__ b) {
    int row = blockIdx.x, tid = threadIdx.x;   // 128 threads x 4 elems
    __shared__ float sh[8];
    const float4 xv = ((const float4*)(x + (size_t)row * D_))[tid];
    const float4 yv = ((const float4*)(y + (size_t)row * D_))[tid];
    float r0 = xv.x + yv.x, r1 = xv.y + yv.y, r2 = xv.z + yv.z, r3 = xv.w + yv.w;

    float sum = r0 + r1 + r2 + r3;
    int lane = tid & 31, wp = tid >> 5;
#pragma unroll
    for (int off = 16; off > 0; off >>= 1) sum += __shfl_xor_sync(0xffffffffu, sum, off);
    if (lane == 0) sh[wp] = sum;
    __syncthreads();
    float mean = (sh[0] + sh[1] + sh[2] + sh[3]) * (1.0f / 512.0f);

    float d0 = r0 - mean, d1 = r1 - mean, d2 = r2 - mean, d3 = r3 - mean;
    float sq = d0 * d0 + d1 * d1 + d2 * d2 + d3 * d3;
#pragma unroll
    for (int off = 16; off > 0; off >>= 1) sq += __shfl_xor_sync(0xffffffffu, sq, off);
    if (lane == 0) sh[4 + wp] = sq;
    __syncthreads();
    float var = (sh[4] + sh[5] + sh[6] + sh[7]) * (1.0f / 512.0f);
    float rstd = 1.0f / sqrtf(var + 1e-5f);

    const float4 sv = ((const float4*)s)[tid];
    const float4 bv = ((const float4*)b)[tid];
    float4 out;
    out.x = d0 * rstd * sv.x + bv.x;
    out.y = d1 * rstd * sv.y + bv.y;
    out.z = d2 * rstd * sv.z + bv.z;
    out.w = d3 * rstd * sv.w + bv.w;
    ((float4*)(x + (size_t)row * D_))[tid] = out;
}

// ---------------------------------------------------------------------------
// Joiner A materialization: A[(n,i,t)][d] = tanh(enc[(i,n)][d] + x[(t,n)][d])
// ---------------------------------------------------------------------------
__global__ void joiner_a_kernel(const float* __restrict__ enc,
                                const float* __restrict__ x,
                                float* __restrict__ A) {
    int r = blockIdx.x;                  // 0..33791
    int n = r / (TI_ * TS_);
    int rem = r - n * (TI_ * TS_);
    int i = rem / TS_;
    int t = rem - i * TS_;
    const float4* er = (const float4*)(enc + (size_t)(i * 8 + n) * D_);
    const float4* xr = (const float4*)(x + (size_t)(t * 8 + n) * D_);
    float4* ar = (float4*)(A + (size_t)r * D_);
    int tid = threadIdx.x;               // 128
    float4 e = er[tid], xx = xr[tid], o;
    o.x = tanhf(e.x + xx.x);
    o.y = tanhf(e.y + xx.y);
    o.z = tanhf(e.z + xx.z);
    o.w = tanhf(e.w + xx.w);
    ar[tid] = o;
}

// ---------------------------------------------------------------------------
// Joiner GEMM: C[33792][2000] = A[33792][512] @ W[2000][512]^T
// 128x128x16 tile, 256 threads, 8x8 per-thread in f32x2 pairs.
// ---------------------------------------------------------------------------
__global__ void __launch_bounds__(256) joiner_gemm(const float* __restrict__ A,
                                                   const float* __restrict__ W,
                                                   float* __restrict__ C) {
    __shared__ float As[16][128];
    __shared__ float Bs[16][128];
    const int tid = threadIdx.x;
    const int tx = tid & 15, ty = tid >> 4;    // ty 0..15
    const int m0 = blockIdx.y * 128, n0 = blockIdx.x * 128;

    unsigned long long acc[8][4];
#pragma unroll
    for (int i = 0; i < 8; i++)
#pragma unroll
        for (int j = 0; j < 4; j++) acc[i][j] = 0ull;

    const int lrow = tid >> 1;
    const int lk = (tid & 1) * 8;
    const float* pa = A + (size_t)(m0 + lrow) * D_ + lk;   // M exact multiple of 128
    const int gn = n0 + lrow;
    const float* pb = W + (size_t)gn * D_ + lk;
    const bool bvalid = gn < V_;

    for (int k0 = 0; k0 < D_; k0 += 16) {
        float4 a0 = *(const float4*)(pa + k0);
        float4 a1 = *(const float4*)(pa + k0 + 4);
        float4 b0 = make_float4(0, 0, 0, 0), b1 = b0;
        if (bvalid) {
            b0 = *(const float4*)(pb + k0);
            b1 = *(const float4*)(pb + k0 + 4);
        }
        __syncthreads();
        As[lk + 0][lrow] = a0.x; As[lk + 1][lrow] = a0.y;
        As[lk + 2][lrow] = a0.z; As[lk + 3][lrow] = a0.w;
        As[lk + 4][lrow] = a1.x; As[lk + 5][lrow] = a1.y;
        As[lk + 6][lrow] = a1.z; As[lk + 7][lrow] = a1.w;
        Bs[lk + 0][lrow] = b0.x; Bs[lk + 1][lrow] = b0.y;
        Bs[lk + 2][lrow] = b0.z; Bs[lk + 3][lrow] = b0.w;
        Bs[lk + 4][lrow] = b1.x; Bs[lk + 5][lrow] = b1.y;
        Bs[lk + 6][lrow] = b1.z; Bs[lk + 7][lrow] = b1.w;
        __syncthreads();
#pragma unroll
        for (int k = 0; k < 16; k++) {
            float4 al = *(const float4*)&As[k][ty * 4];
            float4 ah = *(const float4*)&As[k][64 + ty * 4];
            float4 bl = *(const float4*)&Bs[k][tx * 4];
            float4 bh = *(const float4*)&Bs[k][64 + tx * 4];
            unsigned long long bp0 = pk2(bl.x, bl.y), bp1 = pk2(bl.z, bl.w);
            unsigned long long bp2 = pk2(bh.x, bh.y), bp3 = pk2(bh.z, bh.w);
            float av8[8] = {al.x, al.y, al.z, al.w, ah.x, ah.y, ah.z, ah.w};
#pragma unroll
            for (int i = 0; i < 8; i++) {
                unsigned long long ap = pk2(av8[i], av8[i]);
                acc[i][0] = ffma2(ap, bp0, acc[i][0]);
                acc[i][1] = ffma2(ap, bp1, acc[i][1]);
                acc[i][2] = ffma2(ap, bp2, acc[i][2]);
                acc[i][3] = ffma2(ap, bp3, acc[i][3]);
            }
        }
    }

    const bool full = (n0 + 128) <= V_;
#pragma unroll
    for (int i = 0; i < 8; i++) {
        int r = m0 + ((i < 4) ? (ty * 4 + i) : (64 + ty * 4 + (i - 4)));
        float v[8];
        unpk2(acc[i][0], v[0], v[1]); unpk2(acc[i][1], v[2], v[3]);
        unpk2(acc[i][2], v[4], v[5]); unpk2(acc[i][3], v[6], v[7]);
        float* crow = C + (size_t)r * V_;
        if (full) {
            *(float4*)(crow + n0 + tx * 4)      = make_float4(v[0], v[1], v[2], v[3]);
            *(float4*)(crow + n0 + 64 + tx * 4) = make_float4(v[4], v[5], v[6], v[7]);
        } else {
#pragma unroll
            for (int j = 0; j < 8; j++) {
                int c = n0 + ((j < 4) ? (tx * 4 + j) : (64 + tx * 4 + (j - 4)));
                if (c < V_) crow[c] = v[j];
            }
        }
    }
}

// ---------------------------------------------------------------------------
// Host orchestration (graph-capturable: kernel launches only)
// ---------------------------------------------------------------------------
extern "C" void kernel_launch(void* const* d_in, const int* in_sizes, int n_in,
                              void* d_out, int out_size) {
    const float* enc_out = (const float*)d_in[0];
    const float* embed_w = (const float*)d_in[1];
    const float* enc_w   = (const float*)d_in[2];
    const float* enc_b   = (const float*)d_in[3];
    const float* qkv_w   = (const float*)d_in[4];
    const float* qkv_b   = (const float*)d_in[5];
    const float* o_w     = (const float*)d_in[6];
    const float* o_b     = (const float*)d_in[7];
    const float* ln1_s   = (const float*)d_in[8];
    const float* ln1_b   = (const float*)d_in[9];
    const float* ff1_w   = (const float*)d_in[10];
    const float* ff1_b   = (const float*)d_in[11];
    const float* ff2_w   = (const float*)d_in[12];
    const float* ff2_b   = (const float*)d_in[13];
    const float* ln2_s   = (const float*)d_in[14];
    const float* ln2_b   = (const float*)d_in[15];
    const float* out_w   = (const float*)d_in[16];
    const int*   tgt_pad = (const int*)d_in[17];
    const int*   tgt_len = (const int*)d_in[18];
    const int*   sos     = (const int*)d_in[19];

    float* S = nullptr;
    cudaGetSymbolAddress((void**)&S, g_scratch);
    float* x    = S + OFF_X;
    float* qkv  = S + OFF_QKV;
    float* attn = S + OFF_ATTN;
    float* tmp  = S + OFF_TMP;
    float* ffh  = S + OFF_FFH;
    float* encp = S + OFF_ENC;
    float* Abuf = S + OFF_A;

    // enc projection (independent of decoder layers)
    gemm64<<<dim3(D_ / 64, (TI_ * NB_) / 64), 128>>>(enc_out, enc_w, enc_b, encp,
                                                     TI_ * NB_, D_, D_, 0);

    // embedding + positions
    embed_kernel<<<TOK_, 128>>>(embed_w, tgt_pad, sos, x);

    // 6 post-norm transformer layers
    for (int l = 0; l < L_; l++) {
        gemm64<<<dim3((3 * D_) / 64, (TOK_ + 63) / 64), 128>>>(
            x, qkv_w + (size_t)l * 3 * D_ * D_, qkv_b + (size_t)l * 3 * D_,
            qkv, TOK_, 3 * D_, D_, 0);
        attention_kernel<<<NB_ * H_, 128>>>(qkv, tgt_len, attn);
        gemm64<<<dim3(D_ / 64, (TOK_ + 63) / 64), 128>>>(
            attn, o_w + (size_t)l * D_ * D_, o_b + (size_t)l * D_,
            tmp, TOK_, D_, D_, 0);
        add_ln_kernel<<<TOK_, 128>>>(x, tmp, ln1_s + (size_t)l * D_, ln1_b + (size_t)l * D_);
        gemm64<<<dim3(FF_ / 64, (TOK_ + 63) / 64), 128>>>(
            x, ff1_w + (size_t)l * FF_ * D_, ff1_b + (size_t)l * FF_,
            ffh, TOK_, FF_, D_, 1);
        gemm64<<<dim3(D_ / 64, (TOK_ + 63) / 64), 128>>>(
            ffh, ff2_w + (size_t)l * D_ * FF_, ff2_b + (size_t)l * D_,
            tmp, TOK_, D_, FF_, 0);
        add_ln_kernel<<<TOK_, 128>>>(x, tmp, ln2_s + (size_t)l * D_, ln2_b + (size_t)l * D_);
    }

    // joiner: A = tanh(enc + x) ordered (n,i,t), then A @ out_w^T -> d_out
    joiner_a_kernel<<<MJ_, 128>>>(encp, x, Abuf);
    joiner_gemm<<<dim3((V_ + 127) / 128, MJ_ / 128), 256>>>(Abuf, out_w, (float*)d_out);
}

// round 3
// speedup vs baseline: 2.4184x; 2.4184x over previous
#include <cuda_runtime.h>
#include <cuda_bf16.h>
#include <math.h>
#include <stdint.h>

// ---------------------------------------------------------------------------
// Arch-feature gate: tcgen05 only exists on the sm_10Xa targets. The harness's
// PTX pass targets base compute_103, where tcgen05 is ILLEGAL — so that pass
// gets an mma.sync.bf16 implementation instead (base-target instruction).
// ---------------------------------------------------------------------------
#if defined(__CUDA_ARCH_FEAT_SM103_ALL) || defined(__CUDA_ARCH_FEAT_SM100_ALL) || defined(__CUDA_ARCH_FEAT_SM101_ALL)
#define USE_TCGEN05 1
#else
#define USE_TCGEN05 0
#endif

// ---------------------------------------------------------------------------
// Problem constants
// ---------------------------------------------------------------------------
#define TI_   128
#define NB_   8
#define TO_   32
#define TS_   33
#define D_    512
#define H_    8
#define HD_   64
#define FF_   2048
#define V_    2000
#define VP_   2048
#define L_    6
#define TOK_  (TS_ * NB_)          // 264
#define MJ_   (NB_ * TI_ * TS_)    // 33792

// ---------------------------------------------------------------------------
// Scratch
// ---------------------------------------------------------------------------
#define OFF_X     0
#define SZ_X      (TOK_ * D_)
#define OFF_QKV   (OFF_X + SZ_X)
#define SZ_QKV    (TOK_ * 3 * D_)
#define OFF_ATTN  (OFF_QKV + SZ_QKV)
#define SZ_ATTN   (TOK_ * D_)
#define OFF_TMP   (OFF_ATTN + SZ_ATTN)
#define SZ_TMP    (TOK_ * D_)
#define OFF_FFH   (OFF_TMP + SZ_TMP)
#define SZ_FFH    (TOK_ * FF_)
#define OFF_ENC   (OFF_FFH + SZ_FFH)
#define SZ_ENC    (TI_ * NB_ * D_)
#define SCRATCH_TOTAL (OFF_ENC + SZ_ENC)

__device__ float g_scratch[SCRATCH_TOTAL];

__device__ __nv_bfloat16 g_Ah[(size_t)MJ_ * D_];
__device__ __nv_bfloat16 g_Al[(size_t)MJ_ * D_];
__device__ __nv_bfloat16 g_Wh[(size_t)VP_ * D_];
__device__ __nv_bfloat16 g_Wl[(size_t)VP_ * D_];

// ---------------------------------------------------------------------------
// PTX helpers
// ---------------------------------------------------------------------------
__device__ __forceinline__ uint32_t elect_one_pred() {
    uint32_t pred;
    asm volatile(
        "{\n\t.reg .pred p;\n\telect.sync _|p, 0xFFFFFFFF;\n\t"
        "selp.b32 %0, 1, 0, p;\n\t}"
        : "=r"(pred));
    return pred;
}
__device__ __forceinline__ uint32_t smem_to_u32(const void* smem_ptr) {
    uint32_t addr;
    asm("{ .reg .u64 tmp; cvta.to.shared.u64 tmp, %1; cvt.u32.u64 %0, tmp; }"
        : "=r"(addr) : "l"(smem_ptr));
    return addr;
}
__device__ __forceinline__ uint32_t sw_off(uint32_t bo) {
    return bo ^ ((bo >> 3) & 0x70);
}

static constexpr uint64_t SMEM_DESC_BASE_SW128 =
    (uint64_t(2)  << 61) | (uint64_t(1) << 46) | (uint64_t(64) << 32) | (uint64_t(1) << 16);
#define MAKE_SMEM_DESC(base_addr) \
    (SMEM_DESC_BASE_SW128 | ((uint64_t)((base_addr) >> 4) & 0x3FFF))

#if USE_TCGEN05
#define TCGEN05_ALLOC(smem_result_addr, nCols) \
    asm volatile("tcgen05.alloc.cta_group::1.sync.aligned.shared::cta.b32 [%0], %1;" \
        :: "r"((uint32_t)(smem_result_addr)), "r"((uint32_t)(nCols)) : "memory")
#define TCGEN05_DEALLOC(tmem_addr, nCols) \
    asm volatile("tcgen05.dealloc.cta_group::1.sync.aligned.b32 %0, %1;" \
        :: "r"(tmem_addr), "r"((uint32_t)(nCols)))
#define TCGEN05_RELINQUISH_ALLOC_PERMIT() \
    asm volatile("tcgen05.relinquish_alloc_permit.cta_group::1.sync.aligned;")
#define TCGEN05_COMMIT(mbar_smem_addr) \
    asm volatile("tcgen05.commit.cta_group::1.mbarrier::arrive::one.shared::cluster.b64 [%0];" \
        :: "r"((uint32_t)(mbar_smem_addr)) : "memory")
#define TCGEN05_WAIT_LD() \
    asm volatile("tcgen05.wait::ld.sync.aligned;" ::: "memory")
#define TCGEN05_FENCE_AFTER() \
    asm volatile("tcgen05.fence::after_thread_sync;" ::: "memory")
#define FENCE_PROXY_ASYNC_SHARED_CTA() \
    asm volatile("fence.proxy.async.shared::cta;" ::: "memory")
#define MBARRIER_INIT(mbar_smem_addr, count) \
    asm volatile("mbarrier.init.shared.b64 [%0], %1;" \
        :: "r"((uint32_t)(mbar_smem_addr)), "r"((uint32_t)(count)) : "memory")
#define MBARRIER_INVAL(mbar_smem_addr) \
    asm volatile("mbarrier.inval.shared.b64 [%0];" :: "r"((uint32_t)(mbar_smem_addr)) : "memory")
#define MBARRIER_WAIT_PARITY(mbar_smem_addr, phase_parity) do { \
    uint32_t _mbar = (uint32_t)(mbar_smem_addr); \
    uint32_t _parity = (uint32_t)(phase_parity); \
    uint32_t _done; \
    asm volatile( \
        "{\n\t.reg .pred p;\n\t" \
        "mbarrier.try_wait.parity.acquire.cta.shared::cta.b64 p, [%1], %2;\n\t" \
        "selp.b32 %0, 1, 0, p;\n\t}" \
        : "=r"(_done) : "r"(_mbar), "r"(_parity) : "memory"); \
    if (!_done) { \
        asm volatile( \
            "{\n\t.reg .pred P1;\n\t" \
            "WAIT_LOOP_%=:\n\t" \
            "mbarrier.try_wait.parity.acquire.cta.shared::cta.b64 P1, [%0], %1, 0x989680;\n\t" \
            "@P1 bra.uni WAIT_DONE_%=;\n\t" \
            "bra.uni WAIT_LOOP_%=;\n\t" \
            "WAIT_DONE_%=:\n\t}" \
            :: "r"(_mbar), "r"(_parity) : "memory"); \
    } \
} while(0)
#define TCGEN05_LD_32X32B_X32(r, tmem_addr) \
    asm volatile( \
        "tcgen05.ld.sync.aligned.32x32b.x32.b32 " \
        "{%0, %1, %2, %3, %4, %5, %6, %7, " \
        " %8, %9, %10, %11, %12, %13, %14, %15, " \
        " %16, %17, %18, %19, %20, %21, %22, %23, " \
        " %24, %25, %26, %27, %28, %29, %30, %31}, [%32];" \
        : "=r"((r)[0]),  "=r"((r)[1]),  "=r"((r)[2]),  "=r"((r)[3]), \
          "=r"((r)[4]),  "=r"((r)[5]),  "=r"((r)[6]),  "=r"((r)[7]), \
          "=r"((r)[8]),  "=r"((r)[9]),  "=r"((r)[10]), "=r"((r)[11]), \
          "=r"((r)[12]), "=r"((r)[13]), "=r"((r)[14]), "=r"((r)[15]), \
          "=r"((r)[16]), "=r"((r)[17]), "=r"((r)[18]), "=r"((r)[19]), \
          "=r"((r)[20]), "=r"((r)[21]), "=r"((r)[22]), "=r"((r)[23]), \
          "=r"((r)[24]), "=r"((r)[25]), "=r"((r)[26]), "=r"((r)[27]), \
          "=r"((r)[28]), "=r"((r)[29]), "=r"((r)[30]), "=r"((r)[31]) \
        : "r"(tmem_addr))

__device__ __forceinline__ void mma_f16_ss_cg1(uint32_t d_tmem, uint64_t a_desc,
                                               uint64_t b_desc, uint32_t idesc,
                                               uint32_t enable) {
    asm volatile(
        "{\n\t.reg .pred p;\n\t"
        "setp.ne.u32 p, %4, 0;\n\t"
        "tcgen05.mma.cta_group::1.kind::f16 [%0], %1, %2, %3, {%5, %5, %5, %5}, p;\n\t}"
        :: "r"(d_tmem), "l"(a_desc), "l"(b_desc), "r"(idesc), "r"(enable), "r"(0u)
        : "memory");
}
// dtype F32, atype/btype BF16, N=128, M=128
#define JOINER_IDESC 0x8200490u
#endif // USE_TCGEN05

// ---------------------------------------------------------------------------
// Base-target MMA helpers (mma.sync path)
// ---------------------------------------------------------------------------
__device__ __forceinline__ void ldmatrix_x4(uint32_t* r, uint32_t addr) {
    asm volatile("ldmatrix.sync.aligned.m8n8.x4.shared.b16 {%0,%1,%2,%3}, [%4];"
        : "=r"(r[0]), "=r"(r[1]), "=r"(r[2]), "=r"(r[3]) : "r"(addr));
}
__device__ __forceinline__ void mma16816(float* d, const uint32_t* a,
                                         uint32_t b0, uint32_t b1) {
    asm volatile(
        "mma.sync.aligned.m16n8k16.row.col.f32.bf16.bf16.f32 "
        "{%0,%1,%2,%3}, {%4,%5,%6,%7}, {%8,%9}, {%0,%1,%2,%3};"
        : "+f"(d[0]), "+f"(d[1]), "+f"(d[2]), "+f"(d[3])
        : "r"(a[0]), "r"(a[1]), "r"(a[2]), "r"(a[3]), "r"(b0), "r"(b1));
}

// ---------------------------------------------------------------------------
// f32x2 packed-FMA helpers
// ---------------------------------------------------------------------------
__device__ __forceinline__ unsigned long long pk2(float lo, float hi) {
    unsigned long long r;
    asm("mov.b64 %0, {%1, %2};" : "=l"(r) : "f"(lo), "f"(hi));
    return r;
}
__device__ __forceinline__ void unpk2(unsigned long long v, float& lo, float& hi) {
    asm("mov.b64 {%0, %1}, %2;" : "=f"(lo), "=f"(hi) : "l"(v));
}
__device__ __forceinline__ unsigned long long ffma2(unsigned long long a,
                                                    unsigned long long b,
                                                    unsigned long long c) {
    unsigned long long d;
    asm("fma.rn.f32x2 %0, %1, %2, %3;" : "=l"(d) : "l"(a), "l"(b), "l"(c));
    return d;
}

// ---------------------------------------------------------------------------
// Embedding + positional encoding
// ---------------------------------------------------------------------------
__global__ void embed_kernel(const float* __restrict__ embed,
                             const int* __restrict__ tgt_pad,
                             const int* __restrict__ sos,
                             float* __restrict__ x) {
    int r = blockIdx.x;
    int t = r >> 3, n = r & 7;
    int tok = (t == 0) ? sos[0] : tgt_pad[n * TO_ + (t - 1)];
    const float* e = embed + (size_t)tok * D_;
    const float sc = sqrtf(512.0f);
    int tid = threadIdx.x;
#pragma unroll
    for (int i = 0; i < 4; i++) {
        int d = tid * 4 + i;
        int half = d >> 1;
        double ddiv = exp((double)(2 * half) * (-9.210340371976184 / 512.0));
        double ang = (double)t * ddiv;
        double pv = (d & 1) ? cos(ang) : sin(ang);
        x[(size_t)r * D_ + d] = e[d] * sc + (float)pv;
    }
}

// ---------------------------------------------------------------------------
// Generic small GEMM (layer chain): C = A @ W^T + bias, optional relu
// ---------------------------------------------------------------------------
__global__ void __launch_bounds__(128) gemm64(const float* __restrict__ A,
                                              const float* __restrict__ W,
                                              const float* __restrict__ bias,
                                              float* __restrict__ C,
                                              int M, int N, int K, int relu) {
    __shared__ float As[16][64];
    __shared__ float Bs[16][64];
    const int tid = threadIdx.x;
    const int tx = tid & 15, ty = tid >> 4;
    const int m0 = blockIdx.y * 64, n0 = blockIdx.x * 64;

    unsigned long long acc[8][2];
#pragma unroll
    for (int i = 0; i < 8; i++) { acc[i][0] = 0ull; acc[i][1] = 0ull; }

    const int lrow = tid >> 1;
    const int lk = (tid & 1) * 8;
    const int gm = m0 + lrow, gn = n0 + lrow;
    const bool avalid = gm < M, bvalid = gn < N;
    const float* pa = A + (size_t)gm * K + lk;
    const float* pb = W + (size_t)gn * K + lk;

    for (int k0 = 0; k0 < K; k0 += 16) {
        float4 a0 = make_float4(0, 0, 0, 0), a1 = a0, b0 = a0, b1 = a0;
        if (avalid) {
            a0 = *(const float4*)(pa + k0);
            a1 = *(const float4*)(pa + k0 + 4);
        }
        if (bvalid) {
            b0 = *(const float4*)(pb + k0);
            b1 = *(const float4*)(pb + k0 + 4);
        }
        __syncthreads();
        As[lk + 0][lrow] = a0.x; As[lk + 1][lrow] = a0.y;
        As[lk + 2][lrow] = a0.z; As[lk + 3][lrow] = a0.w;
        As[lk + 4][lrow] = a1.x; As[lk + 5][lrow] = a1.y;
        As[lk + 6][lrow] = a1.z; As[lk + 7][lrow] = a1.w;
        Bs[lk + 0][lrow] = b0.x; Bs[lk + 1][lrow] = b0.y;
        Bs[lk + 2][lrow] = b0.z; Bs[lk + 3][lrow] = b0.w;
        Bs[lk + 4][lrow] = b1.x; Bs[lk + 5][lrow] = b1.y;
        Bs[lk + 6][lrow] = b1.z; Bs[lk + 7][lrow] = b1.w;
        __syncthreads();
#pragma unroll
        for (int k = 0; k < 16; k++) {
            float4 al = *(const float4*)&As[k][ty * 4];
            float4 ah = *(const float4*)&As[k][32 + ty * 4];
            float4 b  = *(const float4*)&Bs[k][tx * 4];
            unsigned long long bp0 = pk2(b.x, b.y), bp1 = pk2(b.z, b.w);
            float av8[8] = {al.x, al.y, al.z, al.w, ah.x, ah.y, ah.z, ah.w};
#pragma unroll
            for (int i = 0; i < 8; i++) {
                unsigned long long ap = pk2(av8[i], av8[i]);
                acc[i][0] = ffma2(ap, bp0, acc[i][0]);
                acc[i][1] = ffma2(ap, bp1, acc[i][1]);
            }
        }
    }
#pragma unroll
    for (int i = 0; i < 8; i++) {
        int r = m0 + ((i < 4) ? (ty * 4 + i) : (32 + ty * 4 + (i - 4)));
        if (r < M) {
            float v[4];
            unpk2(acc[i][0], v[0], v[1]);
            unpk2(acc[i][1], v[2], v[3]);
#pragma unroll
            for (int j = 0; j < 4; j++) {
                int c = n0 + tx * 4 + j;
                if (c < N) {
                    float o = v[j] + bias[c];
                    if (relu && o < 0.f) o = 0.f;
                    C[(size_t)r * N + c] = o;
                }
            }
        }
    }
}

// ---------------------------------------------------------------------------
// Attention
// ---------------------------------------------------------------------------
__global__ void attention_kernel(const float* __restrict__ qkv,
                                 const int* __restrict__ tgt_len,
                                 float* __restrict__ o) {
    int n = blockIdx.x >> 3, h = blockIdx.x & 7;
    __shared__ float qs[TS_][HD_];
    __shared__ float ks[TS_][HD_];
    __shared__ float vs[TS_][HD_];
    __shared__ float sc[TS_][TS_ + 1];
    int tid = threadIdx.x;
    int len = tgt_len[n]; if (len < 1) len = 1;

    for (int e = tid; e < TS_ * HD_; e += 128) {
        int t = e >> 6, d = e & 63;
        const float* base = qkv + (size_t)(t * 8 + n) * (3 * D_) + h * 64 + d;
        qs[t][d] = base[0];
        ks[t][d] = base[512];
        vs[t][d] = base[1024];
    }
    __syncthreads();

    for (int p = tid; p < TS_ * TS_; p += 128) {
        int tq = p / TS_, tk = p - tq * TS_;
        float s;
        if (tk > tq || tk >= len) {
            s = -1e9f;
        } else {
            s = 0.f;
#pragma unroll 8
            for (int d = 0; d < HD_; d++) s += qs[tq][d] * ks[tk][d];
            s *= 0.125f;
        }
        sc[tq][tk] = s;
    }
    __syncthreads();

    if (tid < TS_) {
        int tq = tid;
        float mx = -1e30f;
        for (int tk = 0; tk < TS_; tk++) mx = fmaxf(mx, sc[tq][tk]);
        float sum = 0.f;
        for (int tk = 0; tk < TS_; tk++) {
            float e = expf(sc[tq][tk] - mx);
            sc[tq][tk] = e;
            sum += e;
        }
        float inv = 1.0f / sum;
        for (int tk = 0; tk < TS_; tk++) sc[tq][tk] *= inv;
    }
    __syncthreads();

    for (int e = tid; e < TS_ * HD_; e += 128) {
        int tq = e >> 6, d = e & 63;
        float s = 0.f;
#pragma unroll 8
        for (int tk = 0; tk < TS_; tk++) s += sc[tq][tk] * vs[tk][d];
        o[(size_t)(tq * 8 + n) * D_ + h * 64 + d] = s;
    }
}

// ---------------------------------------------------------------------------
// Fused residual add + layernorm
// ---------------------------------------------------------------------------
__global__ void add_ln_kernel(float* __restrict__ x,
                              const float* __restrict__ y,
                              const float* __restrict__ s,
                              const float* __restrict__ b) {
    int row = blockIdx.x, tid = threadIdx.x;
    __shared__ float sh[8];
    const float4 xv = ((const float4*)(x + (size_t)row * D_))[tid];
    const float4 yv = ((const float4*)(y + (size_t)row * D_))[tid];
    float r0 = xv.x + yv.x, r1 = xv.y + yv.y, r2 = xv.z + yv.z, r3 = xv.w + yv.w;

    float sum = r0 + r1 + r2 + r3;
    int lane = tid & 31, wp = tid >> 5;
#pragma unroll
    for (int off = 16; off > 0; off >>= 1) sum += __shfl_xor_sync(0xffffffffu, sum, off);
    if (lane == 0) sh[wp] = sum;
    __syncthreads();
    float mean = (sh[0] + sh[1] + sh[2] + sh[3]) * (1.0f / 512.0f);

    float d0 = r0 - mean, d1 = r1 - mean, d2 = r2 - mean, d3 = r3 - mean;
    float sq = d0 * d0 + d1 * d1 + d2 * d2 + d3 * d3;
#pragma unroll
    for (int off = 16; off > 0; off >>= 1) sq += __shfl_xor_sync(0xffffffffu, sq, off);
    if (lane == 0) sh[4 + wp] = sq;
    __syncthreads();
    float var = (sh[4] + sh[5] + sh[6] + sh[7]) * (1.0f / 512.0f);
    float rstd = 1.0f / sqrtf(var + 1e-5f);

    const float4 sv = ((const float4*)s)[tid];
    const float4 bv = ((const float4*)b)[tid];
    float4 out;
    out.x = d0 * rstd * sv.x + bv.x;
    out.y = d1 * rstd * sv.y + bv.y;
    out.z = d2 * rstd * sv.z + bv.z;
    out.w = d3 * rstd * sv.w + bv.w;
    ((float4*)(x + (size_t)row * D_))[tid] = out;
}

// ---------------------------------------------------------------------------
// Joiner A materialization + bf16 hi/lo split
// ---------------------------------------------------------------------------
__global__ void joiner_a_split_kernel(const float* __restrict__ enc,
                                      const float* __restrict__ x,
                                      __nv_bfloat16* __restrict__ Ah,
                                      __nv_bfloat16* __restrict__ Al) {
    int r = blockIdx.x;
    int n = r / (TI_ * TS_);
    int rem = r - n * (TI_ * TS_);
    int i = rem / TS_;
    int t = rem - i * TS_;
    const float4* er = (const float4*)(enc + (size_t)(i * 8 + n) * D_);
    const float4* xr = (const float4*)(x + (size_t)(t * 8 + n) * D_);
    int tid = threadIdx.x;   // 128
    float4 e = er[tid], xx = xr[tid];
    float a[4] = {tanhf(e.x + xx.x), tanhf(e.y + xx.y),
                  tanhf(e.z + xx.z), tanhf(e.w + xx.w)};
    __nv_bfloat162 h2[2], l2[2];
#pragma unroll
    for (int j = 0; j < 2; j++) {
        __nv_bfloat16 h0 = __float2bfloat16(a[2 * j]);
        __nv_bfloat16 h1 = __float2bfloat16(a[2 * j + 1]);
        __nv_bfloat16 l0 = __float2bfloat16(a[2 * j] - __bfloat162float(h0));
        __nv_bfloat16 l1 = __float2bfloat16(a[2 * j + 1] - __bfloat162float(h1));
        h2[j] = __nv_bfloat162(h0, h1);
        l2[j] = __nv_bfloat162(l0, l1);
    }
    size_t base = (size_t)r * D_ + tid * 4;
    ((__nv_bfloat162*)(Ah + base))[0] = h2[0];
    ((__nv_bfloat162*)(Ah + base))[1] = h2[1];
    ((__nv_bfloat162*)(Al + base))[0] = l2[0];
    ((__nv_bfloat162*)(Al + base))[1] = l2[1];
}

__global__ void w_split_kernel(const float* __restrict__ W,
                               __nv_bfloat16* __restrict__ Wh,
                               __nv_bfloat16* __restrict__ Wl) {
    int r = blockIdx.x;
    int tid = threadIdx.x;
    size_t base = (size_t)r * D_ + tid * 4;
    if (r < V_) {
        const float4 w = ((const float4*)(W + (size_t)r * D_))[tid];
        float a[4] = {w.x, w.y, w.z, w.w};
        __nv_bfloat162 h2[2], l2[2];
#pragma unroll
        for (int j = 0; j < 2; j++) {
            __nv_bfloat16 h0 = __float2bfloat16(a[2 * j]);
            __nv_bfloat16 h1 = __float2bfloat16(a[2 * j + 1]);
            __nv_bfloat16 l0 = __float2bfloat16(a[2 * j] - __bfloat162float(h0));
            __nv_bfloat16 l1 = __float2bfloat16(a[2 * j + 1] - __bfloat162float(h1));
            h2[j] = __nv_bfloat162(h0, h1);
            l2[j] = __nv_bfloat162(l0, l1);
        }
        ((__nv_bfloat162*)(Wh + base))[0] = h2[0];
        ((__nv_bfloat162*)(Wh + base))[1] = h2[1];
        ((__nv_bfloat162*)(Wl + base))[0] = l2[0];
        ((__nv_bfloat162*)(Wl + base))[1] = l2[1];
    } else {
        __nv_bfloat162 z = __nv_bfloat162(__float2bfloat16(0.f), __float2bfloat16(0.f));
        ((__nv_bfloat162*)(Wh + base))[0] = z;
        ((__nv_bfloat162*)(Wh + base))[1] = z;
        ((__nv_bfloat162*)(Wl + base))[0] = z;
        ((__nv_bfloat162*)(Wl + base))[1] = z;
    }
}

// ---------------------------------------------------------------------------
// Tensor-core joiner GEMM:
// C[33792][2000] = (Ah+Al) @ (Wh+Wl)^T  via 3-term bf16 (AhWh + AhWl + AlWh)
// Tile 128x128, K chunks of 64 (128B SW128 rows), 256 threads.
// ---------------------------------------------------------------------------
#define JT_CHUNKS   8
#define JT_BUF      16384
#define JT_SM_AH    1024
#define JT_SM_AL    (JT_SM_AH + JT_BUF)
#define JT_SM_WH    (JT_SM_AL + JT_BUF)
#define JT_SM_WL    (JT_SM_WH + JT_BUF)
#define JT_SMEM     (JT_SM_WL + JT_BUF)      // 66560 bytes

__device__ __forceinline__ void jt_load_tile(const __nv_bfloat16* __restrict__ src,
                                             int row0, int koff,
                                             char* sm, int tid) {
    // 128 rows x 64 bf16 (128B per row), SW128 swizzle, 16B vector loads
#pragma unroll
    for (int p = 0; p < 4; p++) {
        int idx = p * 256 + tid;
        int row = idx >> 3, seg = idx & 7;
        uint4 v = *(const uint4*)(src + (size_t)(row0 + row) * D_ + koff + seg * 8);
        uint32_t bo = (uint32_t)(row * 128 + seg * 16);
        *(uint4*)(sm + sw_off(bo)) = v;
    }
}

__global__ void __launch_bounds__(256) joiner_tc_kernel(
    const __nv_bfloat16* __restrict__ Ah,
    const __nv_bfloat16* __restrict__ Al,
    const __nv_bfloat16* __restrict__ Wh,
    const __nv_bfloat16* __restrict__ Wl,
    float* __restrict__ C) {
    extern __shared__ char smem[];
    const int tid = threadIdx.x;
    const int n0 = blockIdx.x * 128;   // vocab tile
    const int m0 = blockIdx.y * 128;   // joiner-row tile

#if USE_TCGEN05
    const uint32_t smem_base = smem_to_u32(smem);
    const int wid = tid >> 5, lane = tid & 31;

    if (wid == 0) {
        TCGEN05_ALLOC(smem_base, 128);
        TCGEN05_RELINQUISH_ALLOC_PERMIT();
    }
    if (tid == 0) MBARRIER_INIT(smem_base + 8, 1);
    __syncthreads();
    uint32_t tmem_base;
    asm volatile("ld.shared.b32 %0, [%1];" : "=r"(tmem_base) : "r"(smem_base));

    const uint64_t dAh = MAKE_SMEM_DESC(smem_base + JT_SM_AH);
    const uint64_t dAl = MAKE_SMEM_DESC(smem_base + JT_SM_AL);
    const uint64_t dWh = MAKE_SMEM_DESC(smem_base + JT_SM_WH);
    const uint64_t dWl = MAKE_SMEM_DESC(smem_base + JT_SM_WL);

    for (int c = 0; c < JT_CHUNKS; c++) {
        if (c > 0) MBARRIER_WAIT_PARITY(smem_base + 8, (c - 1) & 1);
        const int koff = c * 64;
        jt_load_tile(Ah, m0, koff, smem + JT_SM_AH, tid);
        jt_load_tile(Al, m0, koff, smem + JT_SM_AL, tid);
        jt_load_tile(Wh, n0, koff, smem + JT_SM_WH, tid);
        jt_load_tile(Wl, n0, koff, smem + JT_SM_WL, tid);
        __syncthreads();
        if (wid == 0) {
            if (elect_one_pred()) {
                FENCE_PROXY_ASYNC_SHARED_CTA();
#pragma unroll
                for (int k = 0; k < 4; k++)
                    mma_f16_ss_cg1(tmem_base, dAh + k * 2, dWh + k * 2,
                                   JOINER_IDESC, (c > 0) || (k > 0));
#pragma unroll
                for (int k = 0; k < 4; k++)
                    mma_f16_ss_cg1(tmem_base, dAh + k * 2, dWl + k * 2,
                                   JOINER_IDESC, 1u);
#pragma unroll
                for (int k = 0; k < 4; k++)
                    mma_f16_ss_cg1(tmem_base, dAl + k * 2, dWh + k * 2,
                                   JOINER_IDESC, 1u);
                TCGEN05_COMMIT(smem_base + 8);
            }
        }
    }
    MBARRIER_WAIT_PARITY(smem_base + 8, (JT_CHUNKS - 1) & 1);
    TCGEN05_FENCE_AFTER();

    // Epilogue: 8 warps; warp w covers rows (w%4)*32, cols half (w/4)*64
    {
        const int sub = wid & 3;
        const int halfc = (wid >> 2) * 64;
        float* crow = C + (size_t)(m0 + sub * 32 + lane) * V_;
        const bool full = (n0 + 128) <= V_;
#pragma unroll
        for (int base = halfc; base < halfc + 64; base += 32) {
            uint32_t r[32];
            TCGEN05_LD_32X32B_X32(r, tmem_base + base);
            TCGEN05_WAIT_LD();
            if (full) {
#pragma unroll
                for (int j = 0; j < 32; j += 4) {
                    *(float4*)(crow + n0 + base + j) =
                        make_float4(__uint_as_float(r[j]), __uint_as_float(r[j + 1]),
                                    __uint_as_float(r[j + 2]), __uint_as_float(r[j + 3]));
                }
            } else {
#pragma unroll
                for (int j = 0; j < 32; j++) {
                    int col = n0 + base + j;
                    if (col < V_) crow[col] = __uint_as_float(r[j]);
                }
            }
        }
    }
    __syncthreads();
    if (wid == 0) {
        if (elect_one_pred()) MBARRIER_INVAL(smem_base + 8);
        TCGEN05_DEALLOC(tmem_base, 128);
    }

#else  // ---------------- mma.sync.bf16 path (base sm_103 target) ----------
    const uint32_t sbase = smem_to_u32(smem);
    const int w = tid >> 5, lane = tid & 31;
    const int wr = w >> 1;        // 0..3 -> 32-row block
    const int wc = w & 1;         // 0..1 -> 64-col block

    float acc[16][4];             // [mi*8+nt][4]
#pragma unroll
    for (int i = 0; i < 16; i++)
#pragma unroll
        for (int j = 0; j < 4; j++) acc[i][j] = 0.f;

    const int aoffs[3] = {JT_SM_AH, JT_SM_AH, JT_SM_AL};
    const int boffs[3] = {JT_SM_WH, JT_SM_WL, JT_SM_WH};

    for (int c = 0; c < JT_CHUNKS; c++) {
        const int koff = c * 64;
        jt_load_tile(Ah, m0, koff, smem + JT_SM_AH, tid);
        jt_load_tile(Al, m0, koff, smem + JT_SM_AL, tid);
        jt_load_tile(Wh, n0, koff, smem + JT_SM_WH, tid);
        jt_load_tile(Wl, n0, koff, smem + JT_SM_WL, tid);
        __syncthreads();
#pragma unroll
        for (int s = 0; s < 4; s++) {          // 4 k16 steps per chunk
#pragma unroll
            for (int tm = 0; tm < 3; tm++) {   // 3 precision terms
                uint32_t afrag[2][4];
#pragma unroll
                for (int mi = 0; mi < 2; mi++) {
                    uint32_t bo = (uint32_t)((wr * 32 + mi * 16 + (lane & 15)) * 128
                                             + s * 32 + (lane >> 4) * 16);
                    ldmatrix_x4(afrag[mi], sbase + aoffs[tm] + sw_off(bo));
                }
                const char* bp = smem + boffs[tm];
#pragma unroll
                for (int nt = 0; nt < 8; nt++) {
                    uint32_t bo0 = (uint32_t)((wc * 64 + nt * 8 + (lane >> 2)) * 128
                                              + s * 32 + (lane & 3) * 4);
                    uint32_t b0 = *(const uint32_t*)(bp + sw_off(bo0));
                    uint32_t b1 = *(const uint32_t*)(bp + sw_off(bo0 + 16));
                    mma16816(acc[nt], afrag[0], b0, b1);
                    mma16816(acc[8 + nt], afrag[1], b0, b1);
                }
            }
        }
        __syncthreads();
    }

    // Epilogue: c0,c1 -> row g, cols 2*(lane%4); c2,c3 -> row g+8
#pragma unroll
    for (int mi = 0; mi < 2; mi++) {
#pragma unroll
        for (int nt = 0; nt < 8; nt++) {
            int m = m0 + wr * 32 + mi * 16 + (lane >> 2);
            int ncol = n0 + wc * 64 + nt * 8 + 2 * (lane & 3);
            if (ncol < V_) {
                float* p0 = C + (size_t)m * V_ + ncol;
                float* p1 = C + (size_t)(m + 8) * V_ + ncol;
                *(float2*)p0 = make_float2(acc[mi * 8 + nt][0], acc[mi * 8 + nt][1]);
                *(float2*)p1 = make_float2(acc[mi * 8 + nt][2], acc[mi * 8 + nt][3]);
            }
        }
    }
#endif
}

// ---------------------------------------------------------------------------
// Host orchestration
// ---------------------------------------------------------------------------
extern "C" void kernel_launch(void* const* d_in, const int* in_sizes, int n_in,
                              void* d_out, int out_size) {
    const float* enc_out = (const float*)d_in[0];
    const float* embed_w = (const float*)d_in[1];
    const float* enc_w   = (const float*)d_in[2];
    const float* enc_b   = (const float*)d_in[3];
    const float* qkv_w   = (const float*)d_in[4];
    const float* qkv_b   = (const float*)d_in[5];
    const float* o_w     = (const float*)d_in[6];
    const float* o_b     = (const float*)d_in[7];
    const float* ln1_s   = (const float*)d_in[8];
    const float* ln1_b   = (const float*)d_in[9];
    const float* ff1_w   = (const float*)d_in[10];
    const float* ff1_b   = (const float*)d_in[11];
    const float* ff2_w   = (const float*)d_in[12];
    const float* ff2_b   = (const float*)d_in[13];
    const float* ln2_s   = (const float*)d_in[14];
    const float* ln2_b   = (const float*)d_in[15];
    const float* out_w   = (const float*)d_in[16];
    const int*   tgt_pad = (const int*)d_in[17];
    const int*   tgt_len = (const int*)d_in[18];
    const int*   sos     = (const int*)d_in[19];

    float* S = nullptr;
    cudaGetSymbolAddress((void**)&S, g_scratch);
    float* x    = S + OFF_X;
    float* qkv  = S + OFF_QKV;
    float* attn = S + OFF_ATTN;
    float* tmp  = S + OFF_TMP;
    float* ffh  = S + OFF_FFH;
    float* encp = S + OFF_ENC;

    __nv_bfloat16 *Ah = nullptr, *Al = nullptr, *Wh = nullptr, *Wl = nullptr;
    cudaGetSymbolAddress((void**)&Ah, g_Ah);
    cudaGetSymbolAddress((void**)&Al, g_Al);
    cudaGetSymbolAddress((void**)&Wh, g_Wh);
    cudaGetSymbolAddress((void**)&Wl, g_Wl);

    static bool attr_done = false;
    if (!attr_done) {
        cudaFuncSetAttribute(joiner_tc_kernel,
                             cudaFuncAttributeMaxDynamicSharedMemorySize, JT_SMEM);
        attr_done = true;
    }

    // out_w split (independent)
    w_split_kernel<<<VP_, 128>>>(out_w, Wh, Wl);

    // enc projection
    gemm64<<<dim3(D_ / 64, (TI_ * NB_) / 64), 128>>>(enc_out, enc_w, enc_b, encp,
                                                     TI_ * NB_, D_, D_, 0);

    // embedding + positions
    embed_kernel<<<TOK_, 128>>>(embed_w, tgt_pad, sos, x);

    // 6 post-norm transformer layers
    for (int l = 0; l < L_; l++) {
        gemm64<<<dim3((3 * D_) / 64, (TOK_ + 63) / 64), 128>>>(
            x, qkv_w + (size_t)l * 3 * D_ * D_, qkv_b + (size_t)l * 3 * D_,
            qkv, TOK_, 3 * D_, D_, 0);
        attention_kernel<<<NB_ * H_, 128>>>(qkv, tgt_len, attn);
        gemm64<<<dim3(D_ / 64, (TOK_ + 63) / 64), 128>>>(
            attn, o_w + (size_t)l * D_ * D_, o_b + (size_t)l * D_,
            tmp, TOK_, D_, D_, 0);
        add_ln_kernel<<<TOK_, 128>>>(x, tmp, ln1_s + (size_t)l * D_, ln1_b + (size_t)l * D_);
        gemm64<<<dim3(FF_ / 64, (TOK_ + 63) / 64), 128>>>(
            x, ff1_w + (size_t)l * FF_ * D_, ff1_b + (size_t)l * FF_,
            ffh, TOK_, FF_, D_, 1);
        gemm64<<<dim3(D_ / 64, (TOK_ + 63) / 64), 128>>>(
            ffh, ff2_w + (size_t)l * D_ * FF_, ff2_b + (size_t)l * D_,
            tmp, TOK_, D_, FF_, 0);
        add_ln_kernel<<<TOK_, 128>>>(x, tmp, ln2_s + (size_t)l * D_, ln2_b + (size_t)l * D_);
    }

    // joiner
    joiner_a_split_kernel<<<MJ_, 128>>>(encp, x, Ah, Al);
    joiner_tc_kernel<<<dim3(VP_ / 128, MJ_ / 128), 256, JT_SMEM>>>(
        Ah, Al, Wh, Wl, (float*)d_out);
}

// round 4
// speedup vs baseline: 3.4230x; 1.4154x over previous
#include <cuda_runtime.h>
#include <cuda_bf16.h>
#include <math.h>
#include <stdint.h>

// ---------------------------------------------------------------------------
// Arch-feature gate (tcgen05 only legal on sm_10Xa feature targets)
// ---------------------------------------------------------------------------
#if defined(__CUDA_ARCH_FEAT_SM103_ALL) || defined(__CUDA_ARCH_FEAT_SM100_ALL) || defined(__CUDA_ARCH_FEAT_SM101_ALL)
#define USE_TCGEN05 1
#else
#define USE_TCGEN05 0
#endif

// ---------------------------------------------------------------------------
// Problem constants
// ---------------------------------------------------------------------------
#define TI_   128
#define NB_   8
#define TO_   32
#define TS_   33
#define D_    512
#define H_    8
#define HD_   64
#define FF_   2048
#define V_    2000
#define VP_   2048
#define L_    6
#define TOK_  (TS_ * NB_)          // 264
#define MJ_   (NB_ * TI_ * TS_)    // 33792
#define FF2_SPLIT 4

// ---------------------------------------------------------------------------
// Scratch (static __device__ arrays)
// ---------------------------------------------------------------------------
__device__ float g_x[TOK_ * D_];
__device__ float g_qkv[TOK_ * 3 * D_];
__device__ float g_tmp[FF2_SPLIT * TOK_ * D_];
__device__ float g_encp[TI_ * NB_ * D_];

__device__ __nv_bfloat16 g_xh[TOK_ * D_],  g_xl[TOK_ * D_];
__device__ __nv_bfloat16 g_ath[TOK_ * D_], g_atl[TOK_ * D_];
__device__ __nv_bfloat16 g_fh[TOK_ * FF_], g_fl[TOK_ * FF_];

__device__ __nv_bfloat16 g_qkvwh[(size_t)L_ * 3 * D_ * D_], g_qkvwl[(size_t)L_ * 3 * D_ * D_];
__device__ __nv_bfloat16 g_owh[(size_t)L_ * D_ * D_],       g_owl[(size_t)L_ * D_ * D_];
__device__ __nv_bfloat16 g_f1h[(size_t)L_ * FF_ * D_],      g_f1l[(size_t)L_ * FF_ * D_];
__device__ __nv_bfloat16 g_f2h[(size_t)L_ * D_ * FF_],      g_f2l[(size_t)L_ * D_ * FF_];
__device__ __nv_bfloat16 g_ewh[D_ * D_],                    g_ewl[D_ * D_];
__device__ __nv_bfloat16 g_exh[TI_ * NB_ * D_],             g_exl[TI_ * NB_ * D_];

__device__ __nv_bfloat16 g_Ah[(size_t)MJ_ * D_], g_Al[(size_t)MJ_ * D_];
__device__ __nv_bfloat16 g_Wh[(size_t)VP_ * D_], g_Wl[(size_t)VP_ * D_];

// ---------------------------------------------------------------------------
// PTX helpers
// ---------------------------------------------------------------------------
__device__ __forceinline__ uint32_t elect_one_pred() {
    uint32_t pred;
    asm volatile(
        "{\n\t.reg .pred p;\n\telect.sync _|p, 0xFFFFFFFF;\n\t"
        "selp.b32 %0, 1, 0, p;\n\t}"
        : "=r"(pred));
    return pred;
}
__device__ __forceinline__ uint32_t smem_to_u32(const void* smem_ptr) {
    uint32_t addr;
    asm("{ .reg .u64 tmp; cvta.to.shared.u64 tmp, %1; cvt.u32.u64 %0, tmp; }"
        : "=r"(addr) : "l"(smem_ptr));
    return addr;
}
__device__ __forceinline__ uint32_t sw_off(uint32_t bo) {
    return bo ^ ((bo >> 3) & 0x70);
}

static constexpr uint64_t SMEM_DESC_BASE_SW128 =
    (uint64_t(2)  << 61) | (uint64_t(1) << 46) | (uint64_t(64) << 32) | (uint64_t(1) << 16);
#define MAKE_SMEM_DESC(base_addr) \
    (SMEM_DESC_BASE_SW128 | ((uint64_t)((base_addr) >> 4) & 0x3FFF))

#if USE_TCGEN05
#define TCGEN05_ALLOC(smem_result_addr, nCols) \
    asm volatile("tcgen05.alloc.cta_group::1.sync.aligned.shared::cta.b32 [%0], %1;" \
        :: "r"((uint32_t)(smem_result_addr)), "r"((uint32_t)(nCols)) : "memory")
#define TCGEN05_DEALLOC(tmem_addr, nCols) \
    asm volatile("tcgen05.dealloc.cta_group::1.sync.aligned.b32 %0, %1;" \
        :: "r"(tmem_addr), "r"((uint32_t)(nCols)))
#define TCGEN05_RELINQUISH_ALLOC_PERMIT() \
    asm volatile("tcgen05.relinquish_alloc_permit.cta_group::1.sync.aligned;")
#define TCGEN05_COMMIT(mbar_smem_addr) \
    asm volatile("tcgen05.commit.cta_group::1.mbarrier::arrive::one.shared::cluster.b64 [%0];" \
        :: "r"((uint32_t)(mbar_smem_addr)) : "memory")
#define TCGEN05_WAIT_LD() \
    asm volatile("tcgen05.wait::ld.sync.aligned;" ::: "memory")
#define TCGEN05_FENCE_AFTER() \
    asm volatile("tcgen05.fence::after_thread_sync;" ::: "memory")
#define FENCE_PROXY_ASYNC_SHARED_CTA() \
    asm volatile("fence.proxy.async.shared::cta;" ::: "memory")
#define MBARRIER_INIT(mbar_smem_addr, count) \
    asm volatile("mbarrier.init.shared.b64 [%0], %1;" \
        :: "r"((uint32_t)(mbar_smem_addr)), "r"((uint32_t)(count)) : "memory")
#define MBARRIER_INVAL(mbar_smem_addr) \
    asm volatile("mbarrier.inval.shared.b64 [%0];" :: "r"((uint32_t)(mbar_smem_addr)) : "memory")
#define MBARRIER_WAIT_PARITY(mbar_smem_addr, phase_parity) do { \
    uint32_t _mbar = (uint32_t)(mbar_smem_addr); \
    uint32_t _parity = (uint32_t)(phase_parity); \
    uint32_t _done; \
    asm volatile( \
        "{\n\t.reg .pred p;\n\t" \
        "mbarrier.try_wait.parity.acquire.cta.shared::cta.b64 p, [%1], %2;\n\t" \
        "selp.b32 %0, 1, 0, p;\n\t}" \
        : "=r"(_done) : "r"(_mbar), "r"(_parity) : "memory"); \
    if (!_done) { \
        asm volatile( \
            "{\n\t.reg .pred P1;\n\t" \
            "WAIT_LOOP_%=:\n\t" \
            "mbarrier.try_wait.parity.acquire.cta.shared::cta.b64 P1, [%0], %1, 0x989680;\n\t" \
            "@P1 bra.uni WAIT_DONE_%=;\n\t" \
            "bra.uni WAIT_LOOP_%=;\n\t" \
            "WAIT_DONE_%=:\n\t}" \
            :: "r"(_mbar), "r"(_parity) : "memory"); \
    } \
} while(0)
#define TCGEN05_LD_32X32B_X32(r, tmem_addr) \
    asm volatile( \
        "tcgen05.ld.sync.aligned.32x32b.x32.b32 " \
        "{%0, %1, %2, %3, %4, %5, %6, %7, " \
        " %8, %9, %10, %11, %12, %13, %14, %15, " \
        " %16, %17, %18, %19, %20, %21, %22, %23, " \
        " %24, %25, %26, %27, %28, %29, %30, %31}, [%32];" \
        : "=r"((r)[0]),  "=r"((r)[1]),  "=r"((r)[2]),  "=r"((r)[3]), \
          "=r"((r)[4]),  "=r"((r)[5]),  "=r"((r)[6]),  "=r"((r)[7]), \
          "=r"((r)[8]),  "=r"((r)[9]),  "=r"((r)[10]), "=r"((r)[11]), \
          "=r"((r)[12]), "=r"((r)[13]), "=r"((r)[14]), "=r"((r)[15]), \
          "=r"((r)[16]), "=r"((r)[17]), "=r"((r)[18]), "=r"((r)[19]), \
          "=r"((r)[20]), "=r"((r)[21]), "=r"((r)[22]), "=r"((r)[23]), \
          "=r"((r)[24]), "=r"((r)[25]), "=r"((r)[26]), "=r"((r)[27]), \
          "=r"((r)[28]), "=r"((r)[29]), "=r"((r)[30]), "=r"((r)[31]) \
        : "r"(tmem_addr))

__device__ __forceinline__ void mma_f16_ss_cg1(uint32_t d_tmem, uint64_t a_desc,
                                               uint64_t b_desc, uint32_t idesc,
                                               uint32_t enable) {
    asm volatile(
        "{\n\t.reg .pred p;\n\t"
        "setp.ne.u32 p, %4, 0;\n\t"
        "tcgen05.mma.cta_group::1.kind::f16 [%0], %1, %2, %3, {%5, %5, %5, %5}, p;\n\t}"
        :: "r"(d_tmem), "l"(a_desc), "l"(b_desc), "r"(idesc), "r"(enable), "r"(0u)
        : "memory");
}
#define JOINER_IDESC 0x8200490u
#endif // USE_TCGEN05

// ---------------------------------------------------------------------------
// mma.sync helpers (base target)
// ---------------------------------------------------------------------------
__device__ __forceinline__ void ldmatrix_x4(uint32_t* r, uint32_t addr) {
    asm volatile("ldmatrix.sync.aligned.m8n8.x4.shared.b16 {%0,%1,%2,%3}, [%4];"
        : "=r"(r[0]), "=r"(r[1]), "=r"(r[2]), "=r"(r[3]) : "r"(addr));
}
__device__ __forceinline__ void mma16816(float* d, const uint32_t* a,
                                         uint32_t b0, uint32_t b1) {
    asm volatile(
        "mma.sync.aligned.m16n8k16.row.col.f32.bf16.bf16.f32 "
        "{%0,%1,%2,%3}, {%4,%5,%6,%7}, {%8,%9}, {%0,%1,%2,%3};"
        : "+f"(d[0]), "+f"(d[1]), "+f"(d[2]), "+f"(d[3])
        : "r"(a[0]), "r"(a[1]), "r"(a[2]), "r"(a[3]), "r"(b0), "r"(b1));
}

__device__ __forceinline__ void split_hl(float v, __nv_bfloat16& h, __nv_bfloat16& l) {
    h = __float2bfloat16(v);
    l = __float2bfloat16(v - __bfloat162float(h));
}

// ---------------------------------------------------------------------------
// Generic fp32 -> bf16 hi/lo split (vectorized)
// ---------------------------------------------------------------------------
__global__ void split_kernel(const float* __restrict__ W,
                             __nv_bfloat16* __restrict__ Wh,
                             __nv_bfloat16* __restrict__ Wl, int nvec4) {
    int i = blockIdx.x * blockDim.x + threadIdx.x;
    if (i >= nvec4) return;
    float4 w = ((const float4*)W)[i];
    __nv_bfloat16 h0, h1, h2, h3, l0, l1, l2, l3;
    split_hl(w.x, h0, l0); split_hl(w.y, h1, l1);
    split_hl(w.z, h2, l2); split_hl(w.w, h3, l3);
    ((__nv_bfloat162*)Wh)[2 * i]     = __nv_bfloat162(h0, h1);
    ((__nv_bfloat162*)Wh)[2 * i + 1] = __nv_bfloat162(h2, h3);
    ((__nv_bfloat162*)Wl)[2 * i]     = __nv_bfloat162(l0, l1);
    ((__nv_bfloat162*)Wl)[2 * i + 1] = __nv_bfloat162(l2, l3);
}

// out_w split padded to VP_ rows
__global__ void w_split_kernel(const float* __restrict__ W,
                               __nv_bfloat16* __restrict__ Wh,
                               __nv_bfloat16* __restrict__ Wl) {
    int r = blockIdx.x;
    int tid = threadIdx.x;
    size_t base = (size_t)r * D_ + tid * 4;
    if (r < V_) {
        const float4 w = ((const float4*)(W + (size_t)r * D_))[tid];
        __nv_bfloat16 h0, h1, h2, h3, l0, l1, l2, l3;
        split_hl(w.x, h0, l0); split_hl(w.y, h1, l1);
        split_hl(w.z, h2, l2); split_hl(w.w, h3, l3);
        ((__nv_bfloat162*)(Wh + base))[0] = __nv_bfloat162(h0, h1);
        ((__nv_bfloat162*)(Wh + base))[1] = __nv_bfloat162(h2, h3);
        ((__nv_bfloat162*)(Wl + base))[0] = __nv_bfloat162(l0, l1);
        ((__nv_bfloat162*)(Wl + base))[1] = __nv_bfloat162(l2, l3);
    } else {
        __nv_bfloat162 z = __nv_bfloat162(__float2bfloat16(0.f), __float2bfloat16(0.f));
        ((__nv_bfloat162*)(Wh + base))[0] = z;
        ((__nv_bfloat162*)(Wh + base))[1] = z;
        ((__nv_bfloat162*)(Wl + base))[0] = z;
        ((__nv_bfloat162*)(Wl + base))[1] = z;
    }
}

// ---------------------------------------------------------------------------
// Embedding + positions -> x fp32 + hi/lo
// ---------------------------------------------------------------------------
__global__ void embed_kernel(const float* __restrict__ embed,
                             const int* __restrict__ tgt_pad,
                             const int* __restrict__ sos,
                             float* __restrict__ x,
                             __nv_bfloat16* __restrict__ xh,
                             __nv_bfloat16* __restrict__ xl) {
    int r = blockIdx.x;
    int t = r >> 3, n = r & 7;
    int tok = (t == 0) ? sos[0] : tgt_pad[n * TO_ + (t - 1)];
    const float* e = embed + (size_t)tok * D_;
    const float sc = sqrtf(512.0f);
    int tid = threadIdx.x;
#pragma unroll
    for (int i = 0; i < 4; i++) {
        int d = tid * 4 + i;
        int half = d >> 1;
        double ddiv = exp((double)(2 * half) * (-9.210340371976184 / 512.0));
        double ang = (double)t * ddiv;
        double pv = (d & 1) ? cos(ang) : sin(ang);
        float v = e[d] * sc + (float)pv;
        size_t idx = (size_t)r * D_ + d;
        x[idx] = v;
        __nv_bfloat16 h, l;
        split_hl(v, h, l);
        xh[idx] = h; xl[idx] = l;
    }
}

// ---------------------------------------------------------------------------
// Shared tile loader (bf16, 128 rows x 64 cols, SW128)
// ---------------------------------------------------------------------------
__device__ __forceinline__ void tc_load_tile(const __nv_bfloat16* __restrict__ src,
                                             int row0, int maxrow, int koff,
                                             int kstride, char* sm, int tid) {
#pragma unroll
    for (int p = 0; p < 4; p++) {
        int idx = p * 256 + tid;
        int row = idx >> 3, seg = idx & 7;
        uint4 v = make_uint4(0, 0, 0, 0);
        int gr = row0 + row;
        if (gr < maxrow)
            v = *(const uint4*)(src + (size_t)gr * kstride + koff + seg * 8);
        uint32_t bo = (uint32_t)(row * 128 + seg * 16);
        *(uint4*)(sm + sw_off(bo)) = v;
    }
}

#define JT_BUF      16384
#define JT_SM_AH    1024
#define JT_SM_AL    (JT_SM_AH + JT_BUF)
#define JT_SM_WH    (JT_SM_AL + JT_BUF)
#define JT_SM_WL    (JT_SM_WH + JT_BUF)
#define JT_SMEM     (JT_SM_WL + JT_BUF)      // 66560

// ---------------------------------------------------------------------------
// Tensor-core GEMM (3-term bf16 hi/lo): C[z] = A @ W^T (+bias on z=0) (opt relu)
// A rows may exceed M (zero padded). N multiple of 128. K-chunk 64.
// Optional fp32 C, optional bf16 hi/lo outputs (for feeding next GEMM).
// gridDim = (N/128, ceil(M/128), ksplits); chunk offset = z*chunks*64.
// ---------------------------------------------------------------------------
__global__ void __launch_bounds__(256) gemm_tc(
    const __nv_bfloat16* __restrict__ Ah, const __nv_bfloat16* __restrict__ Al,
    const __nv_bfloat16* __restrict__ Wh, const __nv_bfloat16* __restrict__ Wl,
    const float* __restrict__ bias,
    float* __restrict__ C,
    __nv_bfloat16* __restrict__ Ch, __nv_bfloat16* __restrict__ Cl,
    int M, int N, int kstride, int chunks, int relu) {
    extern __shared__ char smem[];
    const uint32_t sbase = smem_to_u32(smem);
    const int tid = threadIdx.x;
    const int n0 = blockIdx.x * 128;
    const int m0 = blockIdx.y * 128;
    const int z  = blockIdx.z;
    const int koff0 = z * chunks * 64;
    if (C) C += (size_t)z * M * N;

    const int w = tid >> 5, lane = tid & 31;
    const int wr = w >> 1, wc = w & 1;

    float acc[16][4];
#pragma unroll
    for (int i = 0; i < 16; i++)
#pragma unroll
        for (int j = 0; j < 4; j++) acc[i][j] = 0.f;

    const int aoffs[3] = {JT_SM_AH, JT_SM_AH, JT_SM_AL};
    const int boffs[3] = {JT_SM_WH, JT_SM_WL, JT_SM_WH};

    for (int c = 0; c < chunks; c++) {
        const int koff = koff0 + c * 64;
        tc_load_tile(Ah, m0, M, koff, kstride, smem + JT_SM_AH, tid);
        tc_load_tile(Al, m0, M, koff, kstride, smem + JT_SM_AL, tid);
        tc_load_tile(Wh, n0, N, koff, kstride, smem + JT_SM_WH, tid);
        tc_load_tile(Wl, n0, N, koff, kstride, smem + JT_SM_WL, tid);
        __syncthreads();
#pragma unroll
        for (int s = 0; s < 4; s++) {
#pragma unroll
            for (int tm = 0; tm < 3; tm++) {
                uint32_t afrag[2][4];
#pragma unroll
                for (int mi = 0; mi < 2; mi++) {
                    uint32_t bo = (uint32_t)((wr * 32 + mi * 16 + (lane & 15)) * 128
                                             + s * 32 + (lane >> 4) * 16);
                    ldmatrix_x4(afrag[mi], sbase + aoffs[tm] + sw_off(bo));
                }
                const char* bp = smem + boffs[tm];
#pragma unroll
                for (int nt = 0; nt < 8; nt++) {
                    uint32_t bo0 = (uint32_t)((wc * 64 + nt * 8 + (lane >> 2)) * 128
                                              + s * 32 + (lane & 3) * 4);
                    uint32_t b0 = *(const uint32_t*)(bp + sw_off(bo0));
                    uint32_t b1 = *(const uint32_t*)(bp + sw_off(bo0 + 16));
                    mma16816(acc[nt], afrag[0], b0, b1);
                    mma16816(acc[8 + nt], afrag[1], b0, b1);
                }
            }
        }
        __syncthreads();
    }

    const bool addb = (bias != nullptr) && (z == 0);
#pragma unroll
    for (int mi = 0; mi < 2; mi++) {
#pragma unroll
        for (int nt = 0; nt < 8; nt++) {
            int m = m0 + wr * 32 + mi * 16 + (lane >> 2);
            int ncol = n0 + wc * 64 + nt * 8 + 2 * (lane & 3);
            float b0v = addb ? bias[ncol] : 0.f;
            float b1v = addb ? bias[ncol + 1] : 0.f;
            float v0 = acc[mi * 8 + nt][0] + b0v;
            float v1 = acc[mi * 8 + nt][1] + b1v;
            float v2 = acc[mi * 8 + nt][2] + b0v;
            float v3 = acc[mi * 8 + nt][3] + b1v;
            if (relu) {
                v0 = fmaxf(v0, 0.f); v1 = fmaxf(v1, 0.f);
                v2 = fmaxf(v2, 0.f); v3 = fmaxf(v3, 0.f);
            }
            if (m < M) {
                size_t o = (size_t)m * N + ncol;
                if (C) *(float2*)(C + o) = make_float2(v0, v1);
                if (Ch) {
                    __nv_bfloat16 h0, h1, l0, l1;
                    split_hl(v0, h0, l0); split_hl(v1, h1, l1);
                    *(__nv_bfloat162*)(Ch + o) = __nv_bfloat162(h0, h1);
                    *(__nv_bfloat162*)(Cl + o) = __nv_bfloat162(l0, l1);
                }
            }
            if (m + 8 < M) {
                size_t o = (size_t)(m + 8) * N + ncol;
                if (C) *(float2*)(C + o) = make_float2(v2, v3);
                if (Ch) {
                    __nv_bfloat16 h0, h1, l0, l1;
                    split_hl(v2, h0, l0); split_hl(v3, h1, l1);
                    *(__nv_bfloat162*)(Ch + o) = __nv_bfloat162(h0, h1);
                    *(__nv_bfloat162*)(Cl + o) = __nv_bfloat162(l0, l1);
                }
            }
        }
    }
}

// ---------------------------------------------------------------------------
// Attention: one block per (n,h). Writes hi/lo bf16 output.
// ---------------------------------------------------------------------------
__global__ void attention_kernel(const float* __restrict__ qkv,
                                 const int* __restrict__ tgt_len,
                                 __nv_bfloat16* __restrict__ oh,
                                 __nv_bfloat16* __restrict__ ol) {
    int n = blockIdx.x >> 3, h = blockIdx.x & 7;
    __shared__ float qs[TS_][HD_];
    __shared__ float ks[TS_][HD_];
    __shared__ float vs[TS_][HD_];
    __shared__ float sc[TS_][TS_ + 1];
    int tid = threadIdx.x;
    int len = tgt_len[n]; if (len < 1) len = 1;

    for (int e = tid; e < TS_ * HD_; e += 128) {
        int t = e >> 6, d = e & 63;
        const float* base = qkv + (size_t)(t * 8 + n) * (3 * D_) + h * 64 + d;
        qs[t][d] = base[0];
        ks[t][d] = base[512];
        vs[t][d] = base[1024];
    }
    __syncthreads();

    for (int p = tid; p < TS_ * TS_; p += 128) {
        int tq = p / TS_, tk = p - tq * TS_;
        float s;
        if (tk > tq || tk >= len) {
            s = -1e9f;
        } else {
            s = 0.f;
#pragma unroll 8
            for (int d = 0; d < HD_; d++) s += qs[tq][d] * ks[tk][d];
            s *= 0.125f;
        }
        sc[tq][tk] = s;
    }
    __syncthreads();

    if (tid < TS_) {
        int tq = tid;
        float mx = -1e30f;
        for (int tk = 0; tk < TS_; tk++) mx = fmaxf(mx, sc[tq][tk]);
        float sum = 0.f;
        for (int tk = 0; tk < TS_; tk++) {
            float e = expf(sc[tq][tk] - mx);
            sc[tq][tk] = e;
            sum += e;
        }
        float inv = 1.0f / sum;
        for (int tk = 0; tk < TS_; tk++) sc[tq][tk] *= inv;
    }
    __syncthreads();

    for (int e = tid; e < TS_ * HD_; e += 128) {
        int tq = e >> 6, d = e & 63;
        float s = 0.f;
#pragma unroll 8
        for (int tk = 0; tk < TS_; tk++) s += sc[tq][tk] * vs[tk][d];
        size_t idx = (size_t)(tq * 8 + n) * D_ + h * 64 + d;
        __nv_bfloat16 hv, lv;
        split_hl(s, hv, lv);
        oh[idx] = hv; ol[idx] = lv;
    }
}

// ---------------------------------------------------------------------------
// Residual add (x + sum of nsplit tmp slices) + LN; writes x fp32 + hi/lo
// ---------------------------------------------------------------------------
__global__ void add_ln_kernel(float* __restrict__ x,
                              const float* __restrict__ y, int nsplit,
                              const float* __restrict__ s,
                              const float* __restrict__ b,
                              __nv_bfloat16* __restrict__ xh,
                              __nv_bfloat16* __restrict__ xl) {
    int row = blockIdx.x, tid = threadIdx.x;
    __shared__ float sh[8];
    const float4 xv = ((const float4*)(x + (size_t)row * D_))[tid];
    float r0 = xv.x, r1 = xv.y, r2 = xv.z, r3 = xv.w;
    for (int z = 0; z < nsplit; z++) {
        const float4 yv = ((const float4*)(y + (size_t)z * TOK_ * D_ + (size_t)row * D_))[tid];
        r0 += yv.x; r1 += yv.y; r2 += yv.z; r3 += yv.w;
    }

    float sum = r0 + r1 + r2 + r3;
    int lane = tid & 31, wp = tid >> 5;
#pragma unroll
    for (int off = 16; off > 0; off >>= 1) sum += __shfl_xor_sync(0xffffffffu, sum, off);
    if (lane == 0) sh[wp] = sum;
    __syncthreads();
    float mean = (sh[0] + sh[1] + sh[2] + sh[3]) * (1.0f / 512.0f);

    float d0 = r0 - mean, d1 = r1 - mean, d2 = r2 - mean, d3 = r3 - mean;
    float sq = d0 * d0 + d1 * d1 + d2 * d2 + d3 * d3;
#pragma unroll
    for (int off = 16; off > 0; off >>= 1) sq += __shfl_xor_sync(0xffffffffu, sq, off);
    if (lane == 0) sh[4 + wp] = sq;
    __syncthreads();
    float var = (sh[4] + sh[5] + sh[6] + sh[7]) * (1.0f / 512.0f);
    float rstd = 1.0f / sqrtf(var + 1e-5f);

    const float4 sv = ((const float4*)s)[tid];
    const float4 bv = ((const float4*)b)[tid];
    float o0 = d0 * rstd * sv.x + bv.x;
    float o1 = d1 * rstd * sv.y + bv.y;
    float o2 = d2 * rstd * sv.z + bv.z;
    float o3 = d3 * rstd * sv.w + bv.w;
    ((float4*)(x + (size_t)row * D_))[tid] = make_float4(o0, o1, o2, o3);

    size_t base = (size_t)row * D_ + tid * 4;
    __nv_bfloat16 h0, h1, h2, h3, l0, l1, l2, l3;
    split_hl(o0, h0, l0); split_hl(o1, h1, l1);
    split_hl(o2, h2, l2); split_hl(o3, h3, l3);
    ((__nv_bfloat162*)(xh + base))[0] = __nv_bfloat162(h0, h1);
    ((__nv_bfloat162*)(xh + base))[1] = __nv_bfloat162(h2, h3);
    ((__nv_bfloat162*)(xl + base))[0] = __nv_bfloat162(l0, l1);
    ((__nv_bfloat162*)(xl + base))[1] = __nv_bfloat162(l2, l3);
}

// ---------------------------------------------------------------------------
// Joiner A materialization + bf16 hi/lo split
// ---------------------------------------------------------------------------
__global__ void joiner_a_split_kernel(const float* __restrict__ enc,
                                      const float* __restrict__ x,
                                      __nv_bfloat16* __restrict__ Ah,
                                      __nv_bfloat16* __restrict__ Al) {
    int r = blockIdx.x;
    int n = r / (TI_ * TS_);
    int rem = r - n * (TI_ * TS_);
    int i = rem / TS_;
    int t = rem - i * TS_;
    const float4* er = (const float4*)(enc + (size_t)(i * 8 + n) * D_);
    const float4* xr = (const float4*)(x + (size_t)(t * 8 + n) * D_);
    int tid = threadIdx.x;
    float4 e = er[tid], xx = xr[tid];
    float a[4] = {tanhf(e.x + xx.x), tanhf(e.y + xx.y),
                  tanhf(e.z + xx.z), tanhf(e.w + xx.w)};
    __nv_bfloat16 h0, h1, h2, h3, l0, l1, l2, l3;
    split_hl(a[0], h0, l0); split_hl(a[1], h1, l1);
    split_hl(a[2], h2, l2); split_hl(a[3], h3, l3);
    size_t base = (size_t)r * D_ + tid * 4;
    ((__nv_bfloat162*)(Ah + base))[0] = __nv_bfloat162(h0, h1);
    ((__nv_bfloat162*)(Ah + base))[1] = __nv_bfloat162(h2, h3);
    ((__nv_bfloat162*)(Al + base))[0] = __nv_bfloat162(l0, l1);
    ((__nv_bfloat162*)(Al + base))[1] = __nv_bfloat162(l2, l3);
}

// ---------------------------------------------------------------------------
// Joiner GEMM (tile 128x128, K=512, 3-term bf16) — tcgen05 or mma.sync
// ---------------------------------------------------------------------------
#define JT_CHUNKS   8

__global__ void __launch_bounds__(256) joiner_tc_kernel(
    const __nv_bfloat16* __restrict__ Ah,
    const __nv_bfloat16* __restrict__ Al,
    const __nv_bfloat16* __restrict__ Wh,
    const __nv_bfloat16* __restrict__ Wl,
    float* __restrict__ C) {
    extern __shared__ char smem[];
    const int tid = threadIdx.x;
    const int n0 = blockIdx.x * 128;
    const int m0 = blockIdx.y * 128;

#if USE_TCGEN05
    const uint32_t smem_base = smem_to_u32(smem);
    const int wid = tid >> 5, lane = tid & 31;

    if (wid == 0) {
        TCGEN05_ALLOC(smem_base, 128);
        TCGEN05_RELINQUISH_ALLOC_PERMIT();
    }
    if (tid == 0) MBARRIER_INIT(smem_base + 8, 1);
    __syncthreads();
    uint32_t tmem_base;
    asm volatile("ld.shared.b32 %0, [%1];" : "=r"(tmem_base) : "r"(smem_base));

    const uint64_t dAh = MAKE_SMEM_DESC(smem_base + JT_SM_AH);
    const uint64_t dAl = MAKE_SMEM_DESC(smem_base + JT_SM_AL);
    const uint64_t dWh = MAKE_SMEM_DESC(smem_base + JT_SM_WH);
    const uint64_t dWl = MAKE_SMEM_DESC(smem_base + JT_SM_WL);

    for (int c = 0; c < JT_CHUNKS; c++) {
        if (c > 0) MBARRIER_WAIT_PARITY(smem_base + 8, (c - 1) & 1);
        const int koff = c * 64;
        tc_load_tile(Ah, m0, MJ_, koff, D_, smem + JT_SM_AH, tid);
        tc_load_tile(Al, m0, MJ_, koff, D_, smem + JT_SM_AL, tid);
        tc_load_tile(Wh, n0, VP_, koff, D_, smem + JT_SM_WH, tid);
        tc_load_tile(Wl, n0, VP_, koff, D_, smem + JT_SM_WL, tid);
        __syncthreads();
        if (wid == 0) {
            if (elect_one_pred()) {
                FENCE_PROXY_ASYNC_SHARED_CTA();
#pragma unroll
                for (int k = 0; k < 4; k++)
                    mma_f16_ss_cg1(tmem_base, dAh + k * 2, dWh + k * 2,
                                   JOINER_IDESC, (c > 0) || (k > 0));
#pragma unroll
                for (int k = 0; k < 4; k++)
                    mma_f16_ss_cg1(tmem_base, dAh + k * 2, dWl + k * 2,
                                   JOINER_IDESC, 1u);
#pragma unroll
                for (int k = 0; k < 4; k++)
                    mma_f16_ss_cg1(tmem_base, dAl + k * 2, dWh + k * 2,
                                   JOINER_IDESC, 1u);
                TCGEN05_COMMIT(smem_base + 8);
            }
        }
    }
    MBARRIER_WAIT_PARITY(smem_base + 8, (JT_CHUNKS - 1) & 1);
    TCGEN05_FENCE_AFTER();

    {
        const int sub = wid & 3;
        const int halfc = (wid >> 2) * 64;
        float* crow = C + (size_t)(m0 + sub * 32 + lane) * V_;
        const bool full = (n0 + 128) <= V_;
#pragma unroll
        for (int base = halfc; base < halfc + 64; base += 32) {
            uint32_t r[32];
            TCGEN05_LD_32X32B_X32(r, tmem_base + base);
            TCGEN05_WAIT_LD();
            if (full) {
#pragma unroll
                for (int j = 0; j < 32; j += 4) {
                    *(float4*)(crow + n0 + base + j) =
                        make_float4(__uint_as_float(r[j]), __uint_as_float(r[j + 1]),
                                    __uint_as_float(r[j + 2]), __uint_as_float(r[j + 3]));
                }
            } else {
#pragma unroll
                for (int j = 0; j < 32; j++) {
                    int col = n0 + base + j;
                    if (col < V_) crow[col] = __uint_as_float(r[j]);
                }
            }
        }
    }
    __syncthreads();
    if (wid == 0) {
        if (elect_one_pred()) MBARRIER_INVAL(smem_base + 8);
        TCGEN05_DEALLOC(tmem_base, 128);
    }

#else  // mma.sync path
    const uint32_t sbase = smem_to_u32(smem);
    const int w = tid >> 5, lane = tid & 31;
    const int wr = w >> 1, wc = w & 1;

    float acc[16][4];
#pragma unroll
    for (int i = 0; i < 16; i++)
#pragma unroll
        for (int j = 0; j < 4; j++) acc[i][j] = 0.f;

    const int aoffs[3] = {JT_SM_AH, JT_SM_AH, JT_SM_AL};
    const int boffs[3] = {JT_SM_WH, JT_SM_WL, JT_SM_WH};

    for (int c = 0; c < JT_CHUNKS; c++) {
        const int koff = c * 64;
        tc_load_tile(Ah, m0, MJ_, koff, D_, smem + JT_SM_AH, tid);
        tc_load_tile(Al, m0, MJ_, koff, D_, smem + JT_SM_AL, tid);
        tc_load_tile(Wh, n0, VP_, koff, D_, smem + JT_SM_WH, tid);
        tc_load_tile(Wl, n0, VP_, koff, D_, smem + JT_SM_WL, tid);
        __syncthreads();
#pragma unroll
        for (int s = 0; s < 4; s++) {
#pragma unroll
            for (int tm = 0; tm < 3; tm++) {
                uint32_t afrag[2][4];
#pragma unroll
                for (int mi = 0; mi < 2; mi++) {
                    uint32_t bo = (uint32_t)((wr * 32 + mi * 16 + (lane & 15)) * 128
                                             + s * 32 + (lane >> 4) * 16);
                    ldmatrix_x4(afrag[mi], sbase + aoffs[tm] + sw_off(bo));
                }
                const char* bp = smem + boffs[tm];
#pragma unroll
                for (int nt = 0; nt < 8; nt++) {
                    uint32_t bo0 = (uint32_t)((wc * 64 + nt * 8 + (lane >> 2)) * 128
                                              + s * 32 + (lane & 3) * 4);
                    uint32_t b0 = *(const uint32_t*)(bp + sw_off(bo0));
                    uint32_t b1 = *(const uint32_t*)(bp + sw_off(bo0 + 16));
                    mma16816(acc[nt], afrag[0], b0, b1);
                    mma16816(acc[8 + nt], afrag[1], b0, b1);
                }
            }
        }
        __syncthreads();
    }

#pragma unroll
    for (int mi = 0; mi < 2; mi++) {
#pragma unroll
        for (int nt = 0; nt < 8; nt++) {
            int m = m0 + wr * 32 + mi * 16 + (lane >> 2);
            int ncol = n0 + wc * 64 + nt * 8 + 2 * (lane & 3);
            if (ncol < V_) {
                float* p0 = C + (size_t)m * V_ + ncol;
                float* p1 = C + (size_t)(m + 8) * V_ + ncol;
                *(float2*)p0 = make_float2(acc[mi * 8 + nt][0], acc[mi * 8 + nt][1]);
                *(float2*)p1 = make_float2(acc[mi * 8 + nt][2], acc[mi * 8 + nt][3]);
            }
        }
    }
#endif
}

// ---------------------------------------------------------------------------
// Host orchestration
// ---------------------------------------------------------------------------
extern "C" void kernel_launch(void* const* d_in, const int* in_sizes, int n_in,
                              void* d_out, int out_size) {
    const float* enc_out = (const float*)d_in[0];
    const float* embed_w = (const float*)d_in[1];
    const float* enc_w   = (const float*)d_in[2];
    const float* enc_b   = (const float*)d_in[3];
    const float* qkv_w   = (const float*)d_in[4];
    const float* qkv_b   = (const float*)d_in[5];
    const float* o_w     = (const float*)d_in[6];
    const float* o_b     = (const float*)d_in[7];
    const float* ln1_s   = (const float*)d_in[8];
    const float* ln1_b   = (const float*)d_in[9];
    const float* ff1_w   = (const float*)d_in[10];
    const float* ff1_b   = (const float*)d_in[11];
    const float* ff2_w   = (const float*)d_in[12];
    const float* ff2_b   = (const float*)d_in[13];
    const float* ln2_s   = (const float*)d_in[14];
    const float* ln2_b   = (const float*)d_in[15];
    const float* out_w   = (const float*)d_in[16];
    const int*   tgt_pad = (const int*)d_in[17];
    const int*   tgt_len = (const int*)d_in[18];
    const int*   sos     = (const int*)d_in[19];

    float *x, *qkv, *tmp, *encp;
    cudaGetSymbolAddress((void**)&x, g_x);
    cudaGetSymbolAddress((void**)&qkv, g_qkv);
    cudaGetSymbolAddress((void**)&tmp, g_tmp);
    cudaGetSymbolAddress((void**)&encp, g_encp);

    __nv_bfloat16 *xh, *xl, *ath, *atl, *fh, *fl;
    cudaGetSymbolAddress((void**)&xh, g_xh);
    cudaGetSymbolAddress((void**)&xl, g_xl);
    cudaGetSymbolAddress((void**)&ath, g_ath);
    cudaGetSymbolAddress((void**)&atl, g_atl);
    cudaGetSymbolAddress((void**)&fh, g_fh);
    cudaGetSymbolAddress((void**)&fl, g_fl);

    __nv_bfloat16 *qkvwh, *qkvwl, *owh, *owl, *f1h, *f1l, *f2h, *f2l, *ewh, *ewl, *exh, *exl;
    cudaGetSymbolAddress((void**)&qkvwh, g_qkvwh);
    cudaGetSymbolAddress((void**)&qkvwl, g_qkvwl);
    cudaGetSymbolAddress((void**)&owh, g_owh);
    cudaGetSymbolAddress((void**)&owl, g_owl);
    cudaGetSymbolAddress((void**)&f1h, g_f1h);
    cudaGetSymbolAddress((void**)&f1l, g_f1l);
    cudaGetSymbolAddress((void**)&f2h, g_f2h);
    cudaGetSymbolAddress((void**)&f2l, g_f2l);
    cudaGetSymbolAddress((void**)&ewh, g_ewh);
    cudaGetSymbolAddress((void**)&ewl, g_ewl);
    cudaGetSymbolAddress((void**)&exh, g_exh);
    cudaGetSymbolAddress((void**)&exl, g_exl);

    __nv_bfloat16 *Ah, *Al, *Wh, *Wl;
    cudaGetSymbolAddress((void**)&Ah, g_Ah);
    cudaGetSymbolAddress((void**)&Al, g_Al);
    cudaGetSymbolAddress((void**)&Wh, g_Wh);
    cudaGetSymbolAddress((void**)&Wl, g_Wl);

    static bool attr_done = false;
    if (!attr_done) {
        cudaFuncSetAttribute(joiner_tc_kernel,
                             cudaFuncAttributeMaxDynamicSharedMemorySize, JT_SMEM);
        cudaFuncSetAttribute(gemm_tc,
                             cudaFuncAttributeMaxDynamicSharedMemorySize, JT_SMEM);
        attr_done = true;
    }

    // ---- splits (all independent) ----
    {
        int n;
        n = L_ * 3 * D_ * D_ / 4;
        split_kernel<<<(n + 255) / 256, 256>>>(qkv_w, qkvwh, qkvwl, n);
        n = L_ * D_ * D_ / 4;
        split_kernel<<<(n + 255) / 256, 256>>>(o_w, owh, owl, n);
        n = L_ * FF_ * D_ / 4;
        split_kernel<<<(n + 255) / 256, 256>>>(ff1_w, f1h, f1l, n);
        n = L_ * D_ * FF_ / 4;
        split_kernel<<<(n + 255) / 256, 256>>>(ff2_w, f2h, f2l, n);
        n = D_ * D_ / 4;
        split_kernel<<<(n + 255) / 256, 256>>>(enc_w, ewh, ewl, n);
        n = TI_ * NB_ * D_ / 4;
        split_kernel<<<(n + 255) / 256, 256>>>(enc_out, exh, exl, n);
        w_split_kernel<<<VP_, 128>>>(out_w, Wh, Wl);
    }

    // enc projection: encp[1024x512] = enc_out @ enc_w^T + b
    gemm_tc<<<dim3(D_ / 128, (TI_ * NB_) / 128, 1), 256, JT_SMEM>>>(
        exh, exl, ewh, ewl, enc_b, encp, nullptr, nullptr,
        TI_ * NB_, D_, D_, 8, 0);

    // embedding + positions
    embed_kernel<<<TOK_, 128>>>(embed_w, tgt_pad, sos, x, xh, xl);

    // 6 post-norm transformer layers (all GEMMs on tensor cores)
    for (int l = 0; l < L_; l++) {
        gemm_tc<<<dim3(3 * D_ / 128, 3, 1), 256, JT_SMEM>>>(
            xh, xl, qkvwh + (size_t)l * 3 * D_ * D_, qkvwl + (size_t)l * 3 * D_ * D_,
            qkv_b + (size_t)l * 3 * D_, qkv, nullptr, nullptr,
            TOK_, 3 * D_, D_, 8, 0);
        attention_kernel<<<NB_ * H_, 128>>>(qkv, tgt_len, ath, atl);
        gemm_tc<<<dim3(D_ / 128, 3, 1), 256, JT_SMEM>>>(
            ath, atl, owh + (size_t)l * D_ * D_, owl + (size_t)l * D_ * D_,
            o_b + (size_t)l * D_, tmp, nullptr, nullptr,
            TOK_, D_, D_, 8, 0);
        add_ln_kernel<<<TOK_, 128>>>(x, tmp, 1,
            ln1_s + (size_t)l * D_, ln1_b + (size_t)l * D_, xh, xl);
        gemm_tc<<<dim3(FF_ / 128, 3, 1), 256, JT_SMEM>>>(
            xh, xl, f1h + (size_t)l * FF_ * D_, f1l + (size_t)l * FF_ * D_,
            ff1_b + (size_t)l * FF_, nullptr, fh, fl,
            TOK_, FF_, D_, 8, 1);
        gemm_tc<<<dim3(D_ / 128, 3, FF2_SPLIT), 256, JT_SMEM>>>(
            fh, fl, f2h + (size_t)l * D_ * FF_, f2l + (size_t)l * D_ * FF_,
            ff2_b + (size_t)l * D_, tmp, nullptr, nullptr,
            TOK_, D_, FF_, FF_ / 64 / FF2_SPLIT, 0);
        add_ln_kernel<<<TOK_, 128>>>(x, tmp, FF2_SPLIT,
            ln2_s + (size_t)l * D_, ln2_b + (size_t)l * D_, xh, xl);
    }

    // joiner
    joiner_a_split_kernel<<<MJ_, 128>>>(encp, x, Ah, Al);
    joiner_tc_kernel<<<dim3(VP_ / 128, MJ_ / 128), 256, JT_SMEM>>>(
        Ah, Al, Wh, Wl, (float*)d_out);
}

// round 5
// speedup vs baseline: 4.6870x; 1.3693x over previous
#include <cuda_runtime.h>
#include <cuda_bf16.h>
#include <math.h>
#include <stdint.h>

// ---------------------------------------------------------------------------
// Arch-feature gate (tcgen05 only legal on sm_10Xa feature targets)
// ---------------------------------------------------------------------------
#if defined(__CUDA_ARCH_FEAT_SM103_ALL) || defined(__CUDA_ARCH_FEAT_SM100_ALL) || defined(__CUDA_ARCH_FEAT_SM101_ALL)
#define USE_TCGEN05 1
#else
#define USE_TCGEN05 0
#endif

// ---------------------------------------------------------------------------
// Problem constants
// ---------------------------------------------------------------------------
#define TI_   128
#define NB_   8
#define TO_   32
#define TS_   33
#define D_    512
#define H_    8
#define HD_   64
#define FF_   2048
#define V_    2000
#define VP_   2048
#define L_    6
#define TOK_  (TS_ * NB_)          // 264
#define MJ_   (NB_ * TI_ * TS_)    // 33792
#define FF2_SPLIT 4
#define QKV_SPLIT 2
#define O_SPLIT   2

// ---------------------------------------------------------------------------
// Scratch (static __device__ arrays)
// ---------------------------------------------------------------------------
__device__ float g_x[TOK_ * D_];
__device__ float g_qkv[QKV_SPLIT * TOK_ * 3 * D_];
__device__ float g_tmp[FF2_SPLIT * TOK_ * D_];
__device__ float g_encp[TI_ * NB_ * D_];

__device__ __nv_bfloat16 g_xh[TOK_ * D_],  g_xl[TOK_ * D_];
__device__ __nv_bfloat16 g_ath[TOK_ * D_], g_atl[TOK_ * D_];
__device__ __nv_bfloat16 g_fh[TOK_ * FF_], g_fl[TOK_ * FF_];

__device__ __nv_bfloat16 g_qkvwh[(size_t)L_ * 3 * D_ * D_], g_qkvwl[(size_t)L_ * 3 * D_ * D_];
__device__ __nv_bfloat16 g_owh[(size_t)L_ * D_ * D_],       g_owl[(size_t)L_ * D_ * D_];
__device__ __nv_bfloat16 g_f1h[(size_t)L_ * FF_ * D_],      g_f1l[(size_t)L_ * FF_ * D_];
__device__ __nv_bfloat16 g_f2h[(size_t)L_ * D_ * FF_],      g_f2l[(size_t)L_ * D_ * FF_];
__device__ __nv_bfloat16 g_ewh[D_ * D_],                    g_ewl[D_ * D_];
__device__ __nv_bfloat16 g_exh[TI_ * NB_ * D_],             g_exl[TI_ * NB_ * D_];

__device__ __nv_bfloat16 g_Ah[(size_t)MJ_ * D_], g_Al[(size_t)MJ_ * D_];
__device__ __nv_bfloat16 g_Wh[(size_t)VP_ * D_], g_Wl[(size_t)VP_ * D_];

// ---------------------------------------------------------------------------
// PTX helpers
// ---------------------------------------------------------------------------
__device__ __forceinline__ uint32_t elect_one_pred() {
    uint32_t pred;
    asm volatile(
        "{\n\t.reg .pred p;\n\telect.sync _|p, 0xFFFFFFFF;\n\t"
        "selp.b32 %0, 1, 0, p;\n\t}"
        : "=r"(pred));
    return pred;
}
__device__ __forceinline__ uint32_t smem_to_u32(const void* smem_ptr) {
    uint32_t addr;
    asm("{ .reg .u64 tmp; cvta.to.shared.u64 tmp, %1; cvt.u32.u64 %0, tmp; }"
        : "=r"(addr) : "l"(smem_ptr));
    return addr;
}
__device__ __forceinline__ uint32_t sw_off(uint32_t bo) {
    return bo ^ ((bo >> 3) & 0x70);
}
// cp.async 16B with zero-fill when src invalid
__device__ __forceinline__ void cp_async16(uint32_t saddr, const void* gptr, int valid) {
    asm volatile("cp.async.cg.shared.global [%0], [%1], 16, %2;"
        :: "r"(saddr), "l"(gptr), "r"(valid ? 16 : 0));
}
__device__ __forceinline__ void cp_async_commit_wait() {
    asm volatile("cp.async.commit_group;");
    asm volatile("cp.async.wait_group 0;" ::: "memory");
}

static constexpr uint64_t SMEM_DESC_BASE_SW128 =
    (uint64_t(2)  << 61) | (uint64_t(1) << 46) | (uint64_t(64) << 32) | (uint64_t(1) << 16);
#define MAKE_SMEM_DESC(base_addr) \
    (SMEM_DESC_BASE_SW128 | ((uint64_t)((base_addr) >> 4) & 0x3FFF))

#if USE_TCGEN05
#define TCGEN05_ALLOC(smem_result_addr, nCols) \
    asm volatile("tcgen05.alloc.cta_group::1.sync.aligned.shared::cta.b32 [%0], %1;" \
        :: "r"((uint32_t)(smem_result_addr)), "r"((uint32_t)(nCols)) : "memory")
#define TCGEN05_DEALLOC(tmem_addr, nCols) \
    asm volatile("tcgen05.dealloc.cta_group::1.sync.aligned.b32 %0, %1;" \
        :: "r"(tmem_addr), "r"((uint32_t)(nCols)))
#define TCGEN05_RELINQUISH_ALLOC_PERMIT() \
    asm volatile("tcgen05.relinquish_alloc_permit.cta_group::1.sync.aligned;")
#define TCGEN05_COMMIT(mbar_smem_addr) \
    asm volatile("tcgen05.commit.cta_group::1.mbarrier::arrive::one.shared::cluster.b64 [%0];" \
        :: "r"((uint32_t)(mbar_smem_addr)) : "memory")
#define TCGEN05_WAIT_LD() \
    asm volatile("tcgen05.wait::ld.sync.aligned;" ::: "memory")
#define TCGEN05_FENCE_AFTER() \
    asm volatile("tcgen05.fence::after_thread_sync;" ::: "memory")
#define FENCE_PROXY_ASYNC_SHARED_CTA() \
    asm volatile("fence.proxy.async.shared::cta;" ::: "memory")
#define MBARRIER_INIT(mbar_smem_addr, count) \
    asm volatile("mbarrier.init.shared.b64 [%0], %1;" \
        :: "r"((uint32_t)(mbar_smem_addr)), "r"((uint32_t)(count)) : "memory")
#define MBARRIER_INVAL(mbar_smem_addr) \
    asm volatile("mbarrier.inval.shared.b64 [%0];" :: "r"((uint32_t)(mbar_smem_addr)) : "memory")
#define MBARRIER_WAIT_PARITY(mbar_smem_addr, phase_parity) do { \
    uint32_t _mbar = (uint32_t)(mbar_smem_addr); \
    uint32_t _parity = (uint32_t)(phase_parity); \
    uint32_t _done; \
    asm volatile( \
        "{\n\t.reg .pred p;\n\t" \
        "mbarrier.try_wait.parity.acquire.cta.shared::cta.b64 p, [%1], %2;\n\t" \
        "selp.b32 %0, 1, 0, p;\n\t}" \
        : "=r"(_done) : "r"(_mbar), "r"(_parity) : "memory"); \
    if (!_done) { \
        asm volatile( \
            "{\n\t.reg .pred P1;\n\t" \
            "WAIT_LOOP_%=:\n\t" \
            "mbarrier.try_wait.parity.acquire.cta.shared::cta.b64 P1, [%0], %1, 0x989680;\n\t" \
            "@P1 bra.uni WAIT_DONE_%=;\n\t" \
            "bra.uni WAIT_LOOP_%=;\n\t" \
            "WAIT_DONE_%=:\n\t}" \
            :: "r"(_mbar), "r"(_parity) : "memory"); \
    } \
} while(0)
#define TCGEN05_LD_32X32B_X32(r, tmem_addr) \
    asm volatile( \
        "tcgen05.ld.sync.aligned.32x32b.x32.b32 " \
        "{%0, %1, %2, %3, %4, %5, %6, %7, " \
        " %8, %9, %10, %11, %12, %13, %14, %15, " \
        " %16, %17, %18, %19, %20, %21, %22, %23, " \
        " %24, %25, %26, %27, %28, %29, %30, %31}, [%32];" \
        : "=r"((r)[0]),  "=r"((r)[1]),  "=r"((r)[2]),  "=r"((r)[3]), \
          "=r"((r)[4]),  "=r"((r)[5]),  "=r"((r)[6]),  "=r"((r)[7]), \
          "=r"((r)[8]),  "=r"((r)[9]),  "=r"((r)[10]), "=r"((r)[11]), \
          "=r"((r)[12]), "=r"((r)[13]), "=r"((r)[14]), "=r"((r)[15]), \
          "=r"((r)[16]), "=r"((r)[17]), "=r"((r)[18]), "=r"((r)[19]), \
          "=r"((r)[20]), "=r"((r)[21]), "=r"((r)[22]), "=r"((r)[23]), \
          "=r"((r)[24]), "=r"((r)[25]), "=r"((r)[26]), "=r"((r)[27]), \
          "=r"((r)[28]), "=r"((r)[29]), "=r"((r)[30]), "=r"((r)[31]) \
        : "r"(tmem_addr))

__device__ __forceinline__ void mma_f16_ss_cg1(uint32_t d_tmem, uint64_t a_desc,
                                               uint64_t b_desc, uint32_t idesc,
                                               uint32_t enable) {
    asm volatile(
        "{\n\t.reg .pred p;\n\t"
        "setp.ne.u32 p, %4, 0;\n\t"
        "tcgen05.mma.cta_group::1.kind::f16 [%0], %1, %2, %3, {%5, %5, %5, %5}, p;\n\t}"
        :: "r"(d_tmem), "l"(a_desc), "l"(b_desc), "r"(idesc), "r"(enable), "r"(0u)
        : "memory");
}
#define JOINER_IDESC 0x8200490u
#endif // USE_TCGEN05

// ---------------------------------------------------------------------------
// mma.sync helpers (base target)
// ---------------------------------------------------------------------------
__device__ __forceinline__ void ldmatrix_x4(uint32_t* r, uint32_t addr) {
    asm volatile("ldmatrix.sync.aligned.m8n8.x4.shared.b16 {%0,%1,%2,%3}, [%4];"
        : "=r"(r[0]), "=r"(r[1]), "=r"(r[2]), "=r"(r[3]) : "r"(addr));
}
__device__ __forceinline__ void mma16816(float* d, const uint32_t* a,
                                         uint32_t b0, uint32_t b1) {
    asm volatile(
        "mma.sync.aligned.m16n8k16.row.col.f32.bf16.bf16.f32 "
        "{%0,%1,%2,%3}, {%4,%5,%6,%7}, {%8,%9}, {%0,%1,%2,%3};"
        : "+f"(d[0]), "+f"(d[1]), "+f"(d[2]), "+f"(d[3])
        : "r"(a[0]), "r"(a[1]), "r"(a[2]), "r"(a[3]), "r"(b0), "r"(b1));
}

__device__ __forceinline__ void split_hl(float v, __nv_bfloat16& h, __nv_bfloat16& l) {
    h = __float2bfloat16(v);
    l = __float2bfloat16(v - __bfloat162float(h));
}

// ---------------------------------------------------------------------------
// Fused weight split: one launch handles all fp32 -> bf16 hi/lo conversions
// ---------------------------------------------------------------------------
#define NSPLITJOBS 6
struct SplitJobs {
    const float* src[NSPLITJOBS];
    __nv_bfloat16* h[NSPLITJOBS];
    __nv_bfloat16* l[NSPLITJOBS];
    int end[NSPLITJOBS];   // prefix-sum of vec4 counts
};

__global__ void split_all_kernel(SplitJobs jobs, int total) {
    int i = blockIdx.x * blockDim.x + threadIdx.x;
    if (i >= total) return;
    int j = 0;
#pragma unroll
    for (int k = 0; k < NSPLITJOBS - 1; k++) j += (i >= jobs.end[k]);
    int base = (j == 0) ? 0 : jobs.end[j - 1];
    int li = i - base;
    float4 w = ((const float4*)jobs.src[j])[li];
    __nv_bfloat16 h0, h1, h2, h3, l0, l1, l2, l3;
    split_hl(w.x, h0, l0); split_hl(w.y, h1, l1);
    split_hl(w.z, h2, l2); split_hl(w.w, h3, l3);
    ((__nv_bfloat162*)jobs.h[j])[2 * li]     = __nv_bfloat162(h0, h1);
    ((__nv_bfloat162*)jobs.h[j])[2 * li + 1] = __nv_bfloat162(h2, h3);
    ((__nv_bfloat162*)jobs.l[j])[2 * li]     = __nv_bfloat162(l0, l1);
    ((__nv_bfloat162*)jobs.l[j])[2 * li + 1] = __nv_bfloat162(l2, l3);
}

// out_w split padded to VP_ rows
__global__ void w_split_kernel(const float* __restrict__ W,
                               __nv_bfloat16* __restrict__ Wh,
                               __nv_bfloat16* __restrict__ Wl) {
    int r = blockIdx.x;
    int tid = threadIdx.x;
    size_t base = (size_t)r * D_ + tid * 4;
    if (r < V_) {
        const float4 w = ((const float4*)(W + (size_t)r * D_))[tid];
        __nv_bfloat16 h0, h1, h2, h3, l0, l1, l2, l3;
        split_hl(w.x, h0, l0); split_hl(w.y, h1, l1);
        split_hl(w.z, h2, l2); split_hl(w.w, h3, l3);
        ((__nv_bfloat162*)(Wh + base))[0] = __nv_bfloat162(h0, h1);
        ((__nv_bfloat162*)(Wh + base))[1] = __nv_bfloat162(h2, h3);
        ((__nv_bfloat162*)(Wl + base))[0] = __nv_bfloat162(l0, l1);
        ((__nv_bfloat162*)(Wl + base))[1] = __nv_bfloat162(l2, l3);
    } else {
        __nv_bfloat162 z = __nv_bfloat162(__float2bfloat16(0.f), __float2bfloat16(0.f));
        ((__nv_bfloat162*)(Wh + base))[0] = z;
        ((__nv_bfloat162*)(Wh + base))[1] = z;
        ((__nv_bfloat162*)(Wl + base))[0] = z;
        ((__nv_bfloat162*)(Wl + base))[1] = z;
    }
}

// ---------------------------------------------------------------------------
// Embedding + positions -> x fp32 + hi/lo
// ---------------------------------------------------------------------------
__global__ void embed_kernel(const float* __restrict__ embed,
                             const int* __restrict__ tgt_pad,
                             const int* __restrict__ sos,
                             float* __restrict__ x,
                             __nv_bfloat16* __restrict__ xh,
                             __nv_bfloat16* __restrict__ xl) {
    int r = blockIdx.x;
    int t = r >> 3, n = r & 7;
    int tok = (t == 0) ? sos[0] : tgt_pad[n * TO_ + (t - 1)];
    const float* e = embed + (size_t)tok * D_;
    const float sc = sqrtf(512.0f);
    int tid = threadIdx.x;
#pragma unroll
    for (int i = 0; i < 4; i++) {
        int d = tid * 4 + i;
        int half = d >> 1;
        double ddiv = exp((double)(2 * half) * (-9.210340371976184 / 512.0));
        double ang = (double)t * ddiv;
        double pv = (d & 1) ? cos(ang) : sin(ang);
        float v = e[d] * sc + (float)pv;
        size_t idx = (size_t)r * D_ + d;
        x[idx] = v;
        __nv_bfloat16 h, l;
        split_hl(v, h, l);
        xh[idx] = h; xl[idx] = l;
    }
}

// ---------------------------------------------------------------------------
// Async tile loader (bf16, 128 rows x 64 cols, SW128) via cp.async
// ---------------------------------------------------------------------------
__device__ __forceinline__ void tc_load_tile_async(const __nv_bfloat16* __restrict__ src,
                                                   int row0, int maxrow, int koff,
                                                   int kstride, uint32_t sm, int tid) {
#pragma unroll
    for (int p = 0; p < 4; p++) {
        int idx = p * 256 + tid;
        int row = idx >> 3, seg = idx & 7;
        int gr = row0 + row;
        uint32_t bo = (uint32_t)(row * 128 + seg * 16);
        cp_async16(sm + sw_off(bo),
                   src + (size_t)gr * kstride + koff + seg * 8,
                   gr < maxrow);
    }
}

#define JT_BUF      16384
#define JT_SM_AH    1024
#define JT_SM_AL    (JT_SM_AH + JT_BUF)
#define JT_SM_WH    (JT_SM_AL + JT_BUF)
#define JT_SM_WL    (JT_SM_WH + JT_BUF)
#define JT_SMEM     (JT_SM_WL + JT_BUF)      // 66560

// ---------------------------------------------------------------------------
// Core mma.sync mainloop body (shared by gemm_tc and joiner fallback)
// acc layout: acc[nt] rows wr*32+[0,16), acc[8+nt] rows +16
// ---------------------------------------------------------------------------
__device__ __forceinline__ void mma_mainloop_chunk(uint32_t sbase, int wr, int wc,
                                                   int lane, float acc[16][4]) {
    const int aoffs[3] = {JT_SM_AH, JT_SM_AH, JT_SM_AL};
    const int boffs[3] = {JT_SM_WH, JT_SM_WL, JT_SM_WH};
    const int bt = lane >> 3, br_ = lane & 7;   // B-ldmatrix lane roles
#pragma unroll
    for (int s = 0; s < 4; s++) {
#pragma unroll
        for (int tm = 0; tm < 3; tm++) {
            uint32_t afrag[2][4];
#pragma unroll
            for (int mi = 0; mi < 2; mi++) {
                uint32_t bo = (uint32_t)((wr * 32 + mi * 16 + (lane & 15)) * 128
                                         + s * 32 + (lane >> 4) * 16);
                ldmatrix_x4(afrag[mi], sbase + aoffs[tm] + sw_off(bo));
            }
#pragma unroll
            for (int g = 0; g < 4; g++) {   // nt pairs (2g, 2g+1)
                uint32_t bo = (uint32_t)((wc * 64 + g * 16 + (bt >> 1) * 8 + br_) * 128
                                         + s * 32 + (bt & 1) * 16);
                uint32_t bfr[4];
                ldmatrix_x4(bfr, sbase + boffs[tm] + sw_off(bo));
                mma16816(acc[2 * g],     afrag[0], bfr[0], bfr[1]);
                mma16816(acc[8 + 2 * g], afrag[1], bfr[0], bfr[1]);
                mma16816(acc[2 * g + 1],     afrag[0], bfr[2], bfr[3]);
                mma16816(acc[8 + 2 * g + 1], afrag[1], bfr[2], bfr[3]);
            }
        }
    }
}

// ---------------------------------------------------------------------------
// Tensor-core GEMM (3-term bf16 hi/lo): C[z] = A @ W^T (+bias on z=0) (opt relu)
// ---------------------------------------------------------------------------
__global__ void __launch_bounds__(256) gemm_tc(
    const __nv_bfloat16* __restrict__ Ah, const __nv_bfloat16* __restrict__ Al,
    const __nv_bfloat16* __restrict__ Wh, const __nv_bfloat16* __restrict__ Wl,
    const float* __restrict__ bias,
    float* __restrict__ C,
    __nv_bfloat16* __restrict__ Ch, __nv_bfloat16* __restrict__ Cl,
    int M, int N, int kstride, int chunks, int relu) {
    extern __shared__ char smem[];
    const uint32_t sbase = smem_to_u32(smem);
    const int tid = threadIdx.x;
    const int n0 = blockIdx.x * 128;
    const int m0 = blockIdx.y * 128;
    const int z  = blockIdx.z;
    const int koff0 = z * chunks * 64;
    if (C) C += (size_t)z * M * N;

    const int w = tid >> 5, lane = tid & 31;
    const int wr = w >> 1, wc = w & 1;

    float acc[16][4];
#pragma unroll
    for (int i = 0; i < 16; i++)
#pragma unroll
        for (int j = 0; j < 4; j++) acc[i][j] = 0.f;

    for (int c = 0; c < chunks; c++) {
        const int koff = koff0 + c * 64;
        tc_load_tile_async(Ah, m0, M, koff, kstride, sbase + JT_SM_AH, tid);
        tc_load_tile_async(Al, m0, M, koff, kstride, sbase + JT_SM_AL, tid);
        tc_load_tile_async(Wh, n0, N, koff, kstride, sbase + JT_SM_WH, tid);
        tc_load_tile_async(Wl, n0, N, koff, kstride, sbase + JT_SM_WL, tid);
        cp_async_commit_wait();
        __syncthreads();
        mma_mainloop_chunk(sbase, wr, wc, lane, acc);
        __syncthreads();
    }

    const bool addb = (bias != nullptr) && (z == 0);
#pragma unroll
    for (int mi = 0; mi < 2; mi++) {
#pragma unroll
        for (int nt = 0; nt < 8; nt++) {
            int m = m0 + wr * 32 + mi * 16 + (lane >> 2);
            int ncol = n0 + wc * 64 + nt * 8 + 2 * (lane & 3);
            float b0v = addb ? bias[ncol] : 0.f;
            float b1v = addb ? bias[ncol + 1] : 0.f;
            float v0 = acc[mi * 8 + nt][0] + b0v;
            float v1 = acc[mi * 8 + nt][1] + b1v;
            float v2 = acc[mi * 8 + nt][2] + b0v;
            float v3 = acc[mi * 8 + nt][3] + b1v;
            if (relu) {
                v0 = fmaxf(v0, 0.f); v1 = fmaxf(v1, 0.f);
                v2 = fmaxf(v2, 0.f); v3 = fmaxf(v3, 0.f);
            }
            if (m < M) {
                size_t o = (size_t)m * N + ncol;
                if (C) *(float2*)(C + o) = make_float2(v0, v1);
                if (Ch) {
                    __nv_bfloat16 h0, h1, l0, l1;
                    split_hl(v0, h0, l0); split_hl(v1, h1, l1);
                    *(__nv_bfloat162*)(Ch + o) = __nv_bfloat162(h0, h1);
                    *(__nv_bfloat162*)(Cl + o) = __nv_bfloat162(l0, l1);
                }
            }
            if (m + 8 < M) {
                size_t o = (size_t)(m + 8) * N + ncol;
                if (C) *(float2*)(C + o) = make_float2(v2, v3);
                if (Ch) {
                    __nv_bfloat16 h0, h1, l0, l1;
                    split_hl(v2, h0, l0); split_hl(v3, h1, l1);
                    *(__nv_bfloat162*)(Ch + o) = __nv_bfloat162(h0, h1);
                    *(__nv_bfloat162*)(Cl + o) = __nv_bfloat162(l0, l1);
                }
            }
        }
    }
}

// ---------------------------------------------------------------------------
// Attention: one block per (n,h); sums QKV_SPLIT k-split slices of qkv.
// ---------------------------------------------------------------------------
__global__ void attention_kernel(const float* __restrict__ qkv,
                                 const int* __restrict__ tgt_len,
                                 __nv_bfloat16* __restrict__ oh,
                                 __nv_bfloat16* __restrict__ ol) {
    int n = blockIdx.x >> 3, h = blockIdx.x & 7;
    __shared__ float qs[TS_][HD_];
    __shared__ float ks[TS_][HD_];
    __shared__ float vs[TS_][HD_];
    __shared__ float sc[TS_][TS_ + 1];
    int tid = threadIdx.x;
    int len = tgt_len[n]; if (len < 1) len = 1;

    for (int e = tid; e < TS_ * HD_; e += 128) {
        int t = e >> 6, d = e & 63;
        size_t off = (size_t)(t * 8 + n) * (3 * D_) + h * 64 + d;
        const float* b0 = qkv + off;
        const float* b1 = qkv + (size_t)TOK_ * 3 * D_ + off;
        qs[t][d] = b0[0] + b1[0];
        ks[t][d] = b0[512] + b1[512];
        vs[t][d] = b0[1024] + b1[1024];
    }
    __syncthreads();

    for (int p = tid; p < TS_ * TS_; p += 128) {
        int tq = p / TS_, tk = p - tq * TS_;
        float s;
        if (tk > tq || tk >= len) {
            s = -1e9f;
        } else {
            s = 0.f;
#pragma unroll 8
            for (int d = 0; d < HD_; d++) s += qs[tq][d] * ks[tk][d];
            s *= 0.125f;
        }
        sc[tq][tk] = s;
    }
    __syncthreads();

    if (tid < TS_) {
        int tq = tid;
        float mx = -1e30f;
        for (int tk = 0; tk < TS_; tk++) mx = fmaxf(mx, sc[tq][tk]);
        float sum = 0.f;
        for (int tk = 0; tk < TS_; tk++) {
            float e = expf(sc[tq][tk] - mx);
            sc[tq][tk] = e;
            sum += e;
        }
        float inv = 1.0f / sum;
        for (int tk = 0; tk < TS_; tk++) sc[tq][tk] *= inv;
    }
    __syncthreads();

    for (int e = tid; e < TS_ * HD_; e += 128) {
        int tq = e >> 6, d = e & 63;
        float s = 0.f;
#pragma unroll 8
        for (int tk = 0; tk < TS_; tk++) s += sc[tq][tk] * vs[tk][d];
        size_t idx = (size_t)(tq * 8 + n) * D_ + h * 64 + d;
        __nv_bfloat16 hv, lv;
        split_hl(s, hv, lv);
        oh[idx] = hv; ol[idx] = lv;
    }
}

// ---------------------------------------------------------------------------
// Residual add (x + sum of nsplit tmp slices) + LN; writes x fp32 + hi/lo
// ---------------------------------------------------------------------------
__global__ void add_ln_kernel(float* __restrict__ x,
                              const float* __restrict__ y, int nsplit,
                              const float* __restrict__ s,
                              const float* __restrict__ b,
                              __nv_bfloat16* __restrict__ xh,
                              __nv_bfloat16* __restrict__ xl) {
    int row = blockIdx.x, tid = threadIdx.x;
    __shared__ float sh[8];
    const float4 xv = ((const float4*)(x + (size_t)row * D_))[tid];
    float r0 = xv.x, r1 = xv.y, r2 = xv.z, r3 = xv.w;
    for (int z = 0; z < nsplit; z++) {
        const float4 yv = ((const float4*)(y + (size_t)z * TOK_ * D_ + (size_t)row * D_))[tid];
        r0 += yv.x; r1 += yv.y; r2 += yv.z; r3 += yv.w;
    }

    float sum = r0 + r1 + r2 + r3;
    int lane = tid & 31, wp = tid >> 5;
#pragma unroll
    for (int off = 16; off > 0; off >>= 1) sum += __shfl_xor_sync(0xffffffffu, sum, off);
    if (lane == 0) sh[wp] = sum;
    __syncthreads();
    float mean = (sh[0] + sh[1] + sh[2] + sh[3]) * (1.0f / 512.0f);

    float d0 = r0 - mean, d1 = r1 - mean, d2 = r2 - mean, d3 = r3 - mean;
    float sq = d0 * d0 + d1 * d1 + d2 * d2 + d3 * d3;
#pragma unroll
    for (int off = 16; off > 0; off >>= 1) sq += __shfl_xor_sync(0xffffffffu, sq, off);
    if (lane == 0) sh[4 + wp] = sq;
    __syncthreads();
    float var = (sh[4] + sh[5] + sh[6] + sh[7]) * (1.0f / 512.0f);
    float rstd = 1.0f / sqrtf(var + 1e-5f);

    const float4 sv = ((const float4*)s)[tid];
    const float4 bv = ((const float4*)b)[tid];
    float o0 = d0 * rstd * sv.x + bv.x;
    float o1 = d1 * rstd * sv.y + bv.y;
    float o2 = d2 * rstd * sv.z + bv.z;
    float o3 = d3 * rstd * sv.w + bv.w;
    ((float4*)(x + (size_t)row * D_))[tid] = make_float4(o0, o1, o2, o3);

    size_t base = (size_t)row * D_ + tid * 4;
    __nv_bfloat16 h0, h1, h2, h3, l0, l1, l2, l3;
    split_hl(o0, h0, l0); split_hl(o1, h1, l1);
    split_hl(o2, h2, l2); split_hl(o3, h3, l3);
    ((__nv_bfloat162*)(xh + base))[0] = __nv_bfloat162(h0, h1);
    ((__nv_bfloat162*)(xh + base))[1] = __nv_bfloat162(h2, h3);
    ((__nv_bfloat162*)(xl + base))[0] = __nv_bfloat162(l0, l1);
    ((__nv_bfloat162*)(xl + base))[1] = __nv_bfloat162(l2, l3);
}

// ---------------------------------------------------------------------------
// Joiner A materialization + bf16 hi/lo split
// ---------------------------------------------------------------------------
__global__ void joiner_a_split_kernel(const float* __restrict__ enc,
                                      const float* __restrict__ x,
                                      __nv_bfloat16* __restrict__ Ah,
                                      __nv_bfloat16* __restrict__ Al) {
    int r = blockIdx.x;
    int n = r / (TI_ * TS_);
    int rem = r - n * (TI_ * TS_);
    int i = rem / TS_;
    int t = rem - i * TS_;
    const float4* er = (const float4*)(enc + (size_t)(i * 8 + n) * D_);
    const float4* xr = (const float4*)(x + (size_t)(t * 8 + n) * D_);
    int tid = threadIdx.x;
    float4 e = er[tid], xx = xr[tid];
    float a[4] = {tanhf(e.x + xx.x), tanhf(e.y + xx.y),
                  tanhf(e.z + xx.z), tanhf(e.w + xx.w)};
    __nv_bfloat16 h0, h1, h2, h3, l0, l1, l2, l3;
    split_hl(a[0], h0, l0); split_hl(a[1], h1, l1);
    split_hl(a[2], h2, l2); split_hl(a[3], h3, l3);
    size_t base = (size_t)r * D_ + tid * 4;
    ((__nv_bfloat162*)(Ah + base))[0] = __nv_bfloat162(h0, h1);
    ((__nv_bfloat162*)(Ah + base))[1] = __nv_bfloat162(h2, h3);
    ((__nv_bfloat162*)(Al + base))[0] = __nv_bfloat162(l0, l1);
    ((__nv_bfloat162*)(Al + base))[1] = __nv_bfloat162(l2, l3);
}

// ---------------------------------------------------------------------------
// Joiner GEMM (tile 128x128, K=512, 3-term bf16) — tcgen05 or mma.sync
// ---------------------------------------------------------------------------
#define JT_CHUNKS   8

__global__ void __launch_bounds__(256) joiner_tc_kernel(
    const __nv_bfloat16* __restrict__ Ah,
    const __nv_bfloat16* __restrict__ Al,
    const __nv_bfloat16* __restrict__ Wh,
    const __nv_bfloat16* __restrict__ Wl,
    float* __restrict__ C) {
    extern __shared__ char smem[];
    const uint32_t sbase = smem_to_u32(smem);
    const int tid = threadIdx.x;
    const int n0 = blockIdx.x * 128;
    const int m0 = blockIdx.y * 128;

#if USE_TCGEN05
    const int wid = tid >> 5, lane = tid & 31;

    if (wid == 0) {
        TCGEN05_ALLOC(sbase, 128);
        TCGEN05_RELINQUISH_ALLOC_PERMIT();
    }
    if (tid == 0) MBARRIER_INIT(sbase + 8, 1);
    __syncthreads();
    uint32_t tmem_base;
    asm volatile("ld.shared.b32 %0, [%1];" : "=r"(tmem_base) : "r"(sbase));

    const uint64_t dAh = MAKE_SMEM_DESC(sbase + JT_SM_AH);
    const uint64_t dAl = MAKE_SMEM_DESC(sbase + JT_SM_AL);
    const uint64_t dWh = MAKE_SMEM_DESC(sbase + JT_SM_WH);
    const uint64_t dWl = MAKE_SMEM_DESC(sbase + JT_SM_WL);

    for (int c = 0; c < JT_CHUNKS; c++) {
        if (c > 0) MBARRIER_WAIT_PARITY(sbase + 8, (c - 1) & 1);
        const int koff = c * 64;
        tc_load_tile_async(Ah, m0, MJ_, koff, D_, sbase + JT_SM_AH, tid);
        tc_load_tile_async(Al, m0, MJ_, koff, D_, sbase + JT_SM_AL, tid);
        tc_load_tile_async(Wh, n0, VP_, koff, D_, sbase + JT_SM_WH, tid);
        tc_load_tile_async(Wl, n0, VP_, koff, D_, sbase + JT_SM_WL, tid);
        cp_async_commit_wait();
        __syncthreads();
        if (wid == 0) {
            if (elect_one_pred()) {
                FENCE_PROXY_ASYNC_SHARED_CTA();
#pragma unroll
                for (int k = 0; k < 4; k++)
                    mma_f16_ss_cg1(tmem_base, dAh + k * 2, dWh + k * 2,
                                   JOINER_IDESC, (c > 0) || (k > 0));
#pragma unroll
                for (int k = 0; k < 4; k++)
                    mma_f16_ss_cg1(tmem_base, dAh + k * 2, dWl + k * 2,
                                   JOINER_IDESC, 1u);
#pragma unroll
                for (int k = 0; k < 4; k++)
                    mma_f16_ss_cg1(tmem_base, dAl + k * 2, dWh + k * 2,
                                   JOINER_IDESC, 1u);
                TCGEN05_COMMIT(sbase + 8);
            }
        }
    }
    MBARRIER_WAIT_PARITY(sbase + 8, (JT_CHUNKS - 1) & 1);
    TCGEN05_FENCE_AFTER();

    {
        const int sub = wid & 3;
        const int halfc = (wid >> 2) * 64;
        float* crow = C + (size_t)(m0 + sub * 32 + lane) * V_;
        const bool full = (n0 + 128) <= V_;
#pragma unroll
        for (int base = halfc; base < halfc + 64; base += 32) {
            uint32_t r[32];
            TCGEN05_LD_32X32B_X32(r, tmem_base + base);
            TCGEN05_WAIT_LD();
            if (full) {
#pragma unroll
                for (int j = 0; j < 32; j += 4) {
                    *(float4*)(crow + n0 + base + j) =
                        make_float4(__uint_as_float(r[j]), __uint_as_float(r[j + 1]),
                                    __uint_as_float(r[j + 2]), __uint_as_float(r[j + 3]));
                }
            } else {
#pragma unroll
                for (int j = 0; j < 32; j++) {
                    int col = n0 + base + j;
                    if (col < V_) crow[col] = __uint_as_float(r[j]);
                }
            }
        }
    }
    __syncthreads();
    if (wid == 0) {
        if (elect_one_pred()) MBARRIER_INVAL(sbase + 8);
        TCGEN05_DEALLOC(tmem_base, 128);
    }

#else  // mma.sync path
    const int w = tid >> 5, lane = tid & 31;
    const int wr = w >> 1, wc = w & 1;

    float acc[16][4];
#pragma unroll
    for (int i = 0; i < 16; i++)
#pragma unroll
        for (int j = 0; j < 4; j++) acc[i][j] = 0.f;

    for (int c = 0; c < JT_CHUNKS; c++) {
        const int koff = c * 64;
        tc_load_tile_async(Ah, m0, MJ_, koff, D_, sbase + JT_SM_AH, tid);
        tc_load_tile_async(Al, m0, MJ_, koff, D_, sbase + JT_SM_AL, tid);
        tc_load_tile_async(Wh, n0, VP_, koff, D_, sbase + JT_SM_WH, tid);
        tc_load_tile_async(Wl, n0, VP_, koff, D_, sbase + JT_SM_WL, tid);
        cp_async_commit_wait();
        __syncthreads();
        mma_mainloop_chunk(sbase, wr, wc, lane, acc);
        __syncthreads();
    }

#pragma unroll
    for (int mi = 0; mi < 2; mi++) {
#pragma unroll
        for (int nt = 0; nt < 8; nt++) {
            int m = m0 + wr * 32 + mi * 16 + (lane >> 2);
            int ncol = n0 + wc * 64 + nt * 8 + 2 * (lane & 3);
            if (ncol < V_) {
                float* p0 = C + (size_t)m * V_ + ncol;
                float* p1 = C + (size_t)(m + 8) * V_ + ncol;
                *(float2*)p0 = make_float2(acc[mi * 8 + nt][0], acc[mi * 8 + nt][1]);
                *(float2*)p1 = make_float2(acc[mi * 8 + nt][2], acc[mi * 8 + nt][3]);
            }
        }
    }
#endif
}

// ---------------------------------------------------------------------------
// Host orchestration
// ---------------------------------------------------------------------------
extern "C" void kernel_launch(void* const* d_in, const int* in_sizes, int n_in,
                              void* d_out, int out_size) {
    const float* enc_out = (const float*)d_in[0];
    const float* embed_w = (const float*)d_in[1];
    const float* enc_w   = (const float*)d_in[2];
    const float* enc_b   = (const float*)d_in[3];
    const float* qkv_w   = (const float*)d_in[4];
    const float* qkv_b   = (const float*)d_in[5];
    const float* o_w     = (const float*)d_in[6];
    const float* o_b     = (const float*)d_in[7];
    const float* ln1_s   = (const float*)d_in[8];
    const float* ln1_b   = (const float*)d_in[9];
    const float* ff1_w   = (const float*)d_in[10];
    const float* ff1_b   = (const float*)d_in[11];
    const float* ff2_w   = (const float*)d_in[12];
    const float* ff2_b   = (const float*)d_in[13];
    const float* ln2_s   = (const float*)d_in[14];
    const float* ln2_b   = (const float*)d_in[15];
    const float* out_w   = (const float*)d_in[16];
    const int*   tgt_pad = (const int*)d_in[17];
    const int*   tgt_len = (const int*)d_in[18];
    const int*   sos     = (const int*)d_in[19];

    float *x, *qkv, *tmp, *encp;
    cudaGetSymbolAddress((void**)&x, g_x);
    cudaGetSymbolAddress((void**)&qkv, g_qkv);
    cudaGetSymbolAddress((void**)&tmp, g_tmp);
    cudaGetSymbolAddress((void**)&encp, g_encp);

    __nv_bfloat16 *xh, *xl, *ath, *atl, *fh, *fl;
    cudaGetSymbolAddress((void**)&xh, g_xh);
    cudaGetSymbolAddress((void**)&xl, g_xl);
    cudaGetSymbolAddress((void**)&ath, g_ath);
    cudaGetSymbolAddress((void**)&atl, g_atl);
    cudaGetSymbolAddress((void**)&fh, g_fh);
    cudaGetSymbolAddress((void**)&fl, g_fl);

    __nv_bfloat16 *qkvwh, *qkvwl, *owh, *owl, *f1h, *f1l, *f2h, *f2l, *ewh, *ewl, *exh, *exl;
    cudaGetSymbolAddress((void**)&qkvwh, g_qkvwh);
    cudaGetSymbolAddress((void**)&qkvwl, g_qkvwl);
    cudaGetSymbolAddress((void**)&owh, g_owh);
    cudaGetSymbolAddress((void**)&owl, g_owl);
    cudaGetSymbolAddress((void**)&f1h, g_f1h);
    cudaGetSymbolAddress((void**)&f1l, g_f1l);
    cudaGetSymbolAddress((void**)&f2h, g_f2h);
    cudaGetSymbolAddress((void**)&f2l, g_f2l);
    cudaGetSymbolAddress((void**)&ewh, g_ewh);
    cudaGetSymbolAddress((void**)&ewl, g_ewl);
    cudaGetSymbolAddress((void**)&exh, g_exh);
    cudaGetSymbolAddress((void**)&exl, g_exl);

    __nv_bfloat16 *Ah, *Al, *Wh, *Wl;
    cudaGetSymbolAddress((void**)&Ah, g_Ah);
    cudaGetSymbolAddress((void**)&Al, g_Al);
    cudaGetSymbolAddress((void**)&Wh, g_Wh);
    cudaGetSymbolAddress((void**)&Wl, g_Wl);

    static bool attr_done = false;
    if (!attr_done) {
        cudaFuncSetAttribute(joiner_tc_kernel,
                             cudaFuncAttributeMaxDynamicSharedMemorySize, JT_SMEM);
        cudaFuncSetAttribute(gemm_tc,
                             cudaFuncAttributeMaxDynamicSharedMemorySize, JT_SMEM);
        attr_done = true;
    }

    // ---- fused weight splits (1 launch) + padded out_w split ----
    {
        SplitJobs jobs;
        int c0 = L_ * 3 * D_ * D_ / 4;
        int c1 = L_ * D_ * D_ / 4;
        int c2 = L_ * FF_ * D_ / 4;
        int c3 = L_ * D_ * FF_ / 4;
        int c4 = D_ * D_ / 4;
        int c5 = TI_ * NB_ * D_ / 4;
        jobs.src[0] = qkv_w;  jobs.h[0] = qkvwh; jobs.l[0] = qkvwl; jobs.end[0] = c0;
        jobs.src[1] = o_w;    jobs.h[1] = owh;   jobs.l[1] = owl;   jobs.end[1] = jobs.end[0] + c1;
        jobs.src[2] = ff1_w;  jobs.h[2] = f1h;   jobs.l[2] = f1l;   jobs.end[2] = jobs.end[1] + c2;
        jobs.src[3] = ff2_w;  jobs.h[3] = f2h;   jobs.l[3] = f2l;   jobs.end[3] = jobs.end[2] + c3;
        jobs.src[4] = enc_w;  jobs.h[4] = ewh;   jobs.l[4] = ewl;   jobs.end[4] = jobs.end[3] + c4;
        jobs.src[5] = enc_out;jobs.h[5] = exh;   jobs.l[5] = exl;   jobs.end[5] = jobs.end[4] + c5;
        int total = jobs.end[5];
        split_all_kernel<<<(total + 255) / 256, 256>>>(jobs, total);
        w_split_kernel<<<VP_, 128>>>(out_w, Wh, Wl);
    }

    // enc projection: encp[1024x512] = enc_out @ enc_w^T + b
    gemm_tc<<<dim3(D_ / 128, (TI_ * NB_) / 128, 1), 256, JT_SMEM>>>(
        exh, exl, ewh, ewl, enc_b, encp, nullptr, nullptr,
        TI_ * NB_, D_, D_, 8, 0);

    // embedding + positions
    embed_kernel<<<TOK_, 128>>>(embed_w, tgt_pad, sos, x, xh, xl);

    // 6 post-norm transformer layers
    for (int l = 0; l < L_; l++) {
        gemm_tc<<<dim3(3 * D_ / 128, 3, QKV_SPLIT), 256, JT_SMEM>>>(
            xh, xl, qkvwh + (size_t)l * 3 * D_ * D_, qkvwl + (size_t)l * 3 * D_ * D_,
            qkv_b + (size_t)l * 3 * D_, qkv, nullptr, nullptr,
            TOK_, 3 * D_, D_, 8 / QKV_SPLIT, 0);
        attention_kernel<<<NB_ * H_, 128>>>(qkv, tgt_len, ath, atl);
        gemm_tc<<<dim3(D_ / 128, 3, O_SPLIT), 256, JT_SMEM>>>(
            ath, atl, owh + (size_t)l * D_ * D_, owl + (size_t)l * D_ * D_,
            o_b + (size_t)l * D_, tmp, nullptr, nullptr,
            TOK_, D_, D_, 8 / O_SPLIT, 0);
        add_ln_kernel<<<TOK_, 128>>>(x, tmp, O_SPLIT,
            ln1_s + (size_t)l * D_, ln1_b + (size_t)l * D_, xh, xl);
        gemm_tc<<<dim3(FF_ / 128, 3, 1), 256, JT_SMEM>>>(
            xh, xl, f1h + (size_t)l * FF_ * D_, f1l + (size_t)l * FF_ * D_,
            ff1_b + (size_t)l * FF_, nullptr, fh, fl,
            TOK_, FF_, D_, 8, 1);
        gemm_tc<<<dim3(D_ / 128, 3, FF2_SPLIT), 256, JT_SMEM>>>(
            fh, fl, f2h + (size_t)l * D_ * FF_, f2l + (size_t)l * D_ * FF_,
            ff2_b + (size_t)l * D_, tmp, nullptr, nullptr,
            TOK_, D_, FF_, FF_ / 64 / FF2_SPLIT, 0);
        add_ln_kernel<<<TOK_, 128>>>(x, tmp, FF2_SPLIT,
            ln2_s + (size_t)l * D_, ln2_b + (size_t)l * D_, xh, xl);
    }

    // joiner
    joiner_a_split_kernel<<<MJ_, 128>>>(encp, x, Ah, Al);
    joiner_tc_kernel<<<dim3(VP_ / 128, MJ_ / 128), 256, JT_SMEM>>>(
        Ah, Al, Wh, Wl, (float*)d_out);
}

// round 6
// speedup vs baseline: 5.6610x; 1.2078x over previous
#include <cuda_runtime.h>
#include <cuda_bf16.h>
#include <math.h>
#include <stdint.h>

// ---------------------------------------------------------------------------
// Arch-feature gate (tcgen05 only legal on sm_10Xa feature targets)
// ---------------------------------------------------------------------------
#if defined(__CUDA_ARCH_FEAT_SM103_ALL) || defined(__CUDA_ARCH_FEAT_SM100_ALL) || defined(__CUDA_ARCH_FEAT_SM101_ALL)
#define USE_TCGEN05 1
#else
#define USE_TCGEN05 0
#endif

// ---------------------------------------------------------------------------
// Problem constants
// ---------------------------------------------------------------------------
#define TI_   128
#define NB_   8
#define TO_   32
#define TS_   33
#define D_    512
#define H_    8
#define HD_   64
#define FF_   2048
#define V_    2000
#define VP_   2048
#define L_    6
#define TOK_  (TS_ * NB_)          // 264
#define MJ_   (NB_ * TI_ * TS_)    // 33792
#define FF2_SPLIT 8
#define QKV_SPLIT 4
#define O_SPLIT   4

// ---------------------------------------------------------------------------
// Scratch (static __device__ arrays)
// ---------------------------------------------------------------------------
__device__ float g_x[TOK_ * D_];
__device__ float g_qkv[QKV_SPLIT * TOK_ * 3 * D_];
__device__ float g_tmp[FF2_SPLIT * TOK_ * D_];
__device__ float g_encp[TI_ * NB_ * D_];

__device__ __nv_bfloat16 g_xh[TOK_ * D_],  g_xl[TOK_ * D_];
__device__ __nv_bfloat16 g_ath[TOK_ * D_], g_atl[TOK_ * D_];
__device__ __nv_bfloat16 g_fh[TOK_ * FF_], g_fl[TOK_ * FF_];

__device__ __nv_bfloat16 g_qkvwh[(size_t)L_ * 3 * D_ * D_], g_qkvwl[(size_t)L_ * 3 * D_ * D_];
__device__ __nv_bfloat16 g_owh[(size_t)L_ * D_ * D_],       g_owl[(size_t)L_ * D_ * D_];
__device__ __nv_bfloat16 g_f1h[(size_t)L_ * FF_ * D_],      g_f1l[(size_t)L_ * FF_ * D_];
__device__ __nv_bfloat16 g_f2h[(size_t)L_ * D_ * FF_],      g_f2l[(size_t)L_ * D_ * FF_];
__device__ __nv_bfloat16 g_ewh[D_ * D_],                    g_ewl[D_ * D_];
__device__ __nv_bfloat16 g_exh[TI_ * NB_ * D_],             g_exl[TI_ * NB_ * D_];

__device__ __nv_bfloat16 g_Ah[(size_t)MJ_ * D_], g_Al[(size_t)MJ_ * D_];
__device__ __nv_bfloat16 g_Wh[(size_t)VP_ * D_], g_Wl[(size_t)VP_ * D_];

// ---------------------------------------------------------------------------
// PTX helpers
// ---------------------------------------------------------------------------
__device__ __forceinline__ uint32_t elect_one_pred() {
    uint32_t pred;
    asm volatile(
        "{\n\t.reg .pred p;\n\telect.sync _|p, 0xFFFFFFFF;\n\t"
        "selp.b32 %0, 1, 0, p;\n\t}"
        : "=r"(pred));
    return pred;
}
__device__ __forceinline__ uint32_t smem_to_u32(const void* smem_ptr) {
    uint32_t addr;
    asm("{ .reg .u64 tmp; cvta.to.shared.u64 tmp, %1; cvt.u32.u64 %0, tmp; }"
        : "=r"(addr) : "l"(smem_ptr));
    return addr;
}
__device__ __forceinline__ uint32_t sw_off(uint32_t bo) {
    return bo ^ ((bo >> 3) & 0x70);
}
// cp.async 16B with zero-fill when src invalid
__device__ __forceinline__ void cp_async16(uint32_t saddr, const void* gptr, int valid) {
    asm volatile("cp.async.cg.shared.global [%0], [%1], 16, %2;"
        :: "r"(saddr), "l"(gptr), "r"(valid ? 16 : 0));
}
__device__ __forceinline__ void cp_async_commit() {
    asm volatile("cp.async.commit_group;");
}
template <int N>
__device__ __forceinline__ void cp_async_wait() {
    asm volatile("cp.async.wait_group %0;" :: "n"(N) : "memory");
}
__device__ __forceinline__ void cp_async_commit_wait() {
    asm volatile("cp.async.commit_group;");
    asm volatile("cp.async.wait_group 0;" ::: "memory");
}

static constexpr uint64_t SMEM_DESC_BASE_SW128 =
    (uint64_t(2)  << 61) | (uint64_t(1) << 46) | (uint64_t(64) << 32) | (uint64_t(1) << 16);
#define MAKE_SMEM_DESC(base_addr) \
    (SMEM_DESC_BASE_SW128 | ((uint64_t)((base_addr) >> 4) & 0x3FFF))

#if USE_TCGEN05
#define TCGEN05_ALLOC(smem_result_addr, nCols) \
    asm volatile("tcgen05.alloc.cta_group::1.sync.aligned.shared::cta.b32 [%0], %1;" \
        :: "r"((uint32_t)(smem_result_addr)), "r"((uint32_t)(nCols)) : "memory")
#define TCGEN05_DEALLOC(tmem_addr, nCols) \
    asm volatile("tcgen05.dealloc.cta_group::1.sync.aligned.b32 %0, %1;" \
        :: "r"(tmem_addr), "r"((uint32_t)(nCols)))
#define TCGEN05_RELINQUISH_ALLOC_PERMIT() \
    asm volatile("tcgen05.relinquish_alloc_permit.cta_group::1.sync.aligned;")
#define TCGEN05_COMMIT(mbar_smem_addr) \
    asm volatile("tcgen05.commit.cta_group::1.mbarrier::arrive::one.shared::cluster.b64 [%0];" \
        :: "r"((uint32_t)(mbar_smem_addr)) : "memory")
#define TCGEN05_WAIT_LD() \
    asm volatile("tcgen05.wait::ld.sync.aligned;" ::: "memory")
#define TCGEN05_FENCE_AFTER() \
    asm volatile("tcgen05.fence::after_thread_sync;" ::: "memory")
#define FENCE_PROXY_ASYNC_SHARED_CTA() \
    asm volatile("fence.proxy.async.shared::cta;" ::: "memory")
#define MBARRIER_INIT(mbar_smem_addr, count) \
    asm volatile("mbarrier.init.shared.b64 [%0], %1;" \
        :: "r"((uint32_t)(mbar_smem_addr)), "r"((uint32_t)(count)) : "memory")
#define MBARRIER_INVAL(mbar_smem_addr) \
    asm volatile("mbarrier.inval.shared.b64 [%0];" :: "r"((uint32_t)(mbar_smem_addr)) : "memory")
#define MBARRIER_WAIT_PARITY(mbar_smem_addr, phase_parity) do { \
    uint32_t _mbar = (uint32_t)(mbar_smem_addr); \
    uint32_t _parity = (uint32_t)(phase_parity); \
    uint32_t _done; \
    asm volatile( \
        "{\n\t.reg .pred p;\n\t" \
        "mbarrier.try_wait.parity.acquire.cta.shared::cta.b64 p, [%1], %2;\n\t" \
        "selp.b32 %0, 1, 0, p;\n\t}" \
        : "=r"(_done) : "r"(_mbar), "r"(_parity) : "memory"); \
    if (!_done) { \
        asm volatile( \
            "{\n\t.reg .pred P1;\n\t" \
            "WAIT_LOOP_%=:\n\t" \
            "mbarrier.try_wait.parity.acquire.cta.shared::cta.b64 P1, [%0], %1, 0x989680;\n\t" \
            "@P1 bra.uni WAIT_DONE_%=;\n\t" \
            "bra.uni WAIT_LOOP_%=;\n\t" \
            "WAIT_DONE_%=:\n\t}" \
            :: "r"(_mbar), "r"(_parity) : "memory"); \
    } \
} while(0)
#define TCGEN05_LD_32X32B_X32(r, tmem_addr) \
    asm volatile( \
        "tcgen05.ld.sync.aligned.32x32b.x32.b32 " \
        "{%0, %1, %2, %3, %4, %5, %6, %7, " \
        " %8, %9, %10, %11, %12, %13, %14, %15, " \
        " %16, %17, %18, %19, %20, %21, %22, %23, " \
        " %24, %25, %26, %27, %28, %29, %30, %31}, [%32];" \
        : "=r"((r)[0]),  "=r"((r)[1]),  "=r"((r)[2]),  "=r"((r)[3]), \
          "=r"((r)[4]),  "=r"((r)[5]),  "=r"((r)[6]),  "=r"((r)[7]), \
          "=r"((r)[8]),  "=r"((r)[9]),  "=r"((r)[10]), "=r"((r)[11]), \
          "=r"((r)[12]), "=r"((r)[13]), "=r"((r)[14]), "=r"((r)[15]), \
          "=r"((r)[16]), "=r"((r)[17]), "=r"((r)[18]), "=r"((r)[19]), \
          "=r"((r)[20]), "=r"((r)[21]), "=r"((r)[22]), "=r"((r)[23]), \
          "=r"((r)[24]), "=r"((r)[25]), "=r"((r)[26]), "=r"((r)[27]), \
          "=r"((r)[28]), "=r"((r)[29]), "=r"((r)[30]), "=r"((r)[31]) \
        : "r"(tmem_addr))

__device__ __forceinline__ void mma_f16_ss_cg1(uint32_t d_tmem, uint64_t a_desc,
                                               uint64_t b_desc, uint32_t idesc,
                                               uint32_t enable) {
    asm volatile(
        "{\n\t.reg .pred p;\n\t"
        "setp.ne.u32 p, %4, 0;\n\t"
        "tcgen05.mma.cta_group::1.kind::f16 [%0], %1, %2, %3, {%5, %5, %5, %5}, p;\n\t}"
        :: "r"(d_tmem), "l"(a_desc), "l"(b_desc), "r"(idesc), "r"(enable), "r"(0u)
        : "memory");
}
#define JOINER_IDESC 0x8200490u
#endif // USE_TCGEN05

// ---------------------------------------------------------------------------
// mma.sync helpers (base target)
// ---------------------------------------------------------------------------
__device__ __forceinline__ void ldmatrix_x4(uint32_t* r, uint32_t addr) {
    asm volatile("ldmatrix.sync.aligned.m8n8.x4.shared.b16 {%0,%1,%2,%3}, [%4];"
        : "=r"(r[0]), "=r"(r[1]), "=r"(r[2]), "=r"(r[3]) : "r"(addr));
}
__device__ __forceinline__ void mma16816(float* d, const uint32_t* a,
                                         uint32_t b0, uint32_t b1) {
    asm volatile(
        "mma.sync.aligned.m16n8k16.row.col.f32.bf16.bf16.f32 "
        "{%0,%1,%2,%3}, {%4,%5,%6,%7}, {%8,%9}, {%0,%1,%2,%3};"
        : "+f"(d[0]), "+f"(d[1]), "+f"(d[2]), "+f"(d[3])
        : "r"(a[0]), "r"(a[1]), "r"(a[2]), "r"(a[3]), "r"(b0), "r"(b1));
}

__device__ __forceinline__ void split_hl(float v, __nv_bfloat16& h, __nv_bfloat16& l) {
    h = __float2bfloat16(v);
    l = __float2bfloat16(v - __bfloat162float(h));
}

// ---------------------------------------------------------------------------
// Fused weight split: one launch handles all fp32 -> bf16 hi/lo conversions
// ---------------------------------------------------------------------------
#define NSPLITJOBS 6
struct SplitJobs {
    const float* src[NSPLITJOBS];
    __nv_bfloat16* h[NSPLITJOBS];
    __nv_bfloat16* l[NSPLITJOBS];
    int end[NSPLITJOBS];   // prefix-sum of vec4 counts
};

__global__ void split_all_kernel(SplitJobs jobs, int total) {
    int i = blockIdx.x * blockDim.x + threadIdx.x;
    if (i >= total) return;
    int j = 0;
#pragma unroll
    for (int k = 0; k < NSPLITJOBS - 1; k++) j += (i >= jobs.end[k]);
    int base = (j == 0) ? 0 : jobs.end[j - 1];
    int li = i - base;
    float4 w = ((const float4*)jobs.src[j])[li];
    __nv_bfloat16 h0, h1, h2, h3, l0, l1, l2, l3;
    split_hl(w.x, h0, l0); split_hl(w.y, h1, l1);
    split_hl(w.z, h2, l2); split_hl(w.w, h3, l3);
    ((__nv_bfloat162*)jobs.h[j])[2 * li]     = __nv_bfloat162(h0, h1);
    ((__nv_bfloat162*)jobs.h[j])[2 * li + 1] = __nv_bfloat162(h2, h3);
    ((__nv_bfloat162*)jobs.l[j])[2 * li]     = __nv_bfloat162(l0, l1);
    ((__nv_bfloat162*)jobs.l[j])[2 * li + 1] = __nv_bfloat162(l2, l3);
}

// out_w split padded to VP_ rows
__global__ void w_split_kernel(const float* __restrict__ W,
                               __nv_bfloat16* __restrict__ Wh,
                               __nv_bfloat16* __restrict__ Wl) {
    int r = blockIdx.x;
    int tid = threadIdx.x;
    size_t base = (size_t)r * D_ + tid * 4;
    if (r < V_) {
        const float4 w = ((const float4*)(W + (size_t)r * D_))[tid];
        __nv_bfloat16 h0, h1, h2, h3, l0, l1, l2, l3;
        split_hl(w.x, h0, l0); split_hl(w.y, h1, l1);
        split_hl(w.z, h2, l2); split_hl(w.w, h3, l3);
        ((__nv_bfloat162*)(Wh + base))[0] = __nv_bfloat162(h0, h1);
        ((__nv_bfloat162*)(Wh + base))[1] = __nv_bfloat162(h2, h3);
        ((__nv_bfloat162*)(Wl + base))[0] = __nv_bfloat162(l0, l1);
        ((__nv_bfloat162*)(Wl + base))[1] = __nv_bfloat162(l2, l3);
    } else {
        __nv_bfloat162 z = __nv_bfloat162(__float2bfloat16(0.f), __float2bfloat16(0.f));
        ((__nv_bfloat162*)(Wh + base))[0] = z;
        ((__nv_bfloat162*)(Wh + base))[1] = z;
        ((__nv_bfloat162*)(Wl + base))[0] = z;
        ((__nv_bfloat162*)(Wl + base))[1] = z;
    }
}

// ---------------------------------------------------------------------------
// Embedding + positions -> x fp32 + hi/lo  (fp32 transcendental math)
// ---------------------------------------------------------------------------
__global__ void embed_kernel(const float* __restrict__ embed,
                             const int* __restrict__ tgt_pad,
                             const int* __restrict__ sos,
                             float* __restrict__ x,
                             __nv_bfloat16* __restrict__ xh,
                             __nv_bfloat16* __restrict__ xl) {
    int r = blockIdx.x;
    int t = r >> 3, n = r & 7;
    int tok = (t == 0) ? sos[0] : tgt_pad[n * TO_ + (t - 1)];
    const float* e = embed + (size_t)tok * D_;
    const float sc = sqrtf(512.0f);
    int tid = threadIdx.x;
#pragma unroll
    for (int i = 0; i < 2; i++) {
        int d = tid * 4 + i * 2;       // even index; pair (sin, cos) share angle
        float ddiv = expf((float)d * (-9.210340371976184f / 512.0f));
        float ang = (float)t * ddiv;
        float sv, cv;
        sincosf(ang, &sv, &cv);
        size_t idx = (size_t)r * D_ + d;
        float v0 = e[d] * sc + sv;
        float v1 = e[d + 1] * sc + cv;
        x[idx] = v0; x[idx + 1] = v1;
        __nv_bfloat16 h0, l0, h1, l1;
        split_hl(v0, h0, l0); split_hl(v1, h1, l1);
        xh[idx] = h0; xh[idx + 1] = h1;
        xl[idx] = l0; xl[idx + 1] = l1;
    }
}

// ---------------------------------------------------------------------------
// Tile loaders (bf16, 128 rows; SW128 rows of 128B = 64 elements)
// ---------------------------------------------------------------------------
// full 64-element chunk (used by tcgen05 path only)
__device__ __forceinline__ void tc_load_tile_async(const __nv_bfloat16* __restrict__ src,
                                                   int row0, int maxrow, int koff,
                                                   int kstride, uint32_t sm, int tid) {
#pragma unroll
    for (int p = 0; p < 4; p++) {
        int idx = p * 256 + tid;
        int row = idx >> 3, seg = idx & 7;
        int gr = row0 + row;
        uint32_t bo = (uint32_t)(row * 128 + seg * 16);
        cp_async16(sm + sw_off(bo),
                   src + (size_t)gr * kstride + koff + seg * 8,
                   gr < maxrow);
    }
}
// half chunk (32 elements = 64B): p selects which 64B half of the row buffer
__device__ __forceinline__ void tc_load_half_async(const __nv_bfloat16* __restrict__ src,
                                                   int row0, int maxrow, int kelem,
                                                   int kstride, uint32_t sm, int tid, int p) {
#pragma unroll
    for (int q = 0; q < 2; q++) {
        int idx = q * 256 + tid;        // 0..511
        int row = idx >> 2, seg = idx & 3;
        int gr = row0 + row;
        uint32_t bo = (uint32_t)(row * 128 + p * 64 + seg * 16);
        cp_async16(sm + sw_off(bo),
                   src + (size_t)gr * kstride + kelem + seg * 8,
                   gr < maxrow);
    }
}

#define JT_BUF      16384
#define JT_SM_AH    1024
#define JT_SM_AL    (JT_SM_AH + JT_BUF)
#define JT_SM_WH    (JT_SM_AL + JT_BUF)
#define JT_SM_WL    (JT_SM_WH + JT_BUF)
#define JT_SMEM     (JT_SM_WL + JT_BUF)      // 66560

__device__ __forceinline__ void load_half4(const __nv_bfloat16* Ah, const __nv_bfloat16* Al,
                                           const __nv_bfloat16* Wh, const __nv_bfloat16* Wl,
                                           int m0, int M, int n0, int N,
                                           int kelem, int kstride,
                                           uint32_t sbase, int tid, int p) {
    tc_load_half_async(Ah, m0, M, kelem, kstride, sbase + JT_SM_AH, tid, p);
    tc_load_half_async(Al, m0, M, kelem, kstride, sbase + JT_SM_AL, tid, p);
    tc_load_half_async(Wh, n0, N, kelem, kstride, sbase + JT_SM_WH, tid, p);
    tc_load_half_async(Wl, n0, N, kelem, kstride, sbase + JT_SM_WL, tid, p);
}

// ---------------------------------------------------------------------------
// mma.sync mainloop over ONE 32-element half (s = 2p, 2p+1)
// ---------------------------------------------------------------------------
__device__ __forceinline__ void mma_mainloop_half(uint32_t sbase, int wr, int wc,
                                                  int lane, float acc[16][4], int p) {
    const int aoffs[3] = {JT_SM_AH, JT_SM_AH, JT_SM_AL};
    const int boffs[3] = {JT_SM_WH, JT_SM_WL, JT_SM_WH};
    const int bt = lane >> 3, br_ = lane & 7;
#pragma unroll
    for (int si = 0; si < 2; si++) {
        const int s = 2 * p + si;
#pragma unroll
        for (int tm = 0; tm < 3; tm++) {
            uint32_t afrag[2][4];
#pragma unroll
            for (int mi = 0; mi < 2; mi++) {
                uint32_t bo = (uint32_t)((wr * 32 + mi * 16 + (lane & 15)) * 128
                                         + s * 32 + (lane >> 4) * 16);
                ldmatrix_x4(afrag[mi], sbase + aoffs[tm] + sw_off(bo));
            }
#pragma unroll
            for (int g = 0; g < 4; g++) {
                uint32_t bo = (uint32_t)((wc * 64 + g * 16 + (bt >> 1) * 8 + br_) * 128
                                         + s * 32 + (bt & 1) * 16);
                uint32_t bfr[4];
                ldmatrix_x4(bfr, sbase + boffs[tm] + sw_off(bo));
                mma16816(acc[2 * g],     afrag[0], bfr[0], bfr[1]);
                mma16816(acc[8 + 2 * g], afrag[1], bfr[0], bfr[1]);
                mma16816(acc[2 * g + 1],     afrag[0], bfr[2], bfr[3]);
                mma16816(acc[8 + 2 * g + 1], afrag[1], bfr[2], bfr[3]);
            }
        }
    }
}

// ---------------------------------------------------------------------------
// Tensor-core GEMM (3-term bf16 hi/lo) with intra-CTA half-buffer pipeline
// ---------------------------------------------------------------------------
__global__ void __launch_bounds__(256) gemm_tc(
    const __nv_bfloat16* __restrict__ Ah, const __nv_bfloat16* __restrict__ Al,
    const __nv_bfloat16* __restrict__ Wh, const __nv_bfloat16* __restrict__ Wl,
    const float* __restrict__ bias,
    float* __restrict__ C,
    __nv_bfloat16* __restrict__ Ch, __nv_bfloat16* __restrict__ Cl,
    int M, int N, int kstride, int chunks, int relu) {
    extern __shared__ char smem[];
    const uint32_t sbase = smem_to_u32(smem);
    const int tid = threadIdx.x;
    const int n0 = blockIdx.x * 128;
    const int m0 = blockIdx.y * 128;
    const int z  = blockIdx.z;
    const int koff0 = z * chunks * 64;
    if (C) C += (size_t)z * M * N;

    const int w = tid >> 5, lane = tid & 31;
    const int wr = w >> 1, wc = w & 1;

    float acc[16][4];
#pragma unroll
    for (int i = 0; i < 16; i++)
#pragma unroll
        for (int j = 0; j < 4; j++) acc[i][j] = 0.f;

    const int nhalf = chunks * 2;
    load_half4(Ah, Al, Wh, Wl, m0, M, n0, N, koff0, kstride, sbase, tid, 0);
    cp_async_commit();
    for (int c = 0; c < nhalf; c++) {
        if (c + 1 < nhalf) {
            load_half4(Ah, Al, Wh, Wl, m0, M, n0, N,
                       koff0 + (c + 1) * 32, kstride, sbase, tid, (c + 1) & 1);
            cp_async_commit();
            cp_async_wait<1>();
        } else {
            cp_async_wait<0>();
        }
        __syncthreads();
        mma_mainloop_half(sbase, wr, wc, lane, acc, c & 1);
        __syncthreads();
    }

    const bool addb = (bias != nullptr) && (z == 0);
#pragma unroll
    for (int mi = 0; mi < 2; mi++) {
#pragma unroll
        for (int nt = 0; nt < 8; nt++) {
            int m = m0 + wr * 32 + mi * 16 + (lane >> 2);
            int ncol = n0 + wc * 64 + nt * 8 + 2 * (lane & 3);
            float b0v = addb ? bias[ncol] : 0.f;
            float b1v = addb ? bias[ncol + 1] : 0.f;
            float v0 = acc[mi * 8 + nt][0] + b0v;
            float v1 = acc[mi * 8 + nt][1] + b1v;
            float v2 = acc[mi * 8 + nt][2] + b0v;
            float v3 = acc[mi * 8 + nt][3] + b1v;
            if (relu) {
                v0 = fmaxf(v0, 0.f); v1 = fmaxf(v1, 0.f);
                v2 = fmaxf(v2, 0.f); v3 = fmaxf(v3, 0.f);
            }
            if (m < M) {
                size_t o = (size_t)m * N + ncol;
                if (C) *(float2*)(C + o) = make_float2(v0, v1);
                if (Ch) {
                    __nv_bfloat16 h0, h1, l0, l1;
                    split_hl(v0, h0, l0); split_hl(v1, h1, l1);
                    *(__nv_bfloat162*)(Ch + o) = __nv_bfloat162(h0, h1);
                    *(__nv_bfloat162*)(Cl + o) = __nv_bfloat162(l0, l1);
                }
            }
            if (m + 8 < M) {
                size_t o = (size_t)(m + 8) * N + ncol;
                if (C) *(float2*)(C + o) = make_float2(v2, v3);
                if (Ch) {
                    __nv_bfloat16 h0, h1, l0, l1;
                    split_hl(v2, h0, l0); split_hl(v3, h1, l1);
                    *(__nv_bfloat162*)(Ch + o) = __nv_bfloat162(h0, h1);
                    *(__nv_bfloat162*)(Cl + o) = __nv_bfloat162(l0, l1);
                }
            }
        }
    }
}

// ---------------------------------------------------------------------------
// Attention: one block per (n,h); sums QKV_SPLIT k-split slices of qkv.
// ---------------------------------------------------------------------------
__global__ void attention_kernel(const float* __restrict__ qkv,
                                 const int* __restrict__ tgt_len,
                                 __nv_bfloat16* __restrict__ oh,
                                 __nv_bfloat16* __restrict__ ol) {
    int n = blockIdx.x >> 3, h = blockIdx.x & 7;
    __shared__ float qs[TS_][HD_];
    __shared__ float ks[TS_][HD_];
    __shared__ float vs[TS_][HD_];
    __shared__ float sc[TS_][TS_ + 1];
    int tid = threadIdx.x;
    int len = tgt_len[n]; if (len < 1) len = 1;

    for (int e = tid; e < TS_ * HD_; e += 128) {
        int t = e >> 6, d = e & 63;
        size_t off = (size_t)(t * 8 + n) * (3 * D_) + h * 64 + d;
        float q = 0.f, k = 0.f, v = 0.f;
#pragma unroll
        for (int z = 0; z < QKV_SPLIT; z++) {
            const float* b = qkv + (size_t)z * TOK_ * 3 * D_ + off;
            q += b[0]; k += b[512]; v += b[1024];
        }
        qs[t][d] = q; ks[t][d] = k; vs[t][d] = v;
    }
    __syncthreads();

    for (int p = tid; p < TS_ * TS_; p += 128) {
        int tq = p / TS_, tk = p - tq * TS_;
        float s;
        if (tk > tq || tk >= len) {
            s = -1e9f;
        } else {
            s = 0.f;
#pragma unroll 8
            for (int d = 0; d < HD_; d++) s += qs[tq][d] * ks[tk][d];
            s *= 0.125f;
        }
        sc[tq][tk] = s;
    }
    __syncthreads();

    if (tid < TS_) {
        int tq = tid;
        float mx = -1e30f;
        for (int tk = 0; tk < TS_; tk++) mx = fmaxf(mx, sc[tq][tk]);
        float sum = 0.f;
        for (int tk = 0; tk < TS_; tk++) {
            float e = expf(sc[tq][tk] - mx);
            sc[tq][tk] = e;
            sum += e;
        }
        float inv = 1.0f / sum;
        for (int tk = 0; tk < TS_; tk++) sc[tq][tk] *= inv;
    }
    __syncthreads();

    for (int e = tid; e < TS_ * HD_; e += 128) {
        int tq = e >> 6, d = e & 63;
        float s = 0.f;
#pragma unroll 8
        for (int tk = 0; tk < TS_; tk++) s += sc[tq][tk] * vs[tk][d];
        size_t idx = (size_t)(tq * 8 + n) * D_ + h * 64 + d;
        __nv_bfloat16 hv, lv;
        split_hl(s, hv, lv);
        oh[idx] = hv; ol[idx] = lv;
    }
}

// ---------------------------------------------------------------------------
// Residual add (x + sum of nsplit tmp slices) + LN; writes x fp32 + hi/lo
// ---------------------------------------------------------------------------
__global__ void add_ln_kernel(float* __restrict__ x,
                              const float* __restrict__ y, int nsplit,
                              const float* __restrict__ s,
                              const float* __restrict__ b,
                              __nv_bfloat16* __restrict__ xh,
                              __nv_bfloat16* __restrict__ xl) {
    int row = blockIdx.x, tid = threadIdx.x;
    __shared__ float sh[8];
    const float4 xv = ((const float4*)(x + (size_t)row * D_))[tid];
    float r0 = xv.x, r1 = xv.y, r2 = xv.z, r3 = xv.w;
    for (int z = 0; z < nsplit; z++) {
        const float4 yv = ((const float4*)(y + (size_t)z * TOK_ * D_ + (size_t)row * D_))[tid];
        r0 += yv.x; r1 += yv.y; r2 += yv.z; r3 += yv.w;
    }

    float sum = r0 + r1 + r2 + r3;
    int lane = tid & 31, wp = tid >> 5;
#pragma unroll
    for (int off = 16; off > 0; off >>= 1) sum += __shfl_xor_sync(0xffffffffu, sum, off);
    if (lane == 0) sh[wp] = sum;
    __syncthreads();
    float mean = (sh[0] + sh[1] + sh[2] + sh[3]) * (1.0f / 512.0f);

    float d0 = r0 - mean, d1 = r1 - mean, d2 = r2 - mean, d3 = r3 - mean;
    float sq = d0 * d0 + d1 * d1 + d2 * d2 + d3 * d3;
#pragma unroll
    for (int off = 16; off > 0; off >>= 1) sq += __shfl_xor_sync(0xffffffffu, sq, off);
    if (lane == 0) sh[4 + wp] = sq;
    __syncthreads();
    float var = (sh[4] + sh[5] + sh[6] + sh[7]) * (1.0f / 512.0f);
    float rstd = 1.0f / sqrtf(var + 1e-5f);

    const float4 sv = ((const float4*)s)[tid];
    const float4 bv = ((const float4*)b)[tid];
    float o0 = d0 * rstd * sv.x + bv.x;
    float o1 = d1 * rstd * sv.y + bv.y;
    float o2 = d2 * rstd * sv.z + bv.z;
    float o3 = d3 * rstd * sv.w + bv.w;
    ((float4*)(x + (size_t)row * D_))[tid] = make_float4(o0, o1, o2, o3);

    size_t base = (size_t)row * D_ + tid * 4;
    __nv_bfloat16 h0, h1, h2, h3, l0, l1, l2, l3;
    split_hl(o0, h0, l0); split_hl(o1, h1, l1);
    split_hl(o2, h2, l2); split_hl(o3, h3, l3);
    ((__nv_bfloat162*)(xh + base))[0] = __nv_bfloat162(h0, h1);
    ((__nv_bfloat162*)(xh + base))[1] = __nv_bfloat162(h2, h3);
    ((__nv_bfloat162*)(xl + base))[0] = __nv_bfloat162(l0, l1);
    ((__nv_bfloat162*)(xl + base))[1] = __nv_bfloat162(l2, l3);
}

// ---------------------------------------------------------------------------
// Joiner A materialization + bf16 hi/lo split
// ---------------------------------------------------------------------------
__global__ void joiner_a_split_kernel(const float* __restrict__ enc,
                                      const float* __restrict__ x,
                                      __nv_bfloat16* __restrict__ Ah,
                                      __nv_bfloat16* __restrict__ Al) {
    int r = blockIdx.x;
    int n = r / (TI_ * TS_);
    int rem = r - n * (TI_ * TS_);
    int i = rem / TS_;
    int t = rem - i * TS_;
    const float4* er = (const float4*)(enc + (size_t)(i * 8 + n) * D_);
    const float4* xr = (const float4*)(x + (size_t)(t * 8 + n) * D_);
    int tid = threadIdx.x;
    float4 e = er[tid], xx = xr[tid];
    float a[4] = {tanhf(e.x + xx.x), tanhf(e.y + xx.y),
                  tanhf(e.z + xx.z), tanhf(e.w + xx.w)};
    __nv_bfloat16 h0, h1, h2, h3, l0, l1, l2, l3;
    split_hl(a[0], h0, l0); split_hl(a[1], h1, l1);
    split_hl(a[2], h2, l2); split_hl(a[3], h3, l3);
    size_t base = (size_t)r * D_ + tid * 4;
    ((__nv_bfloat162*)(Ah + base))[0] = __nv_bfloat162(h0, h1);
    ((__nv_bfloat162*)(Ah + base))[1] = __nv_bfloat162(h2, h3);
    ((__nv_bfloat162*)(Al + base))[0] = __nv_bfloat162(l0, l1);
    ((__nv_bfloat162*)(Al + base))[1] = __nv_bfloat162(l2, l3);
}

// ---------------------------------------------------------------------------
// Joiner GEMM (tile 128x128, K=512, 3-term bf16) — tcgen05 or mma.sync
// ---------------------------------------------------------------------------
#define JT_CHUNKS   8

__global__ void __launch_bounds__(256) joiner_tc_kernel(
    const __nv_bfloat16* __restrict__ Ah,
    const __nv_bfloat16* __restrict__ Al,
    const __nv_bfloat16* __restrict__ Wh,
    const __nv_bfloat16* __restrict__ Wl,
    float* __restrict__ C) {
    extern __shared__ char smem[];
    const uint32_t sbase = smem_to_u32(smem);
    const int tid = threadIdx.x;
    const int n0 = blockIdx.x * 128;
    const int m0 = blockIdx.y * 128;

#if USE_TCGEN05
    const int wid = tid >> 5, lane = tid & 31;

    if (wid == 0) {
        TCGEN05_ALLOC(sbase, 128);
        TCGEN05_RELINQUISH_ALLOC_PERMIT();
    }
    if (tid == 0) MBARRIER_INIT(sbase + 8, 1);
    __syncthreads();
    uint32_t tmem_base;
    asm volatile("ld.shared.b32 %0, [%1];" : "=r"(tmem_base) : "r"(sbase));

    const uint64_t dAh = MAKE_SMEM_DESC(sbase + JT_SM_AH);
    const uint64_t dAl = MAKE_SMEM_DESC(sbase + JT_SM_AL);
    const uint64_t dWh = MAKE_SMEM_DESC(sbase + JT_SM_WH);
    const uint64_t dWl = MAKE_SMEM_DESC(sbase + JT_SM_WL);

    for (int c = 0; c < JT_CHUNKS; c++) {
        if (c > 0) MBARRIER_WAIT_PARITY(sbase + 8, (c - 1) & 1);
        const int koff = c * 64;
        tc_load_tile_async(Ah, m0, MJ_, koff, D_, sbase + JT_SM_AH, tid);
        tc_load_tile_async(Al, m0, MJ_, koff, D_, sbase + JT_SM_AL, tid);
        tc_load_tile_async(Wh, n0, VP_, koff, D_, sbase + JT_SM_WH, tid);
        tc_load_tile_async(Wl, n0, VP_, koff, D_, sbase + JT_SM_WL, tid);
        cp_async_commit_wait();
        __syncthreads();
        if (wid == 0) {
            if (elect_one_pred()) {
                FENCE_PROXY_ASYNC_SHARED_CTA();
#pragma unroll
                for (int k = 0; k < 4; k++)
                    mma_f16_ss_cg1(tmem_base, dAh + k * 2, dWh + k * 2,
                                   JOINER_IDESC, (c > 0) || (k > 0));
#pragma unroll
                for (int k = 0; k < 4; k++)
                    mma_f16_ss_cg1(tmem_base, dAh + k * 2, dWl + k * 2,
                                   JOINER_IDESC, 1u);
#pragma unroll
                for (int k = 0; k < 4; k++)
                    mma_f16_ss_cg1(tmem_base, dAl + k * 2, dWh + k * 2,
                                   JOINER_IDESC, 1u);
                TCGEN05_COMMIT(sbase + 8);
            }
        }
    }
    MBARRIER_WAIT_PARITY(sbase + 8, (JT_CHUNKS - 1) & 1);
    TCGEN05_FENCE_AFTER();

    {
        const int sub = wid & 3;
        const int halfc = (wid >> 2) * 64;
        float* crow = C + (size_t)(m0 + sub * 32 + lane) * V_;
        const bool full = (n0 + 128) <= V_;
#pragma unroll
        for (int base = halfc; base < halfc + 64; base += 32) {
            uint32_t r[32];
            TCGEN05_LD_32X32B_X32(r, tmem_base + base);
            TCGEN05_WAIT_LD();
            if (full) {
#pragma unroll
                for (int j = 0; j < 32; j += 4) {
                    *(float4*)(crow + n0 + base + j) =
                        make_float4(__uint_as_float(r[j]), __uint_as_float(r[j + 1]),
                                    __uint_as_float(r[j + 2]), __uint_as_float(r[j + 3]));
                }
            } else {
#pragma unroll
                for (int j = 0; j < 32; j++) {
                    int col = n0 + base + j;
                    if (col < V_) crow[col] = __uint_as_float(r[j]);
                }
            }
        }
    }
    __syncthreads();
    if (wid == 0) {
        if (elect_one_pred()) MBARRIER_INVAL(sbase + 8);
        TCGEN05_DEALLOC(tmem_base, 128);
    }

#else  // mma.sync path with half-buffer pipeline
    const int w = tid >> 5, lane = tid & 31;
    const int wr = w >> 1, wc = w & 1;

    float acc[16][4];
#pragma unroll
    for (int i = 0; i < 16; i++)
#pragma unroll
        for (int j = 0; j < 4; j++) acc[i][j] = 0.f;

    const int nhalf = JT_CHUNKS * 2;
    load_half4(Ah, Al, Wh, Wl, m0, MJ_, n0, VP_, 0, D_, sbase, tid, 0);
    cp_async_commit();
    for (int c = 0; c < nhalf; c++) {
        if (c + 1 < nhalf) {
            load_half4(Ah, Al, Wh, Wl, m0, MJ_, n0, VP_,
                       (c + 1) * 32, D_, sbase, tid, (c + 1) & 1);
            cp_async_commit();
            cp_async_wait<1>();
        } else {
            cp_async_wait<0>();
        }
        __syncthreads();
        mma_mainloop_half(sbase, wr, wc, lane, acc, c & 1);
        __syncthreads();
    }

#pragma unroll
    for (int mi = 0; mi < 2; mi++) {
#pragma unroll
        for (int nt = 0; nt < 8; nt++) {
            int m = m0 + wr * 32 + mi * 16 + (lane >> 2);
            int ncol = n0 + wc * 64 + nt * 8 + 2 * (lane & 3);
            if (ncol < V_) {
                float* p0 = C + (size_t)m * V_ + ncol;
                float* p1 = C + (size_t)(m + 8) * V_ + ncol;
                *(float2*)p0 = make_float2(acc[mi * 8 + nt][0], acc[mi * 8 + nt][1]);
                *(float2*)p1 = make_float2(acc[mi * 8 + nt][2], acc[mi * 8 + nt][3]);
            }
        }
    }
#endif
}

// ---------------------------------------------------------------------------
// Host orchestration
// ---------------------------------------------------------------------------
extern "C" void kernel_launch(void* const* d_in, const int* in_sizes, int n_in,
                              void* d_out, int out_size) {
    const float* enc_out = (const float*)d_in[0];
    const float* embed_w = (const float*)d_in[1];
    const float* enc_w   = (const float*)d_in[2];
    const float* enc_b   = (const float*)d_in[3];
    const float* qkv_w   = (const float*)d_in[4];
    const float* qkv_b   = (const float*)d_in[5];
    const float* o_w     = (const float*)d_in[6];
    const float* o_b     = (const float*)d_in[7];
    const float* ln1_s   = (const float*)d_in[8];
    const float* ln1_b   = (const float*)d_in[9];
    const float* ff1_w   = (const float*)d_in[10];
    const float* ff1_b   = (const float*)d_in[11];
    const float* ff2_w   = (const float*)d_in[12];
    const float* ff2_b   = (const float*)d_in[13];
    const float* ln2_s   = (const float*)d_in[14];
    const float* ln2_b   = (const float*)d_in[15];
    const float* out_w   = (const float*)d_in[16];
    const int*   tgt_pad = (const int*)d_in[17];
    const int*   tgt_len = (const int*)d_in[18];
    const int*   sos     = (const int*)d_in[19];

    float *x, *qkv, *tmp, *encp;
    cudaGetSymbolAddress((void**)&x, g_x);
    cudaGetSymbolAddress((void**)&qkv, g_qkv);
    cudaGetSymbolAddress((void**)&tmp, g_tmp);
    cudaGetSymbolAddress((void**)&encp, g_encp);

    __nv_bfloat16 *xh, *xl, *ath, *atl, *fh, *fl;
    cudaGetSymbolAddress((void**)&xh, g_xh);
    cudaGetSymbolAddress((void**)&xl, g_xl);
    cudaGetSymbolAddress((void**)&ath, g_ath);
    cudaGetSymbolAddress((void**)&atl, g_atl);
    cudaGetSymbolAddress((void**)&fh, g_fh);
    cudaGetSymbolAddress((void**)&fl, g_fl);

    __nv_bfloat16 *qkvwh, *qkvwl, *owh, *owl, *f1h, *f1l, *f2h, *f2l, *ewh, *ewl, *exh, *exl;
    cudaGetSymbolAddress((void**)&qkvwh, g_qkvwh);
    cudaGetSymbolAddress((void**)&qkvwl, g_qkvwl);
    cudaGetSymbolAddress((void**)&owh, g_owh);
    cudaGetSymbolAddress((void**)&owl, g_owl);
    cudaGetSymbolAddress((void**)&f1h, g_f1h);
    cudaGetSymbolAddress((void**)&f1l, g_f1l);
    cudaGetSymbolAddress((void**)&f2h, g_f2h);
    cudaGetSymbolAddress((void**)&f2l, g_f2l);
    cudaGetSymbolAddress((void**)&ewh, g_ewh);
    cudaGetSymbolAddress((void**)&ewl, g_ewl);
    cudaGetSymbolAddress((void**)&exh, g_exh);
    cudaGetSymbolAddress((void**)&exl, g_exl);

    __nv_bfloat16 *Ah, *Al, *Wh, *Wl;
    cudaGetSymbolAddress((void**)&Ah, g_Ah);
    cudaGetSymbolAddress((void**)&Al, g_Al);
    cudaGetSymbolAddress((void**)&Wh, g_Wh);
    cudaGetSymbolAddress((void**)&Wl, g_Wl);

    static bool attr_done = false;
    if (!attr_done) {
        cudaFuncSetAttribute(joiner_tc_kernel,
                             cudaFuncAttributeMaxDynamicSharedMemorySize, JT_SMEM);
        cudaFuncSetAttribute(gemm_tc,
                             cudaFuncAttributeMaxDynamicSharedMemorySize, JT_SMEM);
        attr_done = true;
    }

    // ---- fused weight splits (1 launch) + padded out_w split ----
    {
        SplitJobs jobs;
        int c0 = L_ * 3 * D_ * D_ / 4;
        int c1 = L_ * D_ * D_ / 4;
        int c2 = L_ * FF_ * D_ / 4;
        int c3 = L_ * D_ * FF_ / 4;
        int c4 = D_ * D_ / 4;
        int c5 = TI_ * NB_ * D_ / 4;
        jobs.src[0] = qkv_w;  jobs.h[0] = qkvwh; jobs.l[0] = qkvwl; jobs.end[0] = c0;
        jobs.src[1] = o_w;    jobs.h[1] = owh;   jobs.l[1] = owl;   jobs.end[1] = jobs.end[0] + c1;
        jobs.src[2] = ff1_w;  jobs.h[2] = f1h;   jobs.l[2] = f1l;   jobs.end[2] = jobs.end[1] + c2;
        jobs.src[3] = ff2_w;  jobs.h[3] = f2h;   jobs.l[3] = f2l;   jobs.end[3] = jobs.end[2] + c3;
        jobs.src[4] = enc_w;  jobs.h[4] = ewh;   jobs.l[4] = ewl;   jobs.end[4] = jobs.end[3] + c4;
        jobs.src[5] = enc_out;jobs.h[5] = exh;   jobs.l[5] = exl;   jobs.end[5] = jobs.end[4] + c5;
        int total = jobs.end[5];
        split_all_kernel<<<(total + 255) / 256, 256>>>(jobs, total);
        w_split_kernel<<<VP_, 128>>>(out_w, Wh, Wl);
    }

    // enc projection: encp[1024x512] = enc_out @ enc_w^T + b
    gemm_tc<<<dim3(D_ / 128, (TI_ * NB_) / 128, 1), 256, JT_SMEM>>>(
        exh, exl, ewh, ewl, enc_b, encp, nullptr, nullptr,
        TI_ * NB_, D_, D_, 8, 0);

    // embedding + positions
    embed_kernel<<<TOK_, 128>>>(embed_w, tgt_pad, sos, x, xh, xl);

    // 6 post-norm transformer layers
    for (int l = 0; l < L_; l++) {
        gemm_tc<<<dim3(3 * D_ / 128, 3, QKV_SPLIT), 256, JT_SMEM>>>(
            xh, xl, qkvwh + (size_t)l * 3 * D_ * D_, qkvwl + (size_t)l * 3 * D_ * D_,
            qkv_b + (size_t)l * 3 * D_, qkv, nullptr, nullptr,
            TOK_, 3 * D_, D_, 8 / QKV_SPLIT, 0);
        attention_kernel<<<NB_ * H_, 128>>>(qkv, tgt_len, ath, atl);
        gemm_tc<<<dim3(D_ / 128, 3, O_SPLIT), 256, JT_SMEM>>>(
            ath, atl, owh + (size_t)l * D_ * D_, owl + (size_t)l * D_ * D_,
            o_b + (size_t)l * D_, tmp, nullptr, nullptr,
            TOK_, D_, D_, 8 / O_SPLIT, 0);
        add_ln_kernel<<<TOK_, 128>>>(x, tmp, O_SPLIT,
            ln1_s + (size_t)l * D_, ln1_b + (size_t)l * D_, xh, xl);
        gemm_tc<<<dim3(FF_ / 128, 3, 1), 256, JT_SMEM>>>(
            xh, xl, f1h + (size_t)l * FF_ * D_, f1l + (size_t)l * FF_ * D_,
            ff1_b + (size_t)l * FF_, nullptr, fh, fl,
            TOK_, FF_, D_, 8, 1);
        gemm_tc<<<dim3(D_ / 128, 3, FF2_SPLIT), 256, JT_SMEM>>>(
            fh, fl, f2h + (size_t)l * D_ * FF_, f2l + (size_t)l * D_ * FF_,
            ff2_b + (size_t)l * D_, tmp, nullptr, nullptr,
            TOK_, D_, FF_, FF_ / 64 / FF2_SPLIT, 0);
        add_ln_kernel<<<TOK_, 128>>>(x, tmp, FF2_SPLIT,
            ln2_s + (size_t)l * D_, ln2_b + (size_t)l * D_, xh, xl);
    }

    // joiner
    joiner_a_split_kernel<<<MJ_, 128>>>(encp, x, Ah, Al);
    joiner_tc_kernel<<<dim3(VP_ / 128, MJ_ / 128), 256, JT_SMEM>>>(
        Ah, Al, Wh, Wl, (float*)d_out);
}

// round 7
// speedup vs baseline: 5.9832x; 1.0569x over previous
#include <cuda_runtime.h>
#include <cuda_bf16.h>
#include <cuda_fp16.h>
#include <math.h>
#include <stdint.h>

// ---------------------------------------------------------------------------
// Arch-feature gate (tcgen05 only legal on sm_10Xa feature targets)
// ---------------------------------------------------------------------------
#if defined(__CUDA_ARCH_FEAT_SM103_ALL) || defined(__CUDA_ARCH_FEAT_SM100_ALL) || defined(__CUDA_ARCH_FEAT_SM101_ALL)
#define USE_TCGEN05 1
#else
#define USE_TCGEN05 0
#endif

// ---------------------------------------------------------------------------
// Problem constants
// ---------------------------------------------------------------------------
#define TI_   128
#define NB_   8
#define TO_   32
#define TS_   33
#define D_    512
#define H_    8
#define HD_   64
#define FF_   2048
#define V_    2000
#define VP_   2048
#define L_    6
#define TOK_  (TS_ * NB_)          // 264
#define MJ_   (NB_ * TI_ * TS_)    // 33792
#define FF2_SPLIT 8
#define QKV_SPLIT 4
#define O_SPLIT   4

// ---------------------------------------------------------------------------
// Scratch (static __device__ arrays)
// ---------------------------------------------------------------------------
__device__ float g_x[TOK_ * D_];
__device__ float g_qkv[QKV_SPLIT * TOK_ * 3 * D_];
__device__ float g_tmp[FF2_SPLIT * TOK_ * D_];
__device__ float g_encp[TI_ * NB_ * D_];

__device__ __nv_bfloat16 g_xh[TOK_ * D_],  g_xl[TOK_ * D_];
__device__ __nv_bfloat16 g_ath[TOK_ * D_], g_atl[TOK_ * D_];
__device__ __nv_bfloat16 g_fh[TOK_ * FF_], g_fl[TOK_ * FF_];

__device__ __nv_bfloat16 g_qkvwh[(size_t)L_ * 3 * D_ * D_], g_qkvwl[(size_t)L_ * 3 * D_ * D_];
__device__ __nv_bfloat16 g_owh[(size_t)L_ * D_ * D_],       g_owl[(size_t)L_ * D_ * D_];
__device__ __nv_bfloat16 g_f1h[(size_t)L_ * FF_ * D_],      g_f1l[(size_t)L_ * FF_ * D_];
__device__ __nv_bfloat16 g_f2h[(size_t)L_ * D_ * FF_],      g_f2l[(size_t)L_ * D_ * FF_];
__device__ __nv_bfloat16 g_ewh[D_ * D_],                    g_ewl[D_ * D_];
__device__ __nv_bfloat16 g_exh[TI_ * NB_ * D_],             g_exl[TI_ * NB_ * D_];

// joiner operands: A single fp16, W fp16 hi/lo (2-term scheme)
__device__ __half g_Aj[(size_t)MJ_ * D_];
__device__ __half g_Wjh[(size_t)VP_ * D_], g_Wjl[(size_t)VP_ * D_];

// ---------------------------------------------------------------------------
// PTX helpers
// ---------------------------------------------------------------------------
__device__ __forceinline__ uint32_t elect_one_pred() {
    uint32_t pred;
    asm volatile(
        "{\n\t.reg .pred p;\n\telect.sync _|p, 0xFFFFFFFF;\n\t"
        "selp.b32 %0, 1, 0, p;\n\t}"
        : "=r"(pred));
    return pred;
}
__device__ __forceinline__ uint32_t smem_to_u32(const void* smem_ptr) {
    uint32_t addr;
    asm("{ .reg .u64 tmp; cvta.to.shared.u64 tmp, %1; cvt.u32.u64 %0, tmp; }"
        : "=r"(addr) : "l"(smem_ptr));
    return addr;
}
__device__ __forceinline__ uint32_t sw_off(uint32_t bo) {
    return bo ^ ((bo >> 3) & 0x70);
}
// cp.async 16B with zero-fill when src invalid
__device__ __forceinline__ void cp_async16(uint32_t saddr, const void* gptr, int valid) {
    asm volatile("cp.async.cg.shared.global [%0], [%1], 16, %2;"
        :: "r"(saddr), "l"(gptr), "r"(valid ? 16 : 0));
}
__device__ __forceinline__ void cp_async_commit() {
    asm volatile("cp.async.commit_group;");
}
template <int N>
__device__ __forceinline__ void cp_async_wait() {
    asm volatile("cp.async.wait_group %0;" :: "n"(N) : "memory");
}
__device__ __forceinline__ void cp_async_commit_wait() {
    asm volatile("cp.async.commit_group;");
    asm volatile("cp.async.wait_group 0;" ::: "memory");
}

static constexpr uint64_t SMEM_DESC_BASE_SW128 =
    (uint64_t(2)  << 61) | (uint64_t(1) << 46) | (uint64_t(64) << 32) | (uint64_t(1) << 16);
#define MAKE_SMEM_DESC(base_addr) \
    (SMEM_DESC_BASE_SW128 | ((uint64_t)((base_addr) >> 4) & 0x3FFF))

#if USE_TCGEN05
#define TCGEN05_ALLOC(smem_result_addr, nCols) \
    asm volatile("tcgen05.alloc.cta_group::1.sync.aligned.shared::cta.b32 [%0], %1;" \
        :: "r"((uint32_t)(smem_result_addr)), "r"((uint32_t)(nCols)) : "memory")
#define TCGEN05_DEALLOC(tmem_addr, nCols) \
    asm volatile("tcgen05.dealloc.cta_group::1.sync.aligned.b32 %0, %1;" \
        :: "r"(tmem_addr), "r"((uint32_t)(nCols)))
#define TCGEN05_RELINQUISH_ALLOC_PERMIT() \
    asm volatile("tcgen05.relinquish_alloc_permit.cta_group::1.sync.aligned;")
#define TCGEN05_COMMIT(mbar_smem_addr) \
    asm volatile("tcgen05.commit.cta_group::1.mbarrier::arrive::one.shared::cluster.b64 [%0];" \
        :: "r"((uint32_t)(mbar_smem_addr)) : "memory")
#define TCGEN05_WAIT_LD() \
    asm volatile("tcgen05.wait::ld.sync.aligned;" ::: "memory")
#define TCGEN05_FENCE_AFTER() \
    asm volatile("tcgen05.fence::after_thread_sync;" ::: "memory")
#define FENCE_PROXY_ASYNC_SHARED_CTA() \
    asm volatile("fence.proxy.async.shared::cta;" ::: "memory")
#define MBARRIER_INIT(mbar_smem_addr, count) \
    asm volatile("mbarrier.init.shared.b64 [%0], %1;" \
        :: "r"((uint32_t)(mbar_smem_addr)), "r"((uint32_t)(count)) : "memory")
#define MBARRIER_INVAL(mbar_smem_addr) \
    asm volatile("mbarrier.inval.shared.b64 [%0];" :: "r"((uint32_t)(mbar_smem_addr)) : "memory")
#define MBARRIER_WAIT_PARITY(mbar_smem_addr, phase_parity) do { \
    uint32_t _mbar = (uint32_t)(mbar_smem_addr); \
    uint32_t _parity = (uint32_t)(phase_parity); \
    uint32_t _done; \
    asm volatile( \
        "{\n\t.reg .pred p;\n\t" \
        "mbarrier.try_wait.parity.acquire.cta.shared::cta.b64 p, [%1], %2;\n\t" \
        "selp.b32 %0, 1, 0, p;\n\t}" \
        : "=r"(_done) : "r"(_mbar), "r"(_parity) : "memory"); \
    if (!_done) { \
        asm volatile( \
            "{\n\t.reg .pred P1;\n\t" \
            "WAIT_LOOP_%=:\n\t" \
            "mbarrier.try_wait.parity.acquire.cta.shared::cta.b64 P1, [%0], %1, 0x989680;\n\t" \
            "@P1 bra.uni WAIT_DONE_%=;\n\t" \
            "bra.uni WAIT_LOOP_%=;\n\t" \
            "WAIT_DONE_%=:\n\t}" \
            :: "r"(_mbar), "r"(_parity) : "memory"); \
    } \
} while(0)
#define TCGEN05_LD_32X32B_X32(r, tmem_addr) \
    asm volatile( \
        "tcgen05.ld.sync.aligned.32x32b.x32.b32 " \
        "{%0, %1, %2, %3, %4, %5, %6, %7, " \
        " %8, %9, %10, %11, %12, %13, %14, %15, " \
        " %16, %17, %18, %19, %20, %21, %22, %23, " \
        " %24, %25, %26, %27, %28, %29, %30, %31}, [%32];" \
        : "=r"((r)[0]),  "=r"((r)[1]),  "=r"((r)[2]),  "=r"((r)[3]), \
          "=r"((r)[4]),  "=r"((r)[5]),  "=r"((r)[6]),  "=r"((r)[7]), \
          "=r"((r)[8]),  "=r"((r)[9]),  "=r"((r)[10]), "=r"((r)[11]), \
          "=r"((r)[12]), "=r"((r)[13]), "=r"((r)[14]), "=r"((r)[15]), \
          "=r"((r)[16]), "=r"((r)[17]), "=r"((r)[18]), "=r"((r)[19]), \
          "=r"((r)[20]), "=r"((r)[21]), "=r"((r)[22]), "=r"((r)[23]), \
          "=r"((r)[24]), "=r"((r)[25]), "=r"((r)[26]), "=r"((r)[27]), \
          "=r"((r)[28]), "=r"((r)[29]), "=r"((r)[30]), "=r"((r)[31]) \
        : "r"(tmem_addr))

__device__ __forceinline__ void mma_f16_ss_cg1(uint32_t d_tmem, uint64_t a_desc,
                                               uint64_t b_desc, uint32_t idesc,
                                               uint32_t enable) {
    asm volatile(
        "{\n\t.reg .pred p;\n\t"
        "setp.ne.u32 p, %4, 0;\n\t"
        "tcgen05.mma.cta_group::1.kind::f16 [%0], %1, %2, %3, {%5, %5, %5, %5}, p;\n\t}"
        :: "r"(d_tmem), "l"(a_desc), "l"(b_desc), "r"(idesc), "r"(enable), "r"(0u)
        : "memory");
}
#define JOINER_IDESC_F16 0x8200010u   // dtype F32, atype/btype FP16, M=N=128
#endif // USE_TCGEN05

// ---------------------------------------------------------------------------
// mma.sync helpers (base target)
// ---------------------------------------------------------------------------
__device__ __forceinline__ void ldmatrix_x4(uint32_t* r, uint32_t addr) {
    asm volatile("ldmatrix.sync.aligned.m8n8.x4.shared.b16 {%0,%1,%2,%3}, [%4];"
        : "=r"(r[0]), "=r"(r[1]), "=r"(r[2]), "=r"(r[3]) : "r"(addr));
}
__device__ __forceinline__ void mma16816(float* d, const uint32_t* a,
                                         uint32_t b0, uint32_t b1) {
    asm volatile(
        "mma.sync.aligned.m16n8k16.row.col.f32.bf16.bf16.f32 "
        "{%0,%1,%2,%3}, {%4,%5,%6,%7}, {%8,%9}, {%0,%1,%2,%3};"
        : "+f"(d[0]), "+f"(d[1]), "+f"(d[2]), "+f"(d[3])
        : "r"(a[0]), "r"(a[1]), "r"(a[2]), "r"(a[3]), "r"(b0), "r"(b1));
}
__device__ __forceinline__ void mma16816_f16(float* d, const uint32_t* a,
                                             uint32_t b0, uint32_t b1) {
    asm volatile(
        "mma.sync.aligned.m16n8k16.row.col.f32.f16.f16.f32 "
        "{%0,%1,%2,%3}, {%4,%5,%6,%7}, {%8,%9}, {%0,%1,%2,%3};"
        : "+f"(d[0]), "+f"(d[1]), "+f"(d[2]), "+f"(d[3])
        : "r"(a[0]), "r"(a[1]), "r"(a[2]), "r"(a[3]), "r"(b0), "r"(b1));
}

__device__ __forceinline__ void split_hl(float v, __nv_bfloat16& h, __nv_bfloat16& l) {
    h = __float2bfloat16(v);
    l = __float2bfloat16(v - __bfloat162float(h));
}
__device__ __forceinline__ void split_hl_f16(float v, __half& h, __half& l) {
    h = __float2half(v);
    l = __float2half(v - __half2float(h));
}

// ---------------------------------------------------------------------------
// Fused weight split (bf16 hi/lo for the layer chain)
// ---------------------------------------------------------------------------
#define NSPLITJOBS 6
struct SplitJobs {
    const float* src[NSPLITJOBS];
    __nv_bfloat16* h[NSPLITJOBS];
    __nv_bfloat16* l[NSPLITJOBS];
    int end[NSPLITJOBS];   // prefix-sum of vec4 counts
};

__global__ void split_all_kernel(SplitJobs jobs, int total) {
    int i = blockIdx.x * blockDim.x + threadIdx.x;
    if (i >= total) return;
    int j = 0;
#pragma unroll
    for (int k = 0; k < NSPLITJOBS - 1; k++) j += (i >= jobs.end[k]);
    int base = (j == 0) ? 0 : jobs.end[j - 1];
    int li = i - base;
    float4 w = ((const float4*)jobs.src[j])[li];
    __nv_bfloat16 h0, h1, h2, h3, l0, l1, l2, l3;
    split_hl(w.x, h0, l0); split_hl(w.y, h1, l1);
    split_hl(w.z, h2, l2); split_hl(w.w, h3, l3);
    ((__nv_bfloat162*)jobs.h[j])[2 * li]     = __nv_bfloat162(h0, h1);
    ((__nv_bfloat162*)jobs.h[j])[2 * li + 1] = __nv_bfloat162(h2, h3);
    ((__nv_bfloat162*)jobs.l[j])[2 * li]     = __nv_bfloat162(l0, l1);
    ((__nv_bfloat162*)jobs.l[j])[2 * li + 1] = __nv_bfloat162(l2, l3);
}

// out_w split to fp16 hi/lo, padded to VP_ rows
__global__ void w_split_kernel(const float* __restrict__ W,
                               __half* __restrict__ Wh,
                               __half* __restrict__ Wl) {
    int r = blockIdx.x;
    int tid = threadIdx.x;
    size_t base = (size_t)r * D_ + tid * 4;
    if (r < V_) {
        const float4 w = ((const float4*)(W + (size_t)r * D_))[tid];
        __half h0, h1, h2, h3, l0, l1, l2, l3;
        split_hl_f16(w.x, h0, l0); split_hl_f16(w.y, h1, l1);
        split_hl_f16(w.z, h2, l2); split_hl_f16(w.w, h3, l3);
        ((__half2*)(Wh + base))[0] = __half2(h0, h1);
        ((__half2*)(Wh + base))[1] = __half2(h2, h3);
        ((__half2*)(Wl + base))[0] = __half2(l0, l1);
        ((__half2*)(Wl + base))[1] = __half2(l2, l3);
    } else {
        __half2 z = __half2(__float2half(0.f), __float2half(0.f));
        ((__half2*)(Wh + base))[0] = z;
        ((__half2*)(Wh + base))[1] = z;
        ((__half2*)(Wl + base))[0] = z;
        ((__half2*)(Wl + base))[1] = z;
    }
}

// ---------------------------------------------------------------------------
// Embedding + positions -> x fp32 + bf16 hi/lo  (fp32 transcendentals)
// ---------------------------------------------------------------------------
__global__ void embed_kernel(const float* __restrict__ embed,
                             const int* __restrict__ tgt_pad,
                             const int* __restrict__ sos,
                             float* __restrict__ x,
                             __nv_bfloat16* __restrict__ xh,
                             __nv_bfloat16* __restrict__ xl) {
    int r = blockIdx.x;
    int t = r >> 3, n = r & 7;
    int tok = (t == 0) ? sos[0] : tgt_pad[n * TO_ + (t - 1)];
    const float* e = embed + (size_t)tok * D_;
    const float sc = sqrtf(512.0f);
    int tid = threadIdx.x;
#pragma unroll
    for (int i = 0; i < 2; i++) {
        int d = tid * 4 + i * 2;
        float ddiv = expf((float)d * (-9.210340371976184f / 512.0f));
        float ang = (float)t * ddiv;
        float sv, cv;
        sincosf(ang, &sv, &cv);
        size_t idx = (size_t)r * D_ + d;
        float v0 = e[d] * sc + sv;
        float v1 = e[d + 1] * sc + cv;
        x[idx] = v0; x[idx + 1] = v1;
        __nv_bfloat16 h0, l0, h1, l1;
        split_hl(v0, h0, l0); split_hl(v1, h1, l1);
        xh[idx] = h0; xh[idx + 1] = h1;
        xl[idx] = l0; xl[idx + 1] = l1;
    }
}

// ---------------------------------------------------------------------------
// Tile loaders (16-bit elems, 128 rows; SW128 rows of 128B = 64 elements)
// ---------------------------------------------------------------------------
__device__ __forceinline__ void tc_load_tile_async(const __nv_bfloat16* __restrict__ src,
                                                   int row0, int maxrow, int koff,
                                                   int kstride, uint32_t sm, int tid) {
#pragma unroll
    for (int p = 0; p < 4; p++) {
        int idx = p * 256 + tid;
        int row = idx >> 3, seg = idx & 7;
        int gr = row0 + row;
        uint32_t bo = (uint32_t)(row * 128 + seg * 16);
        cp_async16(sm + sw_off(bo),
                   src + (size_t)gr * kstride + koff + seg * 8,
                   gr < maxrow);
    }
}
// half chunk (32 elements = 64B): p selects which 64B half of the row buffer
__device__ __forceinline__ void tc_load_half_async(const __nv_bfloat16* __restrict__ src,
                                                   int row0, int maxrow, int kelem,
                                                   int kstride, uint32_t sm, int tid, int p) {
#pragma unroll
    for (int q = 0; q < 2; q++) {
        int idx = q * 256 + tid;
        int row = idx >> 2, seg = idx & 3;
        int gr = row0 + row;
        uint32_t bo = (uint32_t)(row * 128 + p * 64 + seg * 16);
        cp_async16(sm + sw_off(bo),
                   src + (size_t)gr * kstride + kelem + seg * 8,
                   gr < maxrow);
    }
}

// layer-chain GEMM smem layout (bf16 3-term)
#define JT_BUF      16384
#define JT_SM_AH    1024
#define JT_SM_AL    (JT_SM_AH + JT_BUF)
#define JT_SM_WH    (JT_SM_AL + JT_BUF)
#define JT_SM_WL    (JT_SM_WH + JT_BUF)
#define JT_SMEM     (JT_SM_WL + JT_BUF)      // 66560

// joiner smem layout (fp16 2-term: A, Wh, Wl)
#define JJ_SM_A     1024
#define JJ_SM_WH    (JJ_SM_A + JT_BUF)
#define JJ_SM_WL    (JJ_SM_WH + JT_BUF)
#define JJ_SMEM     (JJ_SM_WL + JT_BUF)      // 50176

__device__ __forceinline__ void load_half4(const __nv_bfloat16* Ah, const __nv_bfloat16* Al,
                                           const __nv_bfloat16* Wh, const __nv_bfloat16* Wl,
                                           int m0, int M, int n0, int N,
                                           int kelem, int kstride,
                                           uint32_t sbase, int tid, int p) {
    tc_load_half_async(Ah, m0, M, kelem, kstride, sbase + JT_SM_AH, tid, p);
    tc_load_half_async(Al, m0, M, kelem, kstride, sbase + JT_SM_AL, tid, p);
    tc_load_half_async(Wh, n0, N, kelem, kstride, sbase + JT_SM_WH, tid, p);
    tc_load_half_async(Wl, n0, N, kelem, kstride, sbase + JT_SM_WL, tid, p);
}
__device__ __forceinline__ void load_half3_j(const __half* A, const __half* Wh,
                                             const __half* Wl,
                                             int m0, int n0, int kelem,
                                             uint32_t sbase, int tid, int p) {
    tc_load_half_async((const __nv_bfloat16*)A, m0, MJ_, kelem, D_, sbase + JJ_SM_A, tid, p);
    tc_load_half_async((const __nv_bfloat16*)Wh, n0, VP_, kelem, D_, sbase + JJ_SM_WH, tid, p);
    tc_load_half_async((const __nv_bfloat16*)Wl, n0, VP_, kelem, D_, sbase + JJ_SM_WL, tid, p);
}

// ---------------------------------------------------------------------------
// mma.sync mainloops over ONE 32-element half (s = 2p, 2p+1)
// ---------------------------------------------------------------------------
__device__ __forceinline__ void mma_mainloop_half(uint32_t sbase, int wr, int wc,
                                                  int lane, float acc[16][4], int p) {
    const int aoffs[3] = {JT_SM_AH, JT_SM_AH, JT_SM_AL};
    const int boffs[3] = {JT_SM_WH, JT_SM_WL, JT_SM_WH};
    const int bt = lane >> 3, br_ = lane & 7;
#pragma unroll
    for (int si = 0; si < 2; si++) {
        const int s = 2 * p + si;
#pragma unroll
        for (int tm = 0; tm < 3; tm++) {
            uint32_t afrag[2][4];
#pragma unroll
            for (int mi = 0; mi < 2; mi++) {
                uint32_t bo = (uint32_t)((wr * 32 + mi * 16 + (lane & 15)) * 128
                                         + s * 32 + (lane >> 4) * 16);
                ldmatrix_x4(afrag[mi], sbase + aoffs[tm] + sw_off(bo));
            }
#pragma unroll
            for (int g = 0; g < 4; g++) {
                uint32_t bo = (uint32_t)((wc * 64 + g * 16 + (bt >> 1) * 8 + br_) * 128
                                         + s * 32 + (bt & 1) * 16);
                uint32_t bfr[4];
                ldmatrix_x4(bfr, sbase + boffs[tm] + sw_off(bo));
                mma16816(acc[2 * g],     afrag[0], bfr[0], bfr[1]);
                mma16816(acc[8 + 2 * g], afrag[1], bfr[0], bfr[1]);
                mma16816(acc[2 * g + 1],     afrag[0], bfr[2], bfr[3]);
                mma16816(acc[8 + 2 * g + 1], afrag[1], bfr[2], bfr[3]);
            }
        }
    }
}
// joiner fp16 2-term: (A,Wh), (A,Wl); A fragment loaded once per s
__device__ __forceinline__ void mma_mainloop_half_j(uint32_t sbase, int wr, int wc,
                                                    int lane, float acc[16][4], int p) {
    const int boffs[2] = {JJ_SM_WH, JJ_SM_WL};
    const int bt = lane >> 3, br_ = lane & 7;
#pragma unroll
    for (int si = 0; si < 2; si++) {
        const int s = 2 * p + si;
        uint32_t afrag[2][4];
#pragma unroll
        for (int mi = 0; mi < 2; mi++) {
            uint32_t bo = (uint32_t)((wr * 32 + mi * 16 + (lane & 15)) * 128
                                     + s * 32 + (lane >> 4) * 16);
            ldmatrix_x4(afrag[mi], sbase + JJ_SM_A + sw_off(bo));
        }
#pragma unroll
        for (int tm = 0; tm < 2; tm++) {
#pragma unroll
            for (int g = 0; g < 4; g++) {
                uint32_t bo = (uint32_t)((wc * 64 + g * 16 + (bt >> 1) * 8 + br_) * 128
                                         + s * 32 + (bt & 1) * 16);
                uint32_t bfr[4];
                ldmatrix_x4(bfr, sbase + boffs[tm] + sw_off(bo));
                mma16816_f16(acc[2 * g],     afrag[0], bfr[0], bfr[1]);
                mma16816_f16(acc[8 + 2 * g], afrag[1], bfr[0], bfr[1]);
                mma16816_f16(acc[2 * g + 1],     afrag[0], bfr[2], bfr[3]);
                mma16816_f16(acc[8 + 2 * g + 1], afrag[1], bfr[2], bfr[3]);
            }
        }
    }
}

// ---------------------------------------------------------------------------
// Layer-chain tensor GEMM (3-term bf16 hi/lo), half-buffer pipelined
// ---------------------------------------------------------------------------
__global__ void __launch_bounds__(256) gemm_tc(
    const __nv_bfloat16* __restrict__ Ah, const __nv_bfloat16* __restrict__ Al,
    const __nv_bfloat16* __restrict__ Wh, const __nv_bfloat16* __restrict__ Wl,
    const float* __restrict__ bias,
    float* __restrict__ C,
    __nv_bfloat16* __restrict__ Ch, __nv_bfloat16* __restrict__ Cl,
    int M, int N, int kstride, int chunks, int relu) {
    extern __shared__ char smem[];
    const uint32_t sbase = smem_to_u32(smem);
    const int tid = threadIdx.x;
    const int n0 = blockIdx.x * 128;
    const int m0 = blockIdx.y * 128;
    const int z  = blockIdx.z;
    const int koff0 = z * chunks * 64;
    if (C) C += (size_t)z * M * N;

    const int w = tid >> 5, lane = tid & 31;
    const int wr = w >> 1, wc = w & 1;

    float acc[16][4];
#pragma unroll
    for (int i = 0; i < 16; i++)
#pragma unroll
        for (int j = 0; j < 4; j++) acc[i][j] = 0.f;

    const int nhalf = chunks * 2;
    load_half4(Ah, Al, Wh, Wl, m0, M, n0, N, koff0, kstride, sbase, tid, 0);
    cp_async_commit();
    for (int c = 0; c < nhalf; c++) {
        if (c + 1 < nhalf) {
            load_half4(Ah, Al, Wh, Wl, m0, M, n0, N,
                       koff0 + (c + 1) * 32, kstride, sbase, tid, (c + 1) & 1);
            cp_async_commit();
            cp_async_wait<1>();
        } else {
            cp_async_wait<0>();
        }
        __syncthreads();
        mma_mainloop_half(sbase, wr, wc, lane, acc, c & 1);
        __syncthreads();
    }

    const bool addb = (bias != nullptr) && (z == 0);
#pragma unroll
    for (int mi = 0; mi < 2; mi++) {
#pragma unroll
        for (int nt = 0; nt < 8; nt++) {
            int m = m0 + wr * 32 + mi * 16 + (lane >> 2);
            int ncol = n0 + wc * 64 + nt * 8 + 2 * (lane & 3);
            float b0v = addb ? bias[ncol] : 0.f;
            float b1v = addb ? bias[ncol + 1] : 0.f;
            float v0 = acc[mi * 8 + nt][0] + b0v;
            float v1 = acc[mi * 8 + nt][1] + b1v;
            float v2 = acc[mi * 8 + nt][2] + b0v;
            float v3 = acc[mi * 8 + nt][3] + b1v;
            if (relu) {
                v0 = fmaxf(v0, 0.f); v1 = fmaxf(v1, 0.f);
                v2 = fmaxf(v2, 0.f); v3 = fmaxf(v3, 0.f);
            }
            if (m < M) {
                size_t o = (size_t)m * N + ncol;
                if (C) *(float2*)(C + o) = make_float2(v0, v1);
                if (Ch) {
                    __nv_bfloat16 h0, h1, l0, l1;
                    split_hl(v0, h0, l0); split_hl(v1, h1, l1);
                    *(__nv_bfloat162*)(Ch + o) = __nv_bfloat162(h0, h1);
                    *(__nv_bfloat162*)(Cl + o) = __nv_bfloat162(l0, l1);
                }
            }
            if (m + 8 < M) {
                size_t o = (size_t)(m + 8) * N + ncol;
                if (C) *(float2*)(C + o) = make_float2(v2, v3);
                if (Ch) {
                    __nv_bfloat16 h0, h1, l0, l1;
                    split_hl(v2, h0, l0); split_hl(v3, h1, l1);
                    *(__nv_bfloat162*)(Ch + o) = __nv_bfloat162(h0, h1);
                    *(__nv_bfloat162*)(Cl + o) = __nv_bfloat162(l0, l1);
                }
            }
        }
    }
}

// ---------------------------------------------------------------------------
// Attention: one block per (n,h); sums QKV_SPLIT k-split slices of qkv.
// ---------------------------------------------------------------------------
__global__ void attention_kernel(const float* __restrict__ qkv,
                                 const int* __restrict__ tgt_len,
                                 __nv_bfloat16* __restrict__ oh,
                                 __nv_bfloat16* __restrict__ ol) {
    int n = blockIdx.x >> 3, h = blockIdx.x & 7;
    __shared__ float qs[TS_][HD_];
    __shared__ float ks[TS_][HD_];
    __shared__ float vs[TS_][HD_];
    __shared__ float sc[TS_][TS_ + 1];
    int tid = threadIdx.x;
    int len = tgt_len[n]; if (len < 1) len = 1;

    for (int e = tid; e < TS_ * HD_; e += 128) {
        int t = e >> 6, d = e & 63;
        size_t off = (size_t)(t * 8 + n) * (3 * D_) + h * 64 + d;
        float q = 0.f, k = 0.f, v = 0.f;
#pragma unroll
        for (int z = 0; z < QKV_SPLIT; z++) {
            const float* b = qkv + (size_t)z * TOK_ * 3 * D_ + off;
            q += b[0]; k += b[512]; v += b[1024];
        }
        qs[t][d] = q; ks[t][d] = k; vs[t][d] = v;
    }
    __syncthreads();

    for (int p = tid; p < TS_ * TS_; p += 128) {
        int tq = p / TS_, tk = p - tq * TS_;
        float s;
        if (tk > tq || tk >= len) {
            s = -1e9f;
        } else {
            s = 0.f;
#pragma unroll 8
            for (int d = 0; d < HD_; d++) s += qs[tq][d] * ks[tk][d];
            s *= 0.125f;
        }
        sc[tq][tk] = s;
    }
    __syncthreads();

    if (tid < TS_) {
        int tq = tid;
        float mx = -1e30f;
        for (int tk = 0; tk < TS_; tk++) mx = fmaxf(mx, sc[tq][tk]);
        float sum = 0.f;
        for (int tk = 0; tk < TS_; tk++) {
            float e = expf(sc[tq][tk] - mx);
            sc[tq][tk] = e;
            sum += e;
        }
        float inv = 1.0f / sum;
        for (int tk = 0; tk < TS_; tk++) sc[tq][tk] *= inv;
    }
    __syncthreads();

    for (int e = tid; e < TS_ * HD_; e += 128) {
        int tq = e >> 6, d = e & 63;
        float s = 0.f;
#pragma unroll 8
        for (int tk = 0; tk < TS_; tk++) s += sc[tq][tk] * vs[tk][d];
        size_t idx = (size_t)(tq * 8 + n) * D_ + h * 64 + d;
        __nv_bfloat16 hv, lv;
        split_hl(s, hv, lv);
        oh[idx] = hv; ol[idx] = lv;
    }
}

// ---------------------------------------------------------------------------
// Residual add (x + sum of nsplit tmp slices) + LN; writes x fp32 + bf16 hi/lo
// ---------------------------------------------------------------------------
__global__ void add_ln_kernel(float* __restrict__ x,
                              const float* __restrict__ y, int nsplit,
                              const float* __restrict__ s,
                              const float* __restrict__ b,
                              __nv_bfloat16* __restrict__ xh,
                              __nv_bfloat16* __restrict__ xl) {
    int row = blockIdx.x, tid = threadIdx.x;
    __shared__ float sh[8];
    const float4 xv = ((const float4*)(x + (size_t)row * D_))[tid];
    float r0 = xv.x, r1 = xv.y, r2 = xv.z, r3 = xv.w;
    for (int z = 0; z < nsplit; z++) {
        const float4 yv = ((const float4*)(y + (size_t)z * TOK_ * D_ + (size_t)row * D_))[tid];
        r0 += yv.x; r1 += yv.y; r2 += yv.z; r3 += yv.w;
    }

    float sum = r0 + r1 + r2 + r3;
    int lane = tid & 31, wp = tid >> 5;
#pragma unroll
    for (int off = 16; off > 0; off >>= 1) sum += __shfl_xor_sync(0xffffffffu, sum, off);
    if (lane == 0) sh[wp] = sum;
    __syncthreads();
    float mean = (sh[0] + sh[1] + sh[2] + sh[3]) * (1.0f / 512.0f);

    float d0 = r0 - mean, d1 = r1 - mean, d2 = r2 - mean, d3 = r3 - mean;
    float sq = d0 * d0 + d1 * d1 + d2 * d2 + d3 * d3;
#pragma unroll
    for (int off = 16; off > 0; off >>= 1) sq += __shfl_xor_sync(0xffffffffu, sq, off);
    if (lane == 0) sh[4 + wp] = sq;
    __syncthreads();
    float var = (sh[4] + sh[5] + sh[6] + sh[7]) * (1.0f / 512.0f);
    float rstd = 1.0f / sqrtf(var + 1e-5f);

    const float4 sv = ((const float4*)s)[tid];
    const float4 bv = ((const float4*)b)[tid];
    float o0 = d0 * rstd * sv.x + bv.x;
    float o1 = d1 * rstd * sv.y + bv.y;
    float o2 = d2 * rstd * sv.z + bv.z;
    float o3 = d3 * rstd * sv.w + bv.w;
    ((float4*)(x + (size_t)row * D_))[tid] = make_float4(o0, o1, o2, o3);

    size_t base = (size_t)row * D_ + tid * 4;
    __nv_bfloat16 h0, h1, h2, h3, l0, l1, l2, l3;
    split_hl(o0, h0, l0); split_hl(o1, h1, l1);
    split_hl(o2, h2, l2); split_hl(o3, h3, l3);
    ((__nv_bfloat162*)(xh + base))[0] = __nv_bfloat162(h0, h1);
    ((__nv_bfloat162*)(xh + base))[1] = __nv_bfloat162(h2, h3);
    ((__nv_bfloat162*)(xl + base))[0] = __nv_bfloat162(l0, l1);
    ((__nv_bfloat162*)(xl + base))[1] = __nv_bfloat162(l2, l3);
}

// ---------------------------------------------------------------------------
// Joiner A materialization -> single fp16
// ---------------------------------------------------------------------------
__global__ void joiner_a_kernel(const float* __restrict__ enc,
                                const float* __restrict__ x,
                                __half* __restrict__ A) {
    int r = blockIdx.x;
    int n = r / (TI_ * TS_);
    int rem = r - n * (TI_ * TS_);
    int i = rem / TS_;
    int t = rem - i * TS_;
    const float4* er = (const float4*)(enc + (size_t)(i * 8 + n) * D_);
    const float4* xr = (const float4*)(x + (size_t)(t * 8 + n) * D_);
    int tid = threadIdx.x;
    float4 e = er[tid], xx = xr[tid];
    __half2 h0 = __half2(__float2half(tanhf(e.x + xx.x)), __float2half(tanhf(e.y + xx.y)));
    __half2 h1 = __half2(__float2half(tanhf(e.z + xx.z)), __float2half(tanhf(e.w + xx.w)));
    size_t base = (size_t)r * D_ + tid * 4;
    ((__half2*)(A + base))[0] = h0;
    ((__half2*)(A + base))[1] = h1;
}

// ---------------------------------------------------------------------------
// Joiner GEMM (tile 128x128, K=512, fp16 2-term) — tcgen05 or mma.sync
// ---------------------------------------------------------------------------
#define JT_CHUNKS   8

__global__ void __launch_bounds__(256) joiner_tc_kernel(
    const __half* __restrict__ A,
    const __half* __restrict__ Wh,
    const __half* __restrict__ Wl,
    float* __restrict__ C) {
    extern __shared__ char smem[];
    const uint32_t sbase = smem_to_u32(smem);
    const int tid = threadIdx.x;
    const int n0 = blockIdx.x * 128;
    const int m0 = blockIdx.y * 128;

#if USE_TCGEN05
    const int wid = tid >> 5, lane = tid & 31;

    if (wid == 0) {
        TCGEN05_ALLOC(sbase, 128);
        TCGEN05_RELINQUISH_ALLOC_PERMIT();
    }
    if (tid == 0) MBARRIER_INIT(sbase + 8, 1);
    __syncthreads();
    uint32_t tmem_base;
    asm volatile("ld.shared.b32 %0, [%1];" : "=r"(tmem_base) : "r"(sbase));

    const uint64_t dA  = MAKE_SMEM_DESC(sbase + JJ_SM_A);
    const uint64_t dWh = MAKE_SMEM_DESC(sbase + JJ_SM_WH);
    const uint64_t dWl = MAKE_SMEM_DESC(sbase + JJ_SM_WL);

    for (int c = 0; c < JT_CHUNKS; c++) {
        if (c > 0) MBARRIER_WAIT_PARITY(sbase + 8, (c - 1) & 1);
        const int koff = c * 64;
        tc_load_tile_async((const __nv_bfloat16*)A, m0, MJ_, koff, D_, sbase + JJ_SM_A, tid);
        tc_load_tile_async((const __nv_bfloat16*)Wh, n0, VP_, koff, D_, sbase + JJ_SM_WH, tid);
        tc_load_tile_async((const __nv_bfloat16*)Wl, n0, VP_, koff, D_, sbase + JJ_SM_WL, tid);
        cp_async_commit_wait();
        __syncthreads();
        if (wid == 0) {
            if (elect_one_pred()) {
                FENCE_PROXY_ASYNC_SHARED_CTA();
#pragma unroll
                for (int k = 0; k < 4; k++)
                    mma_f16_ss_cg1(tmem_base, dA + k * 2, dWh + k * 2,
                                   JOINER_IDESC_F16, (c > 0) || (k > 0));
#pragma unroll
                for (int k = 0; k < 4; k++)
                    mma_f16_ss_cg1(tmem_base, dA + k * 2, dWl + k * 2,
                                   JOINER_IDESC_F16, 1u);
                TCGEN05_COMMIT(sbase + 8);
            }
        }
    }
    MBARRIER_WAIT_PARITY(sbase + 8, (JT_CHUNKS - 1) & 1);
    TCGEN05_FENCE_AFTER();

    {
        const int sub = wid & 3;
        const int halfc = (wid >> 2) * 64;
        float* crow = C + (size_t)(m0 + sub * 32 + lane) * V_;
        const bool full = (n0 + 128) <= V_;
#pragma unroll
        for (int base = halfc; base < halfc + 64; base += 32) {
            uint32_t r[32];
            TCGEN05_LD_32X32B_X32(r, tmem_base + base);
            TCGEN05_WAIT_LD();
            if (full) {
#pragma unroll
                for (int j = 0; j < 32; j += 4) {
                    *(float4*)(crow + n0 + base + j) =
                        make_float4(__uint_as_float(r[j]), __uint_as_float(r[j + 1]),
                                    __uint_as_float(r[j + 2]), __uint_as_float(r[j + 3]));
                }
            } else {
#pragma unroll
                for (int j = 0; j < 32; j++) {
                    int col = n0 + base + j;
                    if (col < V_) crow[col] = __uint_as_float(r[j]);
                }
            }
        }
    }
    __syncthreads();
    if (wid == 0) {
        if (elect_one_pred()) MBARRIER_INVAL(sbase + 8);
        TCGEN05_DEALLOC(tmem_base, 128);
    }

#else  // mma.sync path, fp16 2-term, half-buffer pipeline
    const int w = tid >> 5, lane = tid & 31;
    const int wr = w >> 1, wc = w & 1;

    float acc[16][4];
#pragma unroll
    for (int i = 0; i < 16; i++)
#pragma unroll
        for (int j = 0; j < 4; j++) acc[i][j] = 0.f;

    const int nhalf = JT_CHUNKS * 2;
    load_half3_j(A, Wh, Wl, m0, n0, 0, sbase, tid, 0);
    cp_async_commit();
    for (int c = 0; c < nhalf; c++) {
        if (c + 1 < nhalf) {
            load_half3_j(A, Wh, Wl, m0, n0, (c + 1) * 32, sbase, tid, (c + 1) & 1);
            cp_async_commit();
            cp_async_wait<1>();
        } else {
            cp_async_wait<0>();
        }
        __syncthreads();
        mma_mainloop_half_j(sbase, wr, wc, lane, acc, c & 1);
        __syncthreads();
    }

#pragma unroll
    for (int mi = 0; mi < 2; mi++) {
#pragma unroll
        for (int nt = 0; nt < 8; nt++) {
            int m = m0 + wr * 32 + mi * 16 + (lane >> 2);
            int ncol = n0 + wc * 64 + nt * 8 + 2 * (lane & 3);
            if (ncol < V_) {
                float* p0 = C + (size_t)m * V_ + ncol;
                float* p1 = C + (size_t)(m + 8) * V_ + ncol;
                *(float2*)p0 = make_float2(acc[mi * 8 + nt][0], acc[mi * 8 + nt][1]);
                *(float2*)p1 = make_float2(acc[mi * 8 + nt][2], acc[mi * 8 + nt][3]);
            }
        }
    }
#endif
}

// ---------------------------------------------------------------------------
// Host orchestration
// ---------------------------------------------------------------------------
extern "C" void kernel_launch(void* const* d_in, const int* in_sizes, int n_in,
                              void* d_out, int out_size) {
    const float* enc_out = (const float*)d_in[0];
    const float* embed_w = (const float*)d_in[1];
    const float* enc_w   = (const float*)d_in[2];
    const float* enc_b   = (const float*)d_in[3];
    const float* qkv_w   = (const float*)d_in[4];
    const float* qkv_b   = (const float*)d_in[5];
    const float* o_w     = (const float*)d_in[6];
    const float* o_b     = (const float*)d_in[7];
    const float* ln1_s   = (const float*)d_in[8];
    const float* ln1_b   = (const float*)d_in[9];
    const float* ff1_w   = (const float*)d_in[10];
    const float* ff1_b   = (const float*)d_in[11];
    const float* ff2_w   = (const float*)d_in[12];
    const float* ff2_b   = (const float*)d_in[13];
    const float* ln2_s   = (const float*)d_in[14];
    const float* ln2_b   = (const float*)d_in[15];
    const float* out_w   = (const float*)d_in[16];
    const int*   tgt_pad = (const int*)d_in[17];
    const int*   tgt_len = (const int*)d_in[18];
    const int*   sos     = (const int*)d_in[19];

    float *x, *qkv, *tmp, *encp;
    cudaGetSymbolAddress((void**)&x, g_x);
    cudaGetSymbolAddress((void**)&qkv, g_qkv);
    cudaGetSymbolAddress((void**)&tmp, g_tmp);
    cudaGetSymbolAddress((void**)&encp, g_encp);

    __nv_bfloat16 *xh, *xl, *ath, *atl, *fh, *fl;
    cudaGetSymbolAddress((void**)&xh, g_xh);
    cudaGetSymbolAddress((void**)&xl, g_xl);
    cudaGetSymbolAddress((void**)&ath, g_ath);
    cudaGetSymbolAddress((void**)&atl, g_atl);
    cudaGetSymbolAddress((void**)&fh, g_fh);
    cudaGetSymbolAddress((void**)&fl, g_fl);

    __nv_bfloat16 *qkvwh, *qkvwl, *owh, *owl, *f1h, *f1l, *f2h, *f2l, *ewh, *ewl, *exh, *exl;
    cudaGetSymbolAddress((void**)&qkvwh, g_qkvwh);
    cudaGetSymbolAddress((void**)&qkvwl, g_qkvwl);
    cudaGetSymbolAddress((void**)&owh, g_owh);
    cudaGetSymbolAddress((void**)&owl, g_owl);
    cudaGetSymbolAddress((void**)&f1h, g_f1h);
    cudaGetSymbolAddress((void**)&f1l, g_f1l);
    cudaGetSymbolAddress((void**)&f2h, g_f2h);
    cudaGetSymbolAddress((void**)&f2l, g_f2l);
    cudaGetSymbolAddress((void**)&ewh, g_ewh);
    cudaGetSymbolAddress((void**)&ewl, g_ewl);
    cudaGetSymbolAddress((void**)&exh, g_exh);
    cudaGetSymbolAddress((void**)&exl, g_exl);

    __half *Aj, *Wjh, *Wjl;
    cudaGetSymbolAddress((void**)&Aj, g_Aj);
    cudaGetSymbolAddress((void**)&Wjh, g_Wjh);
    cudaGetSymbolAddress((void**)&Wjl, g_Wjl);

    static bool attr_done = false;
    if (!attr_done) {
        cudaFuncSetAttribute(joiner_tc_kernel,
                             cudaFuncAttributeMaxDynamicSharedMemorySize, JJ_SMEM);
        cudaFuncSetAttribute(gemm_tc,
                             cudaFuncAttributeMaxDynamicSharedMemorySize, JT_SMEM);
        attr_done = true;
    }

    // ---- fused weight splits (1 launch) + padded fp16 out_w split ----
    {
        SplitJobs jobs;
        int c0 = L_ * 3 * D_ * D_ / 4;
        int c1 = L_ * D_ * D_ / 4;
        int c2 = L_ * FF_ * D_ / 4;
        int c3 = L_ * D_ * FF_ / 4;
        int c4 = D_ * D_ / 4;
        int c5 = TI_ * NB_ * D_ / 4;
        jobs.src[0] = qkv_w;  jobs.h[0] = qkvwh; jobs.l[0] = qkvwl; jobs.end[0] = c0;
        jobs.src[1] = o_w;    jobs.h[1] = owh;   jobs.l[1] = owl;   jobs.end[1] = jobs.end[0] + c1;
        jobs.src[2] = ff1_w;  jobs.h[2] = f1h;   jobs.l[2] = f1l;   jobs.end[2] = jobs.end[1] + c2;
        jobs.src[3] = ff2_w;  jobs.h[3] = f2h;   jobs.l[3] = f2l;   jobs.end[3] = jobs.end[2] + c3;
        jobs.src[4] = enc_w;  jobs.h[4] = ewh;   jobs.l[4] = ewl;   jobs.end[4] = jobs.end[3] + c4;
        jobs.src[5] = enc_out;jobs.h[5] = exh;   jobs.l[5] = exl;   jobs.end[5] = jobs.end[4] + c5;
        int total = jobs.end[5];
        split_all_kernel<<<(total + 255) / 256, 256>>>(jobs, total);
        w_split_kernel<<<VP_, 128>>>(out_w, Wjh, Wjl);
    }

    // enc projection: encp[1024x512] = enc_out @ enc_w^T + b
    gemm_tc<<<dim3(D_ / 128, (TI_ * NB_) / 128, 1), 256, JT_SMEM>>>(
        exh, exl, ewh, ewl, enc_b, encp, nullptr, nullptr,
        TI_ * NB_, D_, D_, 8, 0);

    // embedding + positions
    embed_kernel<<<TOK_, 128>>>(embed_w, tgt_pad, sos, x, xh, xl);

    // 6 post-norm transformer layers
    for (int l = 0; l < L_; l++) {
        gemm_tc<<<dim3(3 * D_ / 128, 3, QKV_SPLIT), 256, JT_SMEM>>>(
            xh, xl, qkvwh + (size_t)l * 3 * D_ * D_, qkvwl + (size_t)l * 3 * D_ * D_,
            qkv_b + (size_t)l * 3 * D_, qkv, nullptr, nullptr,
            TOK_, 3 * D_, D_, 8 / QKV_SPLIT, 0);
        attention_kernel<<<NB_ * H_, 128>>>(qkv, tgt_len, ath, atl);
        gemm_tc<<<dim3(D_ / 128, 3, O_SPLIT), 256, JT_SMEM>>>(
            ath, atl, owh + (size_t)l * D_ * D_, owl + (size_t)l * D_ * D_,
            o_b + (size_t)l * D_, tmp, nullptr, nullptr,
            TOK_, D_, D_, 8 / O_SPLIT, 0);
        add_ln_kernel<<<TOK_, 128>>>(x, tmp, O_SPLIT,
            ln1_s + (size_t)l * D_, ln1_b + (size_t)l * D_, xh, xl);
        gemm_tc<<<dim3(FF_ / 128, 3, 1), 256, JT_SMEM>>>(
            xh, xl, f1h + (size_t)l * FF_ * D_, f1l + (size_t)l * FF_ * D_,
            ff1_b + (size_t)l * FF_, nullptr, fh, fl,
            TOK_, FF_, D_, 8, 1);
        gemm_tc<<<dim3(D_ / 128, 3, FF2_SPLIT), 256, JT_SMEM>>>(
            fh, fl, f2h + (size_t)l * D_ * FF_, f2l + (size_t)l * D_ * FF_,
            ff2_b + (size_t)l * D_, tmp, nullptr, nullptr,
            TOK_, D_, FF_, FF_ / 64 / FF2_SPLIT, 0);
        add_ln_kernel<<<TOK_, 128>>>(x, tmp, FF2_SPLIT,
            ln2_s + (size_t)l * D_, ln2_b + (size_t)l * D_, xh, xl);
    }

    // joiner: A = tanh(enc + x) as single fp16, then 2-term fp16 GEMM
    joiner_a_kernel<<<MJ_, 128>>>(encp, x, Aj);
    joiner_tc_kernel<<<dim3(VP_ / 128, MJ_ / 128), 256, JJ_SMEM>>>(
        Aj, Wjh, Wjl, (float*)d_out);
}

// round 8
// speedup vs baseline: 6.2332x; 1.0418x over previous
#include <cuda_runtime.h>
#include <cuda_bf16.h>
#include <cuda_fp16.h>
#include <math.h>
#include <stdint.h>

// ---------------------------------------------------------------------------
// Arch-feature gate (tcgen05 only legal on sm_10Xa feature targets)
// ---------------------------------------------------------------------------
#if defined(__CUDA_ARCH_FEAT_SM103_ALL) || defined(__CUDA_ARCH_FEAT_SM100_ALL) || defined(__CUDA_ARCH_FEAT_SM101_ALL)
#define USE_TCGEN05 1
#else
#define USE_TCGEN05 0
#endif

// ---------------------------------------------------------------------------
// Problem constants
// ---------------------------------------------------------------------------
#define TI_   128
#define NB_   8
#define TO_   32
#define TS_   33
#define D_    512
#define H_    8
#define HD_   64
#define FF_   2048
#define V_    2000
#define VP_   2048
#define L_    6
#define TOK_  (TS_ * NB_)          // 264
#define MJ_   (NB_ * TI_ * TS_)    // 33792
#define FF2_SPLIT 8
#define QKV_SPLIT 4
#define O_SPLIT   4

// ---------------------------------------------------------------------------
// Scratch (static __device__ arrays)
// ---------------------------------------------------------------------------
__device__ float g_x[TOK_ * D_];
__device__ float g_qkv[QKV_SPLIT * TOK_ * 3 * D_];
__device__ float g_tmp[FF2_SPLIT * TOK_ * D_];
__device__ float g_encp[TI_ * NB_ * D_];

__device__ __nv_bfloat16 g_xh[TOK_ * D_],  g_xl[TOK_ * D_];
__device__ __nv_bfloat16 g_ath[TOK_ * D_], g_atl[TOK_ * D_];
__device__ __nv_bfloat16 g_fh[TOK_ * FF_], g_fl[TOK_ * FF_];

__device__ __nv_bfloat16 g_qkvwh[(size_t)L_ * 3 * D_ * D_], g_qkvwl[(size_t)L_ * 3 * D_ * D_];
__device__ __nv_bfloat16 g_owh[(size_t)L_ * D_ * D_],       g_owl[(size_t)L_ * D_ * D_];
__device__ __nv_bfloat16 g_f1h[(size_t)L_ * FF_ * D_],      g_f1l[(size_t)L_ * FF_ * D_];
__device__ __nv_bfloat16 g_f2h[(size_t)L_ * D_ * FF_],      g_f2l[(size_t)L_ * D_ * FF_];
__device__ __nv_bfloat16 g_ewh[D_ * D_],                    g_ewl[D_ * D_];
__device__ __nv_bfloat16 g_exh[TI_ * NB_ * D_],             g_exl[TI_ * NB_ * D_];

// joiner operands: A single fp16, W single fp16 (plain fp16 GEMM)
__device__ __half g_Aj[(size_t)MJ_ * D_];
__device__ __half g_Wj[(size_t)VP_ * D_];

// ---------------------------------------------------------------------------
// PTX helpers
// ---------------------------------------------------------------------------
__device__ __forceinline__ uint32_t elect_one_pred() {
    uint32_t pred;
    asm volatile(
        "{\n\t.reg .pred p;\n\telect.sync _|p, 0xFFFFFFFF;\n\t"
        "selp.b32 %0, 1, 0, p;\n\t}"
        : "=r"(pred));
    return pred;
}
__device__ __forceinline__ uint32_t smem_to_u32(const void* smem_ptr) {
    uint32_t addr;
    asm("{ .reg .u64 tmp; cvta.to.shared.u64 tmp, %1; cvt.u32.u64 %0, tmp; }"
        : "=r"(addr) : "l"(smem_ptr));
    return addr;
}
__device__ __forceinline__ uint32_t sw_off(uint32_t bo) {
    return bo ^ ((bo >> 3) & 0x70);
}
// cp.async 16B with zero-fill when src invalid
__device__ __forceinline__ void cp_async16(uint32_t saddr, const void* gptr, int valid) {
    asm volatile("cp.async.cg.shared.global [%0], [%1], 16, %2;"
        :: "r"(saddr), "l"(gptr), "r"(valid ? 16 : 0));
}
__device__ __forceinline__ void cp_async_commit() {
    asm volatile("cp.async.commit_group;");
}
template <int N>
__device__ __forceinline__ void cp_async_wait() {
    asm volatile("cp.async.wait_group %0;" :: "n"(N) : "memory");
}
__device__ __forceinline__ void cp_async_commit_wait() {
    asm volatile("cp.async.commit_group;");
    asm volatile("cp.async.wait_group 0;" ::: "memory");
}

static constexpr uint64_t SMEM_DESC_BASE_SW128 =
    (uint64_t(2)  << 61) | (uint64_t(1) << 46) | (uint64_t(64) << 32) | (uint64_t(1) << 16);
#define MAKE_SMEM_DESC(base_addr) \
    (SMEM_DESC_BASE_SW128 | ((uint64_t)((base_addr) >> 4) & 0x3FFF))

#if USE_TCGEN05
#define TCGEN05_ALLOC(smem_result_addr, nCols) \
    asm volatile("tcgen05.alloc.cta_group::1.sync.aligned.shared::cta.b32 [%0], %1;" \
        :: "r"((uint32_t)(smem_result_addr)), "r"((uint32_t)(nCols)) : "memory")
#define TCGEN05_DEALLOC(tmem_addr, nCols) \
    asm volatile("tcgen05.dealloc.cta_group::1.sync.aligned.b32 %0, %1;" \
        :: "r"(tmem_addr), "r"((uint32_t)(nCols)))
#define TCGEN05_RELINQUISH_ALLOC_PERMIT() \
    asm volatile("tcgen05.relinquish_alloc_permit.cta_group::1.sync.aligned;")
#define TCGEN05_COMMIT(mbar_smem_addr) \
    asm volatile("tcgen05.commit.cta_group::1.mbarrier::arrive::one.shared::cluster.b64 [%0];" \
        :: "r"((uint32_t)(mbar_smem_addr)) : "memory")
#define TCGEN05_WAIT_LD() \
    asm volatile("tcgen05.wait::ld.sync.aligned;" ::: "memory")
#define TCGEN05_FENCE_AFTER() \
    asm volatile("tcgen05.fence::after_thread_sync;" ::: "memory")
#define FENCE_PROXY_ASYNC_SHARED_CTA() \
    asm volatile("fence.proxy.async.shared::cta;" ::: "memory")
#define MBARRIER_INIT(mbar_smem_addr, count) \
    asm volatile("mbarrier.init.shared.b64 [%0], %1;" \
        :: "r"((uint32_t)(mbar_smem_addr)), "r"((uint32_t)(count)) : "memory")
#define MBARRIER_INVAL(mbar_smem_addr) \
    asm volatile("mbarrier.inval.shared.b64 [%0];" :: "r"((uint32_t)(mbar_smem_addr)) : "memory")
#define MBARRIER_WAIT_PARITY(mbar_smem_addr, phase_parity) do { \
    uint32_t _mbar = (uint32_t)(mbar_smem_addr); \
    uint32_t _parity = (uint32_t)(phase_parity); \
    uint32_t _done; \
    asm volatile( \
        "{\n\t.reg .pred p;\n\t" \
        "mbarrier.try_wait.parity.acquire.cta.shared::cta.b64 p, [%1], %2;\n\t" \
        "selp.b32 %0, 1, 0, p;\n\t}" \
        : "=r"(_done) : "r"(_mbar), "r"(_parity) : "memory"); \
    if (!_done) { \
        asm volatile( \
            "{\n\t.reg .pred P1;\n\t" \
            "WAIT_LOOP_%=:\n\t" \
            "mbarrier.try_wait.parity.acquire.cta.shared::cta.b64 P1, [%0], %1, 0x989680;\n\t" \
            "@P1 bra.uni WAIT_DONE_%=;\n\t" \
            "bra.uni WAIT_LOOP_%=;\n\t" \
            "WAIT_DONE_%=:\n\t}" \
            :: "r"(_mbar), "r"(_parity) : "memory"); \
    } \
} while(0)
#define TCGEN05_LD_32X32B_X32(r, tmem_addr) \
    asm volatile( \
        "tcgen05.ld.sync.aligned.32x32b.x32.b32 " \
        "{%0, %1, %2, %3, %4, %5, %6, %7, " \
        " %8, %9, %10, %11, %12, %13, %14, %15, " \
        " %16, %17, %18, %19, %20, %21, %22, %23, " \
        " %24, %25, %26, %27, %28, %29, %30, %31}, [%32];" \
        : "=r"((r)[0]),  "=r"((r)[1]),  "=r"((r)[2]),  "=r"((r)[3]), \
          "=r"((r)[4]),  "=r"((r)[5]),  "=r"((r)[6]),  "=r"((r)[7]), \
          "=r"((r)[8]),  "=r"((r)[9]),  "=r"((r)[10]), "=r"((r)[11]), \
          "=r"((r)[12]), "=r"((r)[13]), "=r"((r)[14]), "=r"((r)[15]), \
          "=r"((r)[16]), "=r"((r)[17]), "=r"((r)[18]), "=r"((r)[19]), \
          "=r"((r)[20]), "=r"((r)[21]), "=r"((r)[22]), "=r"((r)[23]), \
          "=r"((r)[24]), "=r"((r)[25]), "=r"((r)[26]), "=r"((r)[27]), \
          "=r"((r)[28]), "=r"((r)[29]), "=r"((r)[30]), "=r"((r)[31]) \
        : "r"(tmem_addr))

__device__ __forceinline__ void mma_f16_ss_cg1(uint32_t d_tmem, uint64_t a_desc,
                                               uint64_t b_desc, uint32_t idesc,
                                               uint32_t enable) {
    asm volatile(
        "{\n\t.reg .pred p;\n\t"
        "setp.ne.u32 p, %4, 0;\n\t"
        "tcgen05.mma.cta_group::1.kind::f16 [%0], %1, %2, %3, {%5, %5, %5, %5}, p;\n\t}"
        :: "r"(d_tmem), "l"(a_desc), "l"(b_desc), "r"(idesc), "r"(enable), "r"(0u)
        : "memory");
}
#define JOINER_IDESC_F16 0x8200010u   // dtype F32, atype/btype FP16, M=N=128
#endif // USE_TCGEN05

// ---------------------------------------------------------------------------
// mma.sync helpers (base target)
// ---------------------------------------------------------------------------
__device__ __forceinline__ void ldmatrix_x4(uint32_t* r, uint32_t addr) {
    asm volatile("ldmatrix.sync.aligned.m8n8.x4.shared.b16 {%0,%1,%2,%3}, [%4];"
        : "=r"(r[0]), "=r"(r[1]), "=r"(r[2]), "=r"(r[3]) : "r"(addr));
}
__device__ __forceinline__ void mma16816(float* d, const uint32_t* a,
                                         uint32_t b0, uint32_t b1) {
    asm volatile(
        "mma.sync.aligned.m16n8k16.row.col.f32.bf16.bf16.f32 "
        "{%0,%1,%2,%3}, {%4,%5,%6,%7}, {%8,%9}, {%0,%1,%2,%3};"
        : "+f"(d[0]), "+f"(d[1]), "+f"(d[2]), "+f"(d[3])
        : "r"(a[0]), "r"(a[1]), "r"(a[2]), "r"(a[3]), "r"(b0), "r"(b1));
}
__device__ __forceinline__ void mma16816_f16(float* d, const uint32_t* a,
                                             uint32_t b0, uint32_t b1) {
    asm volatile(
        "mma.sync.aligned.m16n8k16.row.col.f32.f16.f16.f32 "
        "{%0,%1,%2,%3}, {%4,%5,%6,%7}, {%8,%9}, {%0,%1,%2,%3};"
        : "+f"(d[0]), "+f"(d[1]), "+f"(d[2]), "+f"(d[3])
        : "r"(a[0]), "r"(a[1]), "r"(a[2]), "r"(a[3]), "r"(b0), "r"(b1));
}

__device__ __forceinline__ void split_hl(float v, __nv_bfloat16& h, __nv_bfloat16& l) {
    h = __float2bfloat16(v);
    l = __float2bfloat16(v - __bfloat162float(h));
}

// ---------------------------------------------------------------------------
// Fused weight split (bf16 hi/lo for the layer chain)
// ---------------------------------------------------------------------------
#define NSPLITJOBS 6
struct SplitJobs {
    const float* src[NSPLITJOBS];
    __nv_bfloat16* h[NSPLITJOBS];
    __nv_bfloat16* l[NSPLITJOBS];
    int end[NSPLITJOBS];   // prefix-sum of vec4 counts
};

__global__ void split_all_kernel(SplitJobs jobs, int total) {
    int i = blockIdx.x * blockDim.x + threadIdx.x;
    if (i >= total) return;
    int j = 0;
#pragma unroll
    for (int k = 0; k < NSPLITJOBS - 1; k++) j += (i >= jobs.end[k]);
    int base = (j == 0) ? 0 : jobs.end[j - 1];
    int li = i - base;
    float4 w = ((const float4*)jobs.src[j])[li];
    __nv_bfloat16 h0, h1, h2, h3, l0, l1, l2, l3;
    split_hl(w.x, h0, l0); split_hl(w.y, h1, l1);
    split_hl(w.z, h2, l2); split_hl(w.w, h3, l3);
    ((__nv_bfloat162*)jobs.h[j])[2 * li]     = __nv_bfloat162(h0, h1);
    ((__nv_bfloat162*)jobs.h[j])[2 * li + 1] = __nv_bfloat162(h2, h3);
    ((__nv_bfloat162*)jobs.l[j])[2 * li]     = __nv_bfloat162(l0, l1);
    ((__nv_bfloat162*)jobs.l[j])[2 * li + 1] = __nv_bfloat162(l2, l3);
}

// out_w -> single fp16, padded to VP_ rows
__global__ void w_split_kernel(const float* __restrict__ W,
                               __half* __restrict__ Wj) {
    int r = blockIdx.x;
    int tid = threadIdx.x;
    size_t base = (size_t)r * D_ + tid * 4;
    if (r < V_) {
        const float4 w = ((const float4*)(W + (size_t)r * D_))[tid];
        ((__half2*)(Wj + base))[0] = __half2(__float2half(w.x), __float2half(w.y));
        ((__half2*)(Wj + base))[1] = __half2(__float2half(w.z), __float2half(w.w));
    } else {
        __half2 z = __half2(__float2half(0.f), __float2half(0.f));
        ((__half2*)(Wj + base))[0] = z;
        ((__half2*)(Wj + base))[1] = z;
    }
}

// ---------------------------------------------------------------------------
// Embedding + positions -> x fp32 + bf16 hi/lo  (fp32 transcendentals)
// ---------------------------------------------------------------------------
__global__ void embed_kernel(const float* __restrict__ embed,
                             const int* __restrict__ tgt_pad,
                             const int* __restrict__ sos,
                             float* __restrict__ x,
                             __nv_bfloat16* __restrict__ xh,
                             __nv_bfloat16* __restrict__ xl) {
    int r = blockIdx.x;
    int t = r >> 3, n = r & 7;
    int tok = (t == 0) ? sos[0] : tgt_pad[n * TO_ + (t - 1)];
    const float* e = embed + (size_t)tok * D_;
    const float sc = sqrtf(512.0f);
    int tid = threadIdx.x;
#pragma unroll
    for (int i = 0; i < 2; i++) {
        int d = tid * 4 + i * 2;
        float ddiv = expf((float)d * (-9.210340371976184f / 512.0f));
        float ang = (float)t * ddiv;
        float sv, cv;
        sincosf(ang, &sv, &cv);
        size_t idx = (size_t)r * D_ + d;
        float v0 = e[d] * sc + sv;
        float v1 = e[d + 1] * sc + cv;
        x[idx] = v0; x[idx + 1] = v1;
        __nv_bfloat16 h0, l0, h1, l1;
        split_hl(v0, h0, l0); split_hl(v1, h1, l1);
        xh[idx] = h0; xh[idx + 1] = h1;
        xl[idx] = l0; xl[idx + 1] = l1;
    }
}

// ---------------------------------------------------------------------------
// Tile loaders (16-bit elems, 128 rows; SW128 rows of 128B = 64 elements)
// ---------------------------------------------------------------------------
__device__ __forceinline__ void tc_load_tile_async(const __nv_bfloat16* __restrict__ src,
                                                   int row0, int maxrow, int koff,
                                                   int kstride, uint32_t sm, int tid) {
#pragma unroll
    for (int p = 0; p < 4; p++) {
        int idx = p * 256 + tid;
        int row = idx >> 3, seg = idx & 7;
        int gr = row0 + row;
        uint32_t bo = (uint32_t)(row * 128 + seg * 16);
        cp_async16(sm + sw_off(bo),
                   src + (size_t)gr * kstride + koff + seg * 8,
                   gr < maxrow);
    }
}
// half chunk (32 elements = 64B): p selects which 64B half of the row buffer
__device__ __forceinline__ void tc_load_half_async(const __nv_bfloat16* __restrict__ src,
                                                   int row0, int maxrow, int kelem,
                                                   int kstride, uint32_t sm, int tid, int p) {
#pragma unroll
    for (int q = 0; q < 2; q++) {
        int idx = q * 256 + tid;
        int row = idx >> 2, seg = idx & 3;
        int gr = row0 + row;
        uint32_t bo = (uint32_t)(row * 128 + p * 64 + seg * 16);
        cp_async16(sm + sw_off(bo),
                   src + (size_t)gr * kstride + kelem + seg * 8,
                   gr < maxrow);
    }
}

// layer-chain GEMM smem layout (bf16 3-term)
#define JT_BUF      16384
#define JT_SM_AH    1024
#define JT_SM_AL    (JT_SM_AH + JT_BUF)
#define JT_SM_WH    (JT_SM_AL + JT_BUF)
#define JT_SM_WL    (JT_SM_WH + JT_BUF)
#define JT_SMEM     (JT_SM_WL + JT_BUF)      // 66560

// joiner smem layout (plain fp16: A, W)
#define JJ_SM_A     1024
#define JJ_SM_W     (JJ_SM_A + JT_BUF)
#define JJ_SMEM     (JJ_SM_W + JT_BUF)       // 33792

__device__ __forceinline__ void load_half4(const __nv_bfloat16* Ah, const __nv_bfloat16* Al,
                                           const __nv_bfloat16* Wh, const __nv_bfloat16* Wl,
                                           int m0, int M, int n0, int N,
                                           int kelem, int kstride,
                                           uint32_t sbase, int tid, int p) {
    tc_load_half_async(Ah, m0, M, kelem, kstride, sbase + JT_SM_AH, tid, p);
    tc_load_half_async(Al, m0, M, kelem, kstride, sbase + JT_SM_AL, tid, p);
    tc_load_half_async(Wh, n0, N, kelem, kstride, sbase + JT_SM_WH, tid, p);
    tc_load_half_async(Wl, n0, N, kelem, kstride, sbase + JT_SM_WL, tid, p);
}
__device__ __forceinline__ void load_half2_j(const __half* A, const __half* W,
                                             int m0, int n0, int kelem,
                                             uint32_t sbase, int tid, int p) {
    tc_load_half_async((const __nv_bfloat16*)A, m0, MJ_, kelem, D_, sbase + JJ_SM_A, tid, p);
    tc_load_half_async((const __nv_bfloat16*)W, n0, VP_, kelem, D_, sbase + JJ_SM_W, tid, p);
}

// ---------------------------------------------------------------------------
// mma.sync mainloops over ONE 32-element half (s = 2p, 2p+1)
// ---------------------------------------------------------------------------
__device__ __forceinline__ void mma_mainloop_half(uint32_t sbase, int wr, int wc,
                                                  int lane, float acc[16][4], int p) {
    const int aoffs[3] = {JT_SM_AH, JT_SM_AH, JT_SM_AL};
    const int boffs[3] = {JT_SM_WH, JT_SM_WL, JT_SM_WH};
    const int bt = lane >> 3, br_ = lane & 7;
#pragma unroll
    for (int si = 0; si < 2; si++) {
        const int s = 2 * p + si;
#pragma unroll
        for (int tm = 0; tm < 3; tm++) {
            uint32_t afrag[2][4];
#pragma unroll
            for (int mi = 0; mi < 2; mi++) {
                uint32_t bo = (uint32_t)((wr * 32 + mi * 16 + (lane & 15)) * 128
                                         + s * 32 + (lane >> 4) * 16);
                ldmatrix_x4(afrag[mi], sbase + aoffs[tm] + sw_off(bo));
            }
#pragma unroll
            for (int g = 0; g < 4; g++) {
                uint32_t bo = (uint32_t)((wc * 64 + g * 16 + (bt >> 1) * 8 + br_) * 128
                                         + s * 32 + (bt & 1) * 16);
                uint32_t bfr[4];
                ldmatrix_x4(bfr, sbase + boffs[tm] + sw_off(bo));
                mma16816(acc[2 * g],     afrag[0], bfr[0], bfr[1]);
                mma16816(acc[8 + 2 * g], afrag[1], bfr[0], bfr[1]);
                mma16816(acc[2 * g + 1],     afrag[0], bfr[2], bfr[3]);
                mma16816(acc[8 + 2 * g + 1], afrag[1], bfr[2], bfr[3]);
            }
        }
    }
}
// joiner plain fp16: single term (A, W)
__device__ __forceinline__ void mma_mainloop_half_j(uint32_t sbase, int wr, int wc,
                                                    int lane, float acc[16][4], int p) {
    const int bt = lane >> 3, br_ = lane & 7;
#pragma unroll
    for (int si = 0; si < 2; si++) {
        const int s = 2 * p + si;
        uint32_t afrag[2][4];
#pragma unroll
        for (int mi = 0; mi < 2; mi++) {
            uint32_t bo = (uint32_t)((wr * 32 + mi * 16 + (lane & 15)) * 128
                                     + s * 32 + (lane >> 4) * 16);
            ldmatrix_x4(afrag[mi], sbase + JJ_SM_A + sw_off(bo));
        }
#pragma unroll
        for (int g = 0; g < 4; g++) {
            uint32_t bo = (uint32_t)((wc * 64 + g * 16 + (bt >> 1) * 8 + br_) * 128
                                     + s * 32 + (bt & 1) * 16);
            uint32_t bfr[4];
            ldmatrix_x4(bfr, sbase + JJ_SM_W + sw_off(bo));
            mma16816_f16(acc[2 * g],     afrag[0], bfr[0], bfr[1]);
            mma16816_f16(acc[8 + 2 * g], afrag[1], bfr[0], bfr[1]);
            mma16816_f16(acc[2 * g + 1],     afrag[0], bfr[2], bfr[3]);
            mma16816_f16(acc[8 + 2 * g + 1], afrag[1], bfr[2], bfr[3]);
        }
    }
}

// ---------------------------------------------------------------------------
// Layer-chain tensor GEMM (3-term bf16 hi/lo), half-buffer pipelined
// ---------------------------------------------------------------------------
__global__ void __launch_bounds__(256) gemm_tc(
    const __nv_bfloat16* __restrict__ Ah, const __nv_bfloat16* __restrict__ Al,
    const __nv_bfloat16* __restrict__ Wh, const __nv_bfloat16* __restrict__ Wl,
    const float* __restrict__ bias,
    float* __restrict__ C,
    __nv_bfloat16* __restrict__ Ch, __nv_bfloat16* __restrict__ Cl,
    int M, int N, int kstride, int chunks, int relu) {
    extern __shared__ char smem[];
    const uint32_t sbase = smem_to_u32(smem);
    const int tid = threadIdx.x;
    const int n0 = blockIdx.x * 128;
    const int m0 = blockIdx.y * 128;
    const int z  = blockIdx.z;
    const int koff0 = z * chunks * 64;
    if (C) C += (size_t)z * M * N;

    const int w = tid >> 5, lane = tid & 31;
    const int wr = w >> 1, wc = w & 1;

    float acc[16][4];
#pragma unroll
    for (int i = 0; i < 16; i++)
#pragma unroll
        for (int j = 0; j < 4; j++) acc[i][j] = 0.f;

    const int nhalf = chunks * 2;
    load_half4(Ah, Al, Wh, Wl, m0, M, n0, N, koff0, kstride, sbase, tid, 0);
    cp_async_commit();
    for (int c = 0; c < nhalf; c++) {
        if (c + 1 < nhalf) {
            load_half4(Ah, Al, Wh, Wl, m0, M, n0, N,
                       koff0 + (c + 1) * 32, kstride, sbase, tid, (c + 1) & 1);
            cp_async_commit();
            cp_async_wait<1>();
        } else {
            cp_async_wait<0>();
        }
        __syncthreads();
        mma_mainloop_half(sbase, wr, wc, lane, acc, c & 1);
        __syncthreads();
    }

    const bool addb = (bias != nullptr) && (z == 0);
#pragma unroll
    for (int mi = 0; mi < 2; mi++) {
#pragma unroll
        for (int nt = 0; nt < 8; nt++) {
            int m = m0 + wr * 32 + mi * 16 + (lane >> 2);
            int ncol = n0 + wc * 64 + nt * 8 + 2 * (lane & 3);
            float b0v = addb ? bias[ncol] : 0.f;
            float b1v = addb ? bias[ncol + 1] : 0.f;
            float v0 = acc[mi * 8 + nt][0] + b0v;
            float v1 = acc[mi * 8 + nt][1] + b1v;
            float v2 = acc[mi * 8 + nt][2] + b0v;
            float v3 = acc[mi * 8 + nt][3] + b1v;
            if (relu) {
                v0 = fmaxf(v0, 0.f); v1 = fmaxf(v1, 0.f);
                v2 = fmaxf(v2, 0.f); v3 = fmaxf(v3, 0.f);
            }
            if (m < M) {
                size_t o = (size_t)m * N + ncol;
                if (C) *(float2*)(C + o) = make_float2(v0, v1);
                if (Ch) {
                    __nv_bfloat16 h0, h1, l0, l1;
                    split_hl(v0, h0, l0); split_hl(v1, h1, l1);
                    *(__nv_bfloat162*)(Ch + o) = __nv_bfloat162(h0, h1);
                    *(__nv_bfloat162*)(Cl + o) = __nv_bfloat162(l0, l1);
                }
            }
            if (m + 8 < M) {
                size_t o = (size_t)(m + 8) * N + ncol;
                if (C) *(float2*)(C + o) = make_float2(v2, v3);
                if (Ch) {
                    __nv_bfloat16 h0, h1, l0, l1;
                    split_hl(v2, h0, l0); split_hl(v3, h1, l1);
                    *(__nv_bfloat162*)(Ch + o) = __nv_bfloat162(h0, h1);
                    *(__nv_bfloat162*)(Cl + o) = __nv_bfloat162(l0, l1);
                }
            }
        }
    }
}

// ---------------------------------------------------------------------------
// Attention: one block per (n,h); sums QKV_SPLIT k-split slices of qkv.
// ---------------------------------------------------------------------------
__global__ void attention_kernel(const float* __restrict__ qkv,
                                 const int* __restrict__ tgt_len,
                                 __nv_bfloat16* __restrict__ oh,
                                 __nv_bfloat16* __restrict__ ol) {
    int n = blockIdx.x >> 3, h = blockIdx.x & 7;
    __shared__ float qs[TS_][HD_];
    __shared__ float ks[TS_][HD_];
    __shared__ float vs[TS_][HD_];
    __shared__ float sc[TS_][TS_ + 1];
    int tid = threadIdx.x;
    int len = tgt_len[n]; if (len < 1) len = 1;

    for (int e = tid; e < TS_ * HD_; e += 128) {
        int t = e >> 6, d = e & 63;
        size_t off = (size_t)(t * 8 + n) * (3 * D_) + h * 64 + d;
        float q = 0.f, k = 0.f, v = 0.f;
#pragma unroll
        for (int z = 0; z < QKV_SPLIT; z++) {
            const float* b = qkv + (size_t)z * TOK_ * 3 * D_ + off;
            q += b[0]; k += b[512]; v += b[1024];
        }
        qs[t][d] = q; ks[t][d] = k; vs[t][d] = v;
    }
    __syncthreads();

    for (int p = tid; p < TS_ * TS_; p += 128) {
        int tq = p / TS_, tk = p - tq * TS_;
        float s;
        if (tk > tq || tk >= len) {
            s = -1e9f;
        } else {
            s = 0.f;
#pragma unroll 8
            for (int d = 0; d < HD_; d++) s += qs[tq][d] * ks[tk][d];
            s *= 0.125f;
        }
        sc[tq][tk] = s;
    }
    __syncthreads();

    if (tid < TS_) {
        int tq = tid;
        float mx = -1e30f;
        for (int tk = 0; tk < TS_; tk++) mx = fmaxf(mx, sc[tq][tk]);
        float sum = 0.f;
        for (int tk = 0; tk < TS_; tk++) {
            float e = expf(sc[tq][tk] - mx);
            sc[tq][tk] = e;
            sum += e;
        }
        float inv = 1.0f / sum;
        for (int tk = 0; tk < TS_; tk++) sc[tq][tk] *= inv;
    }
    __syncthreads();

    for (int e = tid; e < TS_ * HD_; e += 128) {
        int tq = e >> 6, d = e & 63;
        float s = 0.f;
#pragma unroll 8
        for (int tk = 0; tk < TS_; tk++) s += sc[tq][tk] * vs[tk][d];
        size_t idx = (size_t)(tq * 8 + n) * D_ + h * 64 + d;
        __nv_bfloat16 hv, lv;
        split_hl(s, hv, lv);
        oh[idx] = hv; ol[idx] = lv;
    }
}

// ---------------------------------------------------------------------------
// Residual add (x + sum of nsplit tmp slices) + LN; writes x fp32 + bf16 hi/lo
// ---------------------------------------------------------------------------
__global__ void add_ln_kernel(float* __restrict__ x,
                              const float* __restrict__ y, int nsplit,
                              const float* __restrict__ s,
                              const float* __restrict__ b,
                              __nv_bfloat16* __restrict__ xh,
                              __nv_bfloat16* __restrict__ xl) {
    int row = blockIdx.x, tid = threadIdx.x;
    __shared__ float sh[8];
    const float4 xv = ((const float4*)(x + (size_t)row * D_))[tid];
    float r0 = xv.x, r1 = xv.y, r2 = xv.z, r3 = xv.w;
    for (int z = 0; z < nsplit; z++) {
        const float4 yv = ((const float4*)(y + (size_t)z * TOK_ * D_ + (size_t)row * D_))[tid];
        r0 += yv.x; r1 += yv.y; r2 += yv.z; r3 += yv.w;
    }

    float sum = r0 + r1 + r2 + r3;
    int lane = tid & 31, wp = tid >> 5;
#pragma unroll
    for (int off = 16; off > 0; off >>= 1) sum += __shfl_xor_sync(0xffffffffu, sum, off);
    if (lane == 0) sh[wp] = sum;
    __syncthreads();
    float mean = (sh[0] + sh[1] + sh[2] + sh[3]) * (1.0f / 512.0f);

    float d0 = r0 - mean, d1 = r1 - mean, d2 = r2 - mean, d3 = r3 - mean;
    float sq = d0 * d0 + d1 * d1 + d2 * d2 + d3 * d3;
#pragma unroll
    for (int off = 16; off > 0; off >>= 1) sq += __shfl_xor_sync(0xffffffffu, sq, off);
    if (lane == 0) sh[4 + wp] = sq;
    __syncthreads();
    float var = (sh[4] + sh[5] + sh[6] + sh[7]) * (1.0f / 512.0f);
    float rstd = 1.0f / sqrtf(var + 1e-5f);

    const float4 sv = ((const float4*)s)[tid];
    const float4 bv = ((const float4*)b)[tid];
    float o0 = d0 * rstd * sv.x + bv.x;
    float o1 = d1 * rstd * sv.y + bv.y;
    float o2 = d2 * rstd * sv.z + bv.z;
    float o3 = d3 * rstd * sv.w + bv.w;
    ((float4*)(x + (size_t)row * D_))[tid] = make_float4(o0, o1, o2, o3);

    size_t base = (size_t)row * D_ + tid * 4;
    __nv_bfloat16 h0, h1, h2, h3, l0, l1, l2, l3;
    split_hl(o0, h0, l0); split_hl(o1, h1, l1);
    split_hl(o2, h2, l2); split_hl(o3, h3, l3);
    ((__nv_bfloat162*)(xh + base))[0] = __nv_bfloat162(h0, h1);
    ((__nv_bfloat162*)(xh + base))[1] = __nv_bfloat162(h2, h3);
    ((__nv_bfloat162*)(xl + base))[0] = __nv_bfloat162(l0, l1);
    ((__nv_bfloat162*)(xl + base))[1] = __nv_bfloat162(l2, l3);
}

// ---------------------------------------------------------------------------
// Joiner A materialization -> single fp16
// ---------------------------------------------------------------------------
__global__ void joiner_a_kernel(const float* __restrict__ enc,
                                const float* __restrict__ x,
                                __half* __restrict__ A) {
    int r = blockIdx.x;
    int n = r / (TI_ * TS_);
    int rem = r - n * (TI_ * TS_);
    int i = rem / TS_;
    int t = rem - i * TS_;
    const float4* er = (const float4*)(enc + (size_t)(i * 8 + n) * D_);
    const float4* xr = (const float4*)(x + (size_t)(t * 8 + n) * D_);
    int tid = threadIdx.x;
    float4 e = er[tid], xx = xr[tid];
    __half2 h0 = __half2(__float2half(tanhf(e.x + xx.x)), __float2half(tanhf(e.y + xx.y)));
    __half2 h1 = __half2(__float2half(tanhf(e.z + xx.z)), __float2half(tanhf(e.w + xx.w)));
    size_t base = (size_t)r * D_ + tid * 4;
    ((__half2*)(A + base))[0] = h0;
    ((__half2*)(A + base))[1] = h1;
}

// ---------------------------------------------------------------------------
// Joiner GEMM (tile 128x128, K=512, plain fp16) — tcgen05 or mma.sync
// ---------------------------------------------------------------------------
#define JT_CHUNKS   8

__global__ void __launch_bounds__(256) joiner_tc_kernel(
    const __half* __restrict__ A,
    const __half* __restrict__ W,
    float* __restrict__ C) {
    extern __shared__ char smem[];
    const uint32_t sbase = smem_to_u32(smem);
    const int tid = threadIdx.x;
    const int n0 = blockIdx.x * 128;
    const int m0 = blockIdx.y * 128;

#if USE_TCGEN05
    const int wid = tid >> 5, lane = tid & 31;

    if (wid == 0) {
        TCGEN05_ALLOC(sbase, 128);
        TCGEN05_RELINQUISH_ALLOC_PERMIT();
    }
    if (tid == 0) MBARRIER_INIT(sbase + 8, 1);
    __syncthreads();
    uint32_t tmem_base;
    asm volatile("ld.shared.b32 %0, [%1];" : "=r"(tmem_base) : "r"(sbase));

    const uint64_t dA = MAKE_SMEM_DESC(sbase + JJ_SM_A);
    const uint64_t dW = MAKE_SMEM_DESC(sbase + JJ_SM_W);

    for (int c = 0; c < JT_CHUNKS; c++) {
        if (c > 0) MBARRIER_WAIT_PARITY(sbase + 8, (c - 1) & 1);
        const int koff = c * 64;
        tc_load_tile_async((const __nv_bfloat16*)A, m0, MJ_, koff, D_, sbase + JJ_SM_A, tid);
        tc_load_tile_async((const __nv_bfloat16*)W, n0, VP_, koff, D_, sbase + JJ_SM_W, tid);
        cp_async_commit_wait();
        __syncthreads();
        if (wid == 0) {
            if (elect_one_pred()) {
                FENCE_PROXY_ASYNC_SHARED_CTA();
#pragma unroll
                for (int k = 0; k < 4; k++)
                    mma_f16_ss_cg1(tmem_base, dA + k * 2, dW + k * 2,
                                   JOINER_IDESC_F16, (c > 0) || (k > 0));
                TCGEN05_COMMIT(sbase + 8);
            }
        }
    }
    MBARRIER_WAIT_PARITY(sbase + 8, (JT_CHUNKS - 1) & 1);
    TCGEN05_FENCE_AFTER();

    {
        const int sub = wid & 3;
        const int halfc = (wid >> 2) * 64;
        float* crow = C + (size_t)(m0 + sub * 32 + lane) * V_;
        const bool full = (n0 + 128) <= V_;
#pragma unroll
        for (int base = halfc; base < halfc + 64; base += 32) {
            uint32_t r[32];
            TCGEN05_LD_32X32B_X32(r, tmem_base + base);
            TCGEN05_WAIT_LD();
            if (full) {
#pragma unroll
                for (int j = 0; j < 32; j += 4) {
                    *(float4*)(crow + n0 + base + j) =
                        make_float4(__uint_as_float(r[j]), __uint_as_float(r[j + 1]),
                                    __uint_as_float(r[j + 2]), __uint_as_float(r[j + 3]));
                }
            } else {
#pragma unroll
                for (int j = 0; j < 32; j++) {
                    int col = n0 + base + j;
                    if (col < V_) crow[col] = __uint_as_float(r[j]);
                }
            }
        }
    }
    __syncthreads();
    if (wid == 0) {
        if (elect_one_pred()) MBARRIER_INVAL(sbase + 8);
        TCGEN05_DEALLOC(tmem_base, 128);
    }

#else  // mma.sync path, plain fp16, half-buffer pipeline
    const int w = tid >> 5, lane = tid & 31;
    const int wr = w >> 1, wc = w & 1;

    float acc[16][4];
#pragma unroll
    for (int i = 0; i < 16; i++)
#pragma unroll
        for (int j = 0; j < 4; j++) acc[i][j] = 0.f;

    const int nhalf = JT_CHUNKS * 2;
    load_half2_j(A, W, m0, n0, 0, sbase, tid, 0);
    cp_async_commit();
    for (int c = 0; c < nhalf; c++) {
        if (c + 1 < nhalf) {
            load_half2_j(A, W, m0, n0, (c + 1) * 32, sbase, tid, (c + 1) & 1);
            cp_async_commit();
            cp_async_wait<1>();
        } else {
            cp_async_wait<0>();
        }
        __syncthreads();
        mma_mainloop_half_j(sbase, wr, wc, lane, acc, c & 1);
        __syncthreads();
    }

#pragma unroll
    for (int mi = 0; mi < 2; mi++) {
#pragma unroll
        for (int nt = 0; nt < 8; nt++) {
            int m = m0 + wr * 32 + mi * 16 + (lane >> 2);
            int ncol = n0 + wc * 64 + nt * 8 + 2 * (lane & 3);
            if (ncol < V_) {
                float* p0 = C + (size_t)m * V_ + ncol;
                float* p1 = C + (size_t)(m + 8) * V_ + ncol;
                *(float2*)p0 = make_float2(acc[mi * 8 + nt][0], acc[mi * 8 + nt][1]);
                *(float2*)p1 = make_float2(acc[mi * 8 + nt][2], acc[mi * 8 + nt][3]);
            }
        }
    }
#endif
}

// ---------------------------------------------------------------------------
// Host orchestration
// ---------------------------------------------------------------------------
extern "C" void kernel_launch(void* const* d_in, const int* in_sizes, int n_in,
                              void* d_out, int out_size) {
    const float* enc_out = (const float*)d_in[0];
    const float* embed_w = (const float*)d_in[1];
    const float* enc_w   = (const float*)d_in[2];
    const float* enc_b   = (const float*)d_in[3];
    const float* qkv_w   = (const float*)d_in[4];
    const float* qkv_b   = (const float*)d_in[5];
    const float* o_w     = (const float*)d_in[6];
    const float* o_b     = (const float*)d_in[7];
    const float* ln1_s   = (const float*)d_in[8];
    const float* ln1_b   = (const float*)d_in[9];
    const float* ff1_w   = (const float*)d_in[10];
    const float* ff1_b   = (const float*)d_in[11];
    const float* ff2_w   = (const float*)d_in[12];
    const float* ff2_b   = (const float*)d_in[13];
    const float* ln2_s   = (const float*)d_in[14];
    const float* ln2_b   = (const float*)d_in[15];
    const float* out_w   = (const float*)d_in[16];
    const int*   tgt_pad = (const int*)d_in[17];
    const int*   tgt_len = (const int*)d_in[18];
    const int*   sos     = (const int*)d_in[19];

    float *x, *qkv, *tmp, *encp;
    cudaGetSymbolAddress((void**)&x, g_x);
    cudaGetSymbolAddress((void**)&qkv, g_qkv);
    cudaGetSymbolAddress((void**)&tmp, g_tmp);
    cudaGetSymbolAddress((void**)&encp, g_encp);

    __nv_bfloat16 *xh, *xl, *ath, *atl, *fh, *fl;
    cudaGetSymbolAddress((void**)&xh, g_xh);
    cudaGetSymbolAddress((void**)&xl, g_xl);
    cudaGetSymbolAddress((void**)&ath, g_ath);
    cudaGetSymbolAddress((void**)&atl, g_atl);
    cudaGetSymbolAddress((void**)&fh, g_fh);
    cudaGetSymbolAddress((void**)&fl, g_fl);

    __nv_bfloat16 *qkvwh, *qkvwl, *owh, *owl, *f1h, *f1l, *f2h, *f2l, *ewh, *ewl, *exh, *exl;
    cudaGetSymbolAddress((void**)&qkvwh, g_qkvwh);
    cudaGetSymbolAddress((void**)&qkvwl, g_qkvwl);
    cudaGetSymbolAddress((void**)&owh, g_owh);
    cudaGetSymbolAddress((void**)&owl, g_owl);
    cudaGetSymbolAddress((void**)&f1h, g_f1h);
    cudaGetSymbolAddress((void**)&f1l, g_f1l);
    cudaGetSymbolAddress((void**)&f2h, g_f2h);
    cudaGetSymbolAddress((void**)&f2l, g_f2l);
    cudaGetSymbolAddress((void**)&ewh, g_ewh);
    cudaGetSymbolAddress((void**)&ewl, g_ewl);
    cudaGetSymbolAddress((void**)&exh, g_exh);
    cudaGetSymbolAddress((void**)&exl, g_exl);

    __half *Aj, *Wj;
    cudaGetSymbolAddress((void**)&Aj, g_Aj);
    cudaGetSymbolAddress((void**)&Wj, g_Wj);

    static bool attr_done = false;
    if (!attr_done) {
        cudaFuncSetAttribute(joiner_tc_kernel,
                             cudaFuncAttributeMaxDynamicSharedMemorySize, JJ_SMEM);
        cudaFuncSetAttribute(gemm_tc,
                             cudaFuncAttributeMaxDynamicSharedMemorySize, JT_SMEM);
        attr_done = true;
    }

    // ---- fused weight splits (1 launch) + padded fp16 out_w ----
    {
        SplitJobs jobs;
        int c0 = L_ * 3 * D_ * D_ / 4;
        int c1 = L_ * D_ * D_ / 4;
        int c2 = L_ * FF_ * D_ / 4;
        int c3 = L_ * D_ * FF_ / 4;
        int c4 = D_ * D_ / 4;
        int c5 = TI_ * NB_ * D_ / 4;
        jobs.src[0] = qkv_w;  jobs.h[0] = qkvwh; jobs.l[0] = qkvwl; jobs.end[0] = c0;
        jobs.src[1] = o_w;    jobs.h[1] = owh;   jobs.l[1] = owl;   jobs.end[1] = jobs.end[0] + c1;
        jobs.src[2] = ff1_w;  jobs.h[2] = f1h;   jobs.l[2] = f1l;   jobs.end[2] = jobs.end[1] + c2;
        jobs.src[3] = ff2_w;  jobs.h[3] = f2h;   jobs.l[3] = f2l;   jobs.end[3] = jobs.end[2] + c3;
        jobs.src[4] = enc_w;  jobs.h[4] = ewh;   jobs.l[4] = ewl;   jobs.end[4] = jobs.end[3] + c4;
        jobs.src[5] = enc_out;jobs.h[5] = exh;   jobs.l[5] = exl;   jobs.end[5] = jobs.end[4] + c5;
        int total = jobs.end[5];
        split_all_kernel<<<(total + 255) / 256, 256>>>(jobs, total);
        w_split_kernel<<<VP_, 128>>>(out_w, Wj);
    }

    // enc projection: encp[1024x512] = enc_out @ enc_w^T + b
    gemm_tc<<<dim3(D_ / 128, (TI_ * NB_) / 128, 1), 256, JT_SMEM>>>(
        exh, exl, ewh, ewl, enc_b, encp, nullptr, nullptr,
        TI_ * NB_, D_, D_, 8, 0);

    // embedding + positions
    embed_kernel<<<TOK_, 128>>>(embed_w, tgt_pad, sos, x, xh, xl);

    // 6 post-norm transformer layers
    for (int l = 0; l < L_; l++) {
        gemm_tc<<<dim3(3 * D_ / 128, 3, QKV_SPLIT), 256, JT_SMEM>>>(
            xh, xl, qkvwh + (size_t)l * 3 * D_ * D_, qkvwl + (size_t)l * 3 * D_ * D_,
            qkv_b + (size_t)l * 3 * D_, qkv, nullptr, nullptr,
            TOK_, 3 * D_, D_, 8 / QKV_SPLIT, 0);
        attention_kernel<<<NB_ * H_, 128>>>(qkv, tgt_len, ath, atl);
        gemm_tc<<<dim3(D_ / 128, 3, O_SPLIT), 256, JT_SMEM>>>(
            ath, atl, owh + (size_t)l * D_ * D_, owl + (size_t)l * D_ * D_,
            o_b + (size_t)l * D_, tmp, nullptr, nullptr,
            TOK_, D_, D_, 8 / O_SPLIT, 0);
        add_ln_kernel<<<TOK_, 128>>>(x, tmp, O_SPLIT,
            ln1_s + (size_t)l * D_, ln1_b + (size_t)l * D_, xh, xl);
        gemm_tc<<<dim3(FF_ / 128, 3, 1), 256, JT_SMEM>>>(
            xh, xl, f1h + (size_t)l * FF_ * D_, f1l + (size_t)l * FF_ * D_,
            ff1_b + (size_t)l * FF_, nullptr, fh, fl,
            TOK_, FF_, D_, 8, 1);
        gemm_tc<<<dim3(D_ / 128, 3, FF2_SPLIT), 256, JT_SMEM>>>(
            fh, fl, f2h + (size_t)l * D_ * FF_, f2l + (size_t)l * D_ * FF_,
            ff2_b + (size_t)l * D_, tmp, nullptr, nullptr,
            TOK_, D_, FF_, FF_ / 64 / FF2_SPLIT, 0);
        add_ln_kernel<<<TOK_, 128>>>(x, tmp, FF2_SPLIT,
            ln2_s + (size_t)l * D_, ln2_b + (size_t)l * D_, xh, xl);
    }

    // joiner: A = tanh(enc + x) as single fp16, then plain fp16 GEMM
    joiner_a_kernel<<<MJ_, 128>>>(encp, x, Aj);
    joiner_tc_kernel<<<dim3(VP_ / 128, MJ_ / 128), 256, JJ_SMEM>>>(
        Aj, Wj, (float*)d_out);
}